// round 2
// baseline (speedup 1.0000x reference)
#include <cuda_runtime.h>
#include <math.h>

#define A_N   20480
#define G_N   5
#define P_N   (A_N * G_N)           // 102400 pairs
#define NVOX  (128 * 128 * 128)
#define WIN   14
#define MAXE  (P_N * 8)             // worst-case tile entries
#define CHUNK 512
#define NB    8

// ---------------- device scratch ----------------
__device__ float        d_gx[P_N * 16];
__device__ float        d_gy[P_N * 16];
__device__ float        d_gz[P_N * 16];     // prefactor folded in
__device__ int4         d_meta[P_N];        // ix0, iy0, iz0, packed tile spans (w=-1: none)
__device__ float        d_vol[NVOX];
__device__ unsigned int d_counts[512];
__device__ unsigned int d_cursor[512];
__device__ unsigned int d_entries[MAXE];    // (tile << 17) | pair
__device__ unsigned int d_total;
__device__ double       d_sums[3];          // S1, S2, S3

// ---------------- K0: zero ----------------
__global__ void k_zero() {
    int i = blockIdx.x * blockDim.x + threadIdx.x;
    d_vol[i] = 0.0f;
    if (i < 512) d_counts[i] = 0u;
    if (i < 3)   d_sums[i] = 0.0;
}

// ---------------- K2: rotate + 1D gaussians + tile counting ----------------
__global__ void k_precompute(const float* __restrict__ quat,
                             const float* __restrict__ offset,
                             const float* __restrict__ pos,
                             const float* __restrict__ amp,
                             const float* __restrict__ var) {
    int p = blockIdx.x * blockDim.x + threadIdx.x;
    if (p >= P_N) return;

    float qw = quat[0], qx = quat[1], qy = quat[2], qz = quat[3];
    float qn = rsqrtf(qw * qw + qx * qx + qy * qy + qz * qz);
    qw *= qn; qx *= qn; qy *= qn; qz *= qn;
    float R00 = 1.f - 2.f * (qy * qy + qz * qz);
    float R01 = 2.f * (qx * qy - qw * qz);
    float R02 = 2.f * (qx * qz + qw * qy);
    float R10 = 2.f * (qx * qy + qw * qz);
    float R11 = 1.f - 2.f * (qx * qx + qz * qz);
    float R12 = 2.f * (qy * qz - qw * qx);
    float R20 = 2.f * (qx * qz - qw * qy);
    float R21 = 2.f * (qy * qz + qw * qx);
    float R22 = 1.f - 2.f * (qx * qx + qy * qy);

    int a = p / G_N;
    float px = pos[a * 3 + 0], py = pos[a * 3 + 1], pz = pos[a * 3 + 2];
    // pos_rot = positions @ R + offset  (row-vector times matrix)
    float cx = px * R00 + py * R10 + pz * R20 + offset[0];
    float cy = px * R01 + py * R11 + pz * R21 + offset[1];
    float cz = px * R02 + py * R12 + pz * R22 + offset[2];

    float v    = var[p];
    float am   = amp[p];
    float r    = rsqrtf(6.283185307179586f * v);
    float pref = am * r * r * r;            // amp * (2*pi*var)^(-3/2)
    float ninv = -0.5f / v;

    // voxel coord of index i is (i-64); window = floor(c)+64-6 .. +7
    int ix0 = (int)floorf(cx) + 58;
    int iy0 = (int)floorf(cy) + 58;
    int iz0 = (int)floorf(cz) + 58;

    #pragma unroll
    for (int i = 0; i < 16; i++) {
        float gxv = 0.f, gyv = 0.f, gzv = 0.f;
        if (i < WIN) {
            float dx = (float)(ix0 + i - 64) - cx;
            float dy = (float)(iy0 + i - 64) - cy;
            float dz = (float)(iz0 + i - 64) - cz;
            gxv = __expf(dx * dx * ninv);
            gyv = __expf(dy * dy * ninv);
            gzv = __expf(dz * dz * ninv) * pref;
        }
        d_gx[p * 16 + i] = gxv;
        d_gy[p * 16 + i] = gyv;
        d_gz[p * 16 + i] = gzv;
    }

    int xlo = max(ix0, 0), xhi = min(ix0 + WIN - 1, 127);
    int ylo = max(iy0, 0), yhi = min(iy0 + WIN - 1, 127);
    int zlo = max(iz0, 0), zhi = min(iz0 + WIN - 1, 127);
    int w = -1;
    if (xlo <= xhi && ylo <= yhi && zlo <= zhi) {
        int txlo = xlo >> 4, txhi = xhi >> 4;
        int tylo = ylo >> 4, tyhi = yhi >> 4;
        int tzlo = zlo >> 4, tzhi = zhi >> 4;
        w = txlo | (txhi << 3) | (tylo << 6) | (tyhi << 9) | (tzlo << 12) | (tzhi << 15);
        for (int tz = tzlo; tz <= tzhi; tz++)
            for (int ty = tylo; ty <= tyhi; ty++)
                for (int tx = txlo; tx <= txhi; tx++)
                    atomicAdd(&d_counts[(tz << 6) | (ty << 3) | tx], 1u);
    }
    d_meta[p] = make_int4(ix0, iy0, iz0, w);
}

// ---------------- K3: exclusive scan over 512 tiles ----------------
__global__ void k_scan() {
    __shared__ unsigned int s[512];
    int t = threadIdx.x;
    unsigned int own = d_counts[t];
    s[t] = own;
    __syncthreads();
    for (int off = 1; off < 512; off <<= 1) {
        unsigned int v = (t >= off) ? s[t - off] : 0u;
        __syncthreads();
        s[t] += v;
        __syncthreads();
    }
    d_cursor[t] = s[t] - own;
    if (t == 511) d_total = s[511];
}

// ---------------- K4: fill tile-grouped entry list ----------------
__global__ void k_fill() {
    int p = blockIdx.x * blockDim.x + threadIdx.x;
    if (p >= P_N) return;
    int w = d_meta[p].w;
    if (w < 0) return;
    int txlo =  w        & 7, txhi = (w >> 3)  & 7;
    int tylo = (w >> 6)  & 7, tyhi = (w >> 9)  & 7;
    int tzlo = (w >> 12) & 7, tzhi = (w >> 15) & 7;
    for (int tz = tzlo; tz <= tzhi; tz++)
        for (int ty = tylo; ty <= tyhi; ty++)
            for (int tx = txlo; tx <= txhi; tx++) {
                int tile = (tz << 6) | (ty << 3) | tx;
                unsigned int posn = atomicAdd(&d_cursor[tile], 1u);
                d_entries[posn] = ((unsigned int)tile << 17) | (unsigned int)p;
            }
}

// ---------------- K5: splat (register tile per CTA chunk) ----------------
__global__ void __launch_bounds__(128) k_splat() {
    __shared__ float sgx[NB][48];
    __shared__ float sgy[NB][48];
    __shared__ float sgz[NB][48];
    __shared__ int4  smeta[NB];
    __shared__ int   stile[NB];

    unsigned int total = d_total;
    unsigned int s = (unsigned int)blockIdx.x * CHUNK;
    if (s >= total) return;
    unsigned int e_end = s + CHUNK;
    if (e_end > total) e_end = total;

    int t = threadIdx.x;
    for (int i = t; i < NB * 48; i += 128) {
        sgx[i / 48][i % 48] = 0.f;
        sgy[i / 48][i % 48] = 0.f;
        sgz[i / 48][i % 48] = 0.f;
    }

    int y  = t & 15;     // owned y within tile
    int z1 = t >> 4;     // owned z rows: z1, z1+8
    float acc[32];
    #pragma unroll
    for (int i = 0; i < 32; i++) acc[i] = 0.f;

    int curTile = -1, X0 = 0, Y0 = 0, Z0 = 0;

    for (unsigned int base = s; base < e_end; base += NB) {
        int n = (int)(e_end - base);
        if (n > NB) n = NB;
        __syncthreads();
        int b = t >> 4, l = t & 15;
        if (b < n) {
            unsigned int ent = d_entries[base + (unsigned int)b];
            int pid = (int)(ent & 0x1FFFFu);
            sgx[b][15 + l] = d_gx[pid * 16 + l];
            sgy[b][15 + l] = d_gy[pid * 16 + l];
            sgz[b][15 + l] = d_gz[pid * 16 + l];
            if (l == 0) { smeta[b] = d_meta[pid]; stile[b] = (int)(ent >> 17); }
        }
        __syncthreads();

        for (int k = 0; k < n; k++) {
            int tile = stile[k];
            if (tile != curTile) {
                if (curTile >= 0) {
                    int base1 = ((Z0 + z1) * 128 + (Y0 + y)) * 128 + X0;
                    int base2 = base1 + 8 * 128 * 128;
                    #pragma unroll
                    for (int i = 0; i < 16; i++) {
                        if (acc[i]      != 0.f) atomicAdd(&d_vol[base1 + i], acc[i]);
                        if (acc[16 + i] != 0.f) atomicAdd(&d_vol[base2 + i], acc[16 + i]);
                    }
                    #pragma unroll
                    for (int i = 0; i < 32; i++) acc[i] = 0.f;
                }
                curTile = tile;
                X0 =  (tile       & 7) << 4;
                Y0 = ((tile >> 3) & 7) << 4;
                Z0 = ((tile >> 6) & 7) << 4;
            }
            int4 mt = smeta[k];
            float gyv = sgy[k][15 + Y0 - mt.y + y];
            float gz1 = sgz[k][15 + Z0 - mt.z + z1];
            float gz2 = sgz[k][15 + Z0 - mt.z + z1 + 8];
            float a1 = gz1 * gyv;
            float a2 = gz2 * gyv;
            int xo = 15 + X0 - mt.x;
            #pragma unroll
            for (int i = 0; i < 16; i++) {
                float gxv = sgx[k][xo + i];
                acc[i]      += a1 * gxv;
                acc[16 + i] += a2 * gxv;
            }
        }
    }

    if (curTile >= 0) {
        int base1 = ((Z0 + z1) * 128 + (Y0 + y)) * 128 + X0;
        int base2 = base1 + 8 * 128 * 128;
        #pragma unroll
        for (int i = 0; i < 16; i++) {
            if (acc[i]      != 0.f) atomicAdd(&d_vol[base1 + i], acc[i]);
            if (acc[16 + i] != 0.f) atomicAdd(&d_vol[base2 + i], acc[16 + i]);
        }
    }
}

// ---------------- K6: fused triple reduction ----------------
__global__ void k_reduce(const float* __restrict__ grid) {
    __shared__ double sh0[256], sh1[256], sh2[256];
    int t = threadIdx.x;
    double s1 = 0.0, s2 = 0.0, s3 = 0.0;
    for (int i = blockIdx.x * 256 + t; i < NVOX; i += gridDim.x * 256) {
        float v = d_vol[i];
        float g = grid[i];
        s1 += (double)v * (double)g;
        s2 += (double)v * (double)v;
        s3 += (double)g * (double)g;
    }
    sh0[t] = s1; sh1[t] = s2; sh2[t] = s3;
    __syncthreads();
    for (int off = 128; off > 0; off >>= 1) {
        if (t < off) {
            sh0[t] += sh0[t + off];
            sh1[t] += sh1[t + off];
            sh2[t] += sh2[t + off];
        }
        __syncthreads();
    }
    if (t == 0) {
        atomicAdd(&d_sums[0], sh0[0]);
        atomicAdd(&d_sums[1], sh1[0]);
        atomicAdd(&d_sums[2], sh2[0]);
    }
}

// ---------------- K7: scalar finish ----------------
__global__ void k_final(float* __restrict__ out) {
    out[0] = (float)(1.0 - d_sums[0] / sqrt(d_sums[1] * d_sums[2]));
}

extern "C" void kernel_launch(void* const* d_in, const int* in_sizes, int n_in,
                              void* d_out, int out_size) {
    const float* quat   = (const float*)d_in[0];
    const float* offset = (const float*)d_in[1];
    const float* pos    = (const float*)d_in[2];
    const float* amp    = (const float*)d_in[3];
    const float* var    = (const float*)d_in[4];
    const float* grid   = (const float*)d_in[5];
    float* out = (float*)d_out;

    k_zero<<<NVOX / 256, 256>>>();
    k_precompute<<<(P_N + 255) / 256, 256>>>(quat, offset, pos, amp, var);
    k_scan<<<1, 512>>>();
    k_fill<<<(P_N + 255) / 256, 256>>>();
    k_splat<<<MAXE / CHUNK, 128>>>();
    k_reduce<<<512, 256>>>(grid);
    k_final<<<1, 1>>>(out);
}

// round 3
// speedup vs baseline: 1.5415x; 1.5415x over previous
#include <cuda_runtime.h>
#include <math.h>

#define A_N   20480
#define G_N   5
#define P_N   (A_N * G_N)           // 102400 pairs
#define NVOX  (128 * 128 * 128)
#define MAXE  (P_N * 8)
#define CHUNK 512
#define NB    16

typedef unsigned long long ull;

// ---------------- device scratch ----------------
__device__ float        d_gx[P_N * 16];
__device__ float        d_gy[P_N * 16];
__device__ float        d_gz[P_N * 16];     // prefactor folded in
__device__ int4         d_meta[P_N];        // ix0, iy0, iz0, packed tile spans (w=-1: none)
__device__ float        d_vol[NVOX];
__device__ unsigned int d_counts[512];
__device__ unsigned int d_cursor[512];
__device__ unsigned int d_entries[MAXE];    // (tile << 17) | pair
__device__ unsigned int d_total;
__device__ double       d_sums[3];          // S1, S2, S3

// ---------------- f32x2 helpers ----------------
__device__ __forceinline__ ull pack2(float lo, float hi) {
    ull r; asm("mov.b64 %0, {%1, %2};" : "=l"(r) : "f"(lo), "f"(hi)); return r;
}
__device__ __forceinline__ void unpack2(ull v, float& lo, float& hi) {
    asm("mov.b64 {%0, %1}, %2;" : "=f"(lo), "=f"(hi) : "l"(v));
}
__device__ __forceinline__ ull fma2(ull a, ull b, ull c) {
    ull d; asm("fma.rn.f32x2 %0, %1, %2, %3;" : "=l"(d) : "l"(a), "l"(b), "l"(c)); return d;
}
__device__ __forceinline__ void red2(float* p, ull v) {
    float lo, hi; unpack2(v, lo, hi);
    asm volatile("red.global.add.v2.f32 [%0], {%1, %2};" :: "l"(p), "f"(lo), "f"(hi) : "memory");
}

// ---------------- K0: zero ----------------
__global__ void k_zero() {
    int i = blockIdx.x * blockDim.x + threadIdx.x;
    d_vol[i] = 0.0f;
    if (i < 512) d_counts[i] = 0u;
    if (i < 3)   d_sums[i] = 0.0;
}

// ---------------- K2: rotate + 1D gaussians (exp recurrence) + tile counting ----------------
__global__ void k_precompute(const float* __restrict__ quat,
                             const float* __restrict__ offset,
                             const float* __restrict__ pos,
                             const float* __restrict__ amp,
                             const float* __restrict__ var) {
    int p = blockIdx.x * blockDim.x + threadIdx.x;
    if (p >= P_N) return;

    float qw = quat[0], qx = quat[1], qy = quat[2], qz = quat[3];
    float qn = rsqrtf(qw * qw + qx * qx + qy * qy + qz * qz);
    qw *= qn; qx *= qn; qy *= qn; qz *= qn;
    float R00 = 1.f - 2.f * (qy * qy + qz * qz);
    float R01 = 2.f * (qx * qy - qw * qz);
    float R02 = 2.f * (qx * qz + qw * qy);
    float R10 = 2.f * (qx * qy + qw * qz);
    float R11 = 1.f - 2.f * (qx * qx + qz * qz);
    float R12 = 2.f * (qy * qz - qw * qx);
    float R20 = 2.f * (qx * qz - qw * qy);
    float R21 = 2.f * (qy * qz + qw * qx);
    float R22 = 1.f - 2.f * (qx * qx + qy * qy);

    int a = p / G_N;
    float px = pos[a * 3 + 0], py = pos[a * 3 + 1], pz = pos[a * 3 + 2];
    float cx = px * R00 + py * R10 + pz * R20 + offset[0];
    float cy = px * R01 + py * R11 + pz * R21 + offset[1];
    float cz = px * R02 + py * R12 + pz * R22 + offset[2];

    float v    = var[p];
    float am   = amp[p];
    float r    = rsqrtf(6.283185307179586f * v);
    float pref = am * r * r * r;            // amp * (2*pi*var)^(-3/2)
    float ninv = -0.5f / v;

    // even-aligned window start (16 voxels wide, >=6 voxel margin each side)
    int ix0 = ((int)floorf(cx) + 58) & ~1;
    int iy0 = ((int)floorf(cy) + 58) & ~1;
    int iz0 = ((int)floorf(cz) + 58) & ~1;

    // e_{i+1} = e_i * r_i ; r_{i+1} = r_i * q   with q = exp(2*ninv) shared
    float q2 = __expf(2.f * ninv);
    {
        float d0 = (float)(ix0 - 64) - cx;
        float e  = __expf(ninv * d0 * d0);
        float rr = __expf(ninv * (2.f * d0 + 1.f));
        #pragma unroll
        for (int i = 0; i < 16; i++) { d_gx[p * 16 + i] = e; e *= rr; rr *= q2; }
    }
    {
        float d0 = (float)(iy0 - 64) - cy;
        float e  = __expf(ninv * d0 * d0);
        float rr = __expf(ninv * (2.f * d0 + 1.f));
        #pragma unroll
        for (int i = 0; i < 16; i++) { d_gy[p * 16 + i] = e; e *= rr; rr *= q2; }
    }
    {
        float d0 = (float)(iz0 - 64) - cz;
        float e  = pref * __expf(ninv * d0 * d0);
        float rr = __expf(ninv * (2.f * d0 + 1.f));
        #pragma unroll
        for (int i = 0; i < 16; i++) { d_gz[p * 16 + i] = e; e *= rr; rr *= q2; }
    }

    int xlo = max(ix0, 0), xhi = min(ix0 + 15, 127);
    int ylo = max(iy0, 0), yhi = min(iy0 + 15, 127);
    int zlo = max(iz0, 0), zhi = min(iz0 + 15, 127);
    int w = -1;
    if (xlo <= xhi && ylo <= yhi && zlo <= zhi) {
        int txlo = xlo >> 4, txhi = xhi >> 4;
        int tylo = ylo >> 4, tyhi = yhi >> 4;
        int tzlo = zlo >> 4, tzhi = zhi >> 4;
        w = txlo | (txhi << 3) | (tylo << 6) | (tyhi << 9) | (tzlo << 12) | (tzhi << 15);
        for (int tz = tzlo; tz <= tzhi; tz++)
            for (int ty = tylo; ty <= tyhi; ty++)
                for (int tx = txlo; tx <= txhi; tx++)
                    atomicAdd(&d_counts[(tz << 6) | (ty << 3) | tx], 1u);  // no return -> RED
    }
    d_meta[p] = make_int4(ix0, iy0, iz0, w);
}

// ---------------- K3: exclusive scan over 512 tiles ----------------
__global__ void k_scan() {
    __shared__ unsigned int s[512];
    int t = threadIdx.x;
    unsigned int own = d_counts[t];
    s[t] = own;
    __syncthreads();
    for (int off = 1; off < 512; off <<= 1) {
        unsigned int v = (t >= off) ? s[t - off] : 0u;
        __syncthreads();
        s[t] += v;
        __syncthreads();
    }
    d_cursor[t] = s[t] - own;
    if (t == 511) d_total = s[511];
}

// ---------------- K4: fill entry list, block-aggregated cursors ----------------
__global__ void k_fill() {
    __shared__ unsigned int scount[512];
    __shared__ unsigned int sbase[512];
    int t = threadIdx.x;
    scount[t] = 0u; scount[t + 256] = 0u;
    __syncthreads();

    int p = blockIdx.x * 256 + t;
    int w = (p < P_N) ? d_meta[p].w : -1;
    int txlo = 0, txhi = -1, tylo = 0, tyhi = -1, tzlo = 0, tzhi = -1;
    if (w >= 0) {
        txlo =  w        & 7; txhi = (w >> 3)  & 7;
        tylo = (w >> 6)  & 7; tyhi = (w >> 9)  & 7;
        tzlo = (w >> 12) & 7; tzhi = (w >> 15) & 7;
        for (int tz = tzlo; tz <= tzhi; tz++)
            for (int ty = tylo; ty <= tyhi; ty++)
                for (int tx = txlo; tx <= txhi; tx++)
                    atomicAdd(&scount[(tz << 6) | (ty << 3) | tx], 1u);
    }
    __syncthreads();
    for (int i = t; i < 512; i += 256) {
        unsigned int c = scount[i];
        sbase[i] = c ? atomicAdd(&d_cursor[i], c) : 0u;
    }
    __syncthreads();
    if (w >= 0) {
        for (int tz = tzlo; tz <= tzhi; tz++)
            for (int ty = tylo; ty <= tyhi; ty++)
                for (int tx = txlo; tx <= txhi; tx++) {
                    int tile = (tz << 6) | (ty << 3) | tx;
                    unsigned int posn = atomicAdd(&sbase[tile], 1u);
                    d_entries[posn] = ((unsigned int)tile << 17) | (unsigned int)p;
                }
    }
}

// ---------------- K5: splat (register tile, f32x2 inner loop) ----------------
__global__ void __launch_bounds__(128) k_splat() {
    __shared__ __align__(16) float sgx[NB][48];
    __shared__ __align__(16) float sgy[NB][48];
    __shared__ __align__(16) float sgz[NB][48];
    __shared__ int4  smeta[NB];
    __shared__ int   stile[NB];

    unsigned int total = d_total;
    unsigned int s = (unsigned int)blockIdx.x * CHUNK;
    if (s >= total) return;
    unsigned int e_end = s + CHUNK;
    if (e_end > total) e_end = total;

    int t = threadIdx.x;
    for (int i = t; i < NB * 48; i += 128) {
        sgx[i / 48][i % 48] = 0.f;
        sgy[i / 48][i % 48] = 0.f;
        sgz[i / 48][i % 48] = 0.f;
    }

    int y  = t & 15;          // owned y within tile
    int u  = t >> 4;          // owned z rows: 2u, 2u+1  (warp w covers z in [4w,4w+4))
    int wzlo = (t >> 5) << 2; // warp's lowest z row
    ull accA[8], accB[8];     // z=2u and z=2u+1 planes, 8 x-pairs each
    #pragma unroll
    for (int i = 0; i < 8; i++) { accA[i] = 0ull; accB[i] = 0ull; }

    int curTile = -1, X0 = 0, Y0 = 0, Z0 = 0;

    for (unsigned int base = s; base < e_end; base += NB) {
        int n = (int)(e_end - base);
        if (n > NB) n = NB;
        __syncthreads();
        for (int s2 = t; s2 < NB * 16; s2 += 128) {
            int b = s2 >> 4, l = s2 & 15;
            if (b < n) {
                unsigned int ent = d_entries[base + (unsigned int)b];
                int pid = (int)(ent & 0x1FFFFu);
                sgx[b][16 + l] = d_gx[pid * 16 + l];
                sgy[b][16 + l] = d_gy[pid * 16 + l];
                sgz[b][16 + l] = d_gz[pid * 16 + l];
                if (l == 0) { smeta[b] = d_meta[pid]; stile[b] = (int)(ent >> 17); }
            }
        }
        __syncthreads();

        for (int k = 0; k < n; k++) {
            int tile = stile[k];
            if (tile != curTile) {
                if (curTile >= 0) {
                    int rb1 = ((Z0 + 2 * u) * 128 + (Y0 + y)) * 128 + X0;
                    int rb2 = rb1 + 128;   // z+1 row is +128*128? no: +1 in z = +128*128
                    rb2 = rb1 + 128 * 128;
                    #pragma unroll
                    for (int i = 0; i < 8; i++) {
                        if (accA[i]) red2(&d_vol[rb1 + 2 * i], accA[i]);
                        if (accB[i]) red2(&d_vol[rb2 + 2 * i], accB[i]);
                    }
                    #pragma unroll
                    for (int i = 0; i < 8; i++) { accA[i] = 0ull; accB[i] = 0ull; }
                }
                curTile = tile;
                X0 =  (tile       & 7) << 4;
                Y0 = ((tile >> 3) & 7) << 4;
                Z0 = ((tile >> 6) & 7) << 4;
            }
            int4 mt = smeta[k];
            // per-warp z skip: window z (rel tile) = [zr0, zr0+15]; warp covers [wzlo, wzlo+4)
            int zr0 = mt.z - Z0;
            if (wzlo + 3 < zr0 || wzlo > zr0 + 15) continue;

            float gyv = sgy[k][16 + Y0 - mt.y + y];
            float gz1 = sgz[k][16 + Z0 - mt.z + 2 * u];
            float gz2 = sgz[k][17 + Z0 - mt.z + 2 * u];
            ull a1p = pack2(gz1 * gyv, gz1 * gyv);
            ull a2p = pack2(gz2 * gyv, gz2 * gyv);
            int xo = 16 + X0 - mt.x;       // even -> 8B aligned LDS.64
            int dx = mt.x - X0;            // in [-15,15]
            const ull* gxp = (const ull*)&sgx[k][xo];
            if (dx <= 7) {                 // half 0: x rel tile [0,8)
                #pragma unroll
                for (int j = 0; j < 4; j++) {
                    ull gp = gxp[j];
                    accA[j] = fma2(a1p, gp, accA[j]);
                    accB[j] = fma2(a2p, gp, accB[j]);
                }
            }
            if (dx >= -7) {                // half 1: x rel tile [8,16)
                #pragma unroll
                for (int j = 4; j < 8; j++) {
                    ull gp = gxp[j];
                    accA[j] = fma2(a1p, gp, accA[j]);
                    accB[j] = fma2(a2p, gp, accB[j]);
                }
            }
        }
    }

    if (curTile >= 0) {
        int rb1 = ((Z0 + 2 * u) * 128 + (Y0 + y)) * 128 + X0;
        int rb2 = rb1 + 128 * 128;
        #pragma unroll
        for (int i = 0; i < 8; i++) {
            if (accA[i]) red2(&d_vol[rb1 + 2 * i], accA[i]);
            if (accB[i]) red2(&d_vol[rb2 + 2 * i], accB[i]);
        }
    }
}

// ---------------- K6: fused triple reduction ----------------
__global__ void k_reduce(const float* __restrict__ grid) {
    __shared__ double sh0[256], sh1[256], sh2[256];
    int t = threadIdx.x;
    double s1 = 0.0, s2 = 0.0, s3 = 0.0;
    for (int i = blockIdx.x * 256 + t; i < NVOX; i += gridDim.x * 256) {
        float v = d_vol[i];
        float g = grid[i];
        s1 += (double)v * (double)g;
        s2 += (double)v * (double)v;
        s3 += (double)g * (double)g;
    }
    sh0[t] = s1; sh1[t] = s2; sh2[t] = s3;
    __syncthreads();
    for (int off = 128; off > 0; off >>= 1) {
        if (t < off) {
            sh0[t] += sh0[t + off];
            sh1[t] += sh1[t + off];
            sh2[t] += sh2[t + off];
        }
        __syncthreads();
    }
    if (t == 0) {
        atomicAdd(&d_sums[0], sh0[0]);
        atomicAdd(&d_sums[1], sh1[0]);
        atomicAdd(&d_sums[2], sh2[0]);
    }
}

// ---------------- K7: scalar finish ----------------
__global__ void k_final(float* __restrict__ out) {
    out[0] = (float)(1.0 - d_sums[0] / sqrt(d_sums[1] * d_sums[2]));
}

extern "C" void kernel_launch(void* const* d_in, const int* in_sizes, int n_in,
                              void* d_out, int out_size) {
    const float* quat   = (const float*)d_in[0];
    const float* offset = (const float*)d_in[1];
    const float* pos    = (const float*)d_in[2];
    const float* amp    = (const float*)d_in[3];
    const float* var    = (const float*)d_in[4];
    const float* grid   = (const float*)d_in[5];
    float* out = (float*)d_out;

    k_zero<<<NVOX / 256, 256>>>();
    k_precompute<<<(P_N + 255) / 256, 256>>>(quat, offset, pos, amp, var);
    k_scan<<<1, 512>>>();
    k_fill<<<(P_N + 255) / 256, 256>>>();
    k_splat<<<MAXE / CHUNK, 128>>>();
    k_reduce<<<512, 256>>>(grid);
    k_final<<<1, 1>>>(out);
}

// round 5
// speedup vs baseline: 1.8066x; 1.1720x over previous
#include <cuda_runtime.h>
#include <math.h>

#define A_N   20480
#define G_N   5
#define P_N   (A_N * G_N)           // 102400 pairs
#define NVOX  (128 * 128 * 128)
#define WIN   14                    // gaussian window width (slots 0..13)
#define MAXE  (P_N * 8)
#define CHUNK 512
#define NB    16

typedef unsigned long long ull;

// ---------------- device scratch ----------------
__device__ float        d_gx[P_N * 16];
__device__ float        d_gy[P_N * 16];
__device__ float        d_gz[P_N * 16];     // prefactor folded in
__device__ int4         d_meta[P_N];        // ix0, iy0, iz0, packed tile spans (w=-1: none)
__device__ float        d_vol[NVOX];
__device__ unsigned int d_counts[512];
__device__ unsigned int d_cursor[512];
__device__ unsigned int d_entries[MAXE];    // (tile << 17) | pair
__device__ unsigned int d_total;
__device__ double       d_sums[3];          // S1, S2, S3

// ---------------- f32x2 helpers ----------------
__device__ __forceinline__ ull pack2(float lo, float hi) {
    ull r; asm("mov.b64 %0, {%1, %2};" : "=l"(r) : "f"(lo), "f"(hi)); return r;
}
__device__ __forceinline__ void unpack2(ull v, float& lo, float& hi) {
    asm("mov.b64 {%0, %1}, %2;" : "=f"(lo), "=f"(hi) : "l"(v));
}
__device__ __forceinline__ ull fma2(ull a, ull b, ull c) {
    ull d; asm("fma.rn.f32x2 %0, %1, %2, %3;" : "=l"(d) : "l"(a), "l"(b), "l"(c)); return d;
}
__device__ __forceinline__ void red2(float* p, ull v) {
    float lo, hi; unpack2(v, lo, hi);
    asm volatile("red.global.add.v2.f32 [%0], {%1, %2};" :: "l"(p), "f"(lo), "f"(hi) : "memory");
}

// ---------------- K0: zero ----------------
__global__ void k_zero() {
    int i = blockIdx.x * blockDim.x + threadIdx.x;
    d_vol[i] = 0.0f;
    if (i < 512) d_counts[i] = 0u;
    if (i < 3)   d_sums[i] = 0.0;
}

// ---------------- K2: rotate + 1D gaussians (exp recurrence) + tile counting ----------------
__global__ void k_precompute(const float* __restrict__ quat,
                             const float* __restrict__ offset,
                             const float* __restrict__ pos,
                             const float* __restrict__ amp,
                             const float* __restrict__ var) {
    int p = blockIdx.x * blockDim.x + threadIdx.x;
    if (p >= P_N) return;

    float qw = quat[0], qx = quat[1], qy = quat[2], qz = quat[3];
    float qn = rsqrtf(qw * qw + qx * qx + qy * qy + qz * qz);
    qw *= qn; qx *= qn; qy *= qn; qz *= qn;
    float R00 = 1.f - 2.f * (qy * qy + qz * qz);
    float R01 = 2.f * (qx * qy - qw * qz);
    float R02 = 2.f * (qx * qz + qw * qy);
    float R10 = 2.f * (qx * qy + qw * qz);
    float R11 = 1.f - 2.f * (qx * qx + qz * qz);
    float R12 = 2.f * (qy * qz - qw * qx);
    float R20 = 2.f * (qx * qz - qw * qy);
    float R21 = 2.f * (qy * qz + qw * qx);
    float R22 = 1.f - 2.f * (qx * qx + qy * qy);

    int a = p / G_N;
    float px = pos[a * 3 + 0], py = pos[a * 3 + 1], pz = pos[a * 3 + 2];
    float cx = px * R00 + py * R10 + pz * R20 + offset[0];
    float cy = px * R01 + py * R11 + pz * R21 + offset[1];
    float cz = px * R02 + py * R12 + pz * R22 + offset[2];

    float v    = var[p];
    float am   = amp[p];
    float r    = rsqrtf(6.283185307179586f * v);
    float pref = am * r * r * r;            // amp * (2*pi*var)^(-3/2)
    float ninv = -0.5f / v;

    // even-aligned window start; covers [ix0 .. ix0+13], margin >= 5 voxels
    int ix0 = ((int)floorf(cx) + 58) & ~1;
    int iy0 = ((int)floorf(cy) + 58) & ~1;
    int iz0 = ((int)floorf(cz) + 58) & ~1;

    float q2 = __expf(2.f * ninv);
    {
        float d0 = (float)(ix0 - 64) - cx;
        float e  = __expf(ninv * d0 * d0);
        float rr = __expf(ninv * (2.f * d0 + 1.f));
        #pragma unroll
        for (int i = 0; i < WIN; i++) { d_gx[p * 16 + i] = e; e *= rr; rr *= q2; }
    }
    {
        float d0 = (float)(iy0 - 64) - cy;
        float e  = __expf(ninv * d0 * d0);
        float rr = __expf(ninv * (2.f * d0 + 1.f));
        #pragma unroll
        for (int i = 0; i < WIN; i++) { d_gy[p * 16 + i] = e; e *= rr; rr *= q2; }
    }
    {
        float d0 = (float)(iz0 - 64) - cz;
        float e  = pref * __expf(ninv * d0 * d0);
        float rr = __expf(ninv * (2.f * d0 + 1.f));
        #pragma unroll
        for (int i = 0; i < WIN; i++) { d_gz[p * 16 + i] = e; e *= rr; rr *= q2; }
    }

    int xlo = max(ix0, 0), xhi = min(ix0 + WIN - 1, 127);
    int ylo = max(iy0, 0), yhi = min(iy0 + WIN - 1, 127);
    int zlo = max(iz0, 0), zhi = min(iz0 + WIN - 1, 127);
    int w = -1;
    if (xlo <= xhi && ylo <= yhi && zlo <= zhi) {
        int txlo = xlo >> 4, txhi = xhi >> 4;
        int tylo = ylo >> 4, tyhi = yhi >> 4;
        int tzlo = zlo >> 4, tzhi = zhi >> 4;
        w = txlo | (txhi << 3) | (tylo << 6) | (tyhi << 9) | (tzlo << 12) | (tzhi << 15);
        for (int tz = tzlo; tz <= tzhi; tz++)
            for (int ty = tylo; ty <= tyhi; ty++)
                for (int tx = txlo; tx <= txhi; tx++)
                    atomicAdd(&d_counts[(tz << 6) | (ty << 3) | tx], 1u);
    }
    d_meta[p] = make_int4(ix0, iy0, iz0, w);
}

// ---------------- K3: exclusive scan over 512 tiles ----------------
__global__ void k_scan() {
    __shared__ unsigned int s[512];
    int t = threadIdx.x;
    unsigned int own = d_counts[t];
    s[t] = own;
    __syncthreads();
    for (int off = 1; off < 512; off <<= 1) {
        unsigned int v = (t >= off) ? s[t - off] : 0u;
        __syncthreads();
        s[t] += v;
        __syncthreads();
    }
    d_cursor[t] = s[t] - own;
    if (t == 511) d_total = s[511];
}

// ---------------- K4: fill entry list, block-aggregated cursors ----------------
__global__ void k_fill() {
    __shared__ unsigned int scount[512];
    __shared__ unsigned int sbase[512];
    int t = threadIdx.x;
    scount[t] = 0u; scount[t + 256] = 0u;
    __syncthreads();

    int p = blockIdx.x * 256 + t;
    int w = (p < P_N) ? d_meta[p].w : -1;
    int txlo = 0, txhi = -1, tylo = 0, tyhi = -1, tzlo = 0, tzhi = -1;
    if (w >= 0) {
        txlo =  w        & 7; txhi = (w >> 3)  & 7;
        tylo = (w >> 6)  & 7; tyhi = (w >> 9)  & 7;
        tzlo = (w >> 12) & 7; tzhi = (w >> 15) & 7;
        for (int tz = tzlo; tz <= tzhi; tz++)
            for (int ty = tylo; ty <= tyhi; ty++)
                for (int tx = txlo; tx <= txhi; tx++)
                    atomicAdd(&scount[(tz << 6) | (ty << 3) | tx], 1u);
    }
    __syncthreads();
    for (int i = t; i < 512; i += 256) {
        unsigned int c = scount[i];
        sbase[i] = c ? atomicAdd(&d_cursor[i], c) : 0u;
    }
    __syncthreads();
    if (w >= 0) {
        for (int tz = tzlo; tz <= tzhi; tz++)
            for (int ty = tylo; ty <= tyhi; ty++)
                for (int tx = txlo; tx <= txhi; tx++) {
                    int tile = (tz << 6) | (ty << 3) | tx;
                    unsigned int posn = atomicAdd(&sbase[tile], 1u);
                    d_entries[posn] = ((unsigned int)tile << 17) | (unsigned int)p;
                }
    }
}

// ---------------- K5: splat — tile-aligned staging, 64 thr, 64 cells/thr ----------------
__global__ void __launch_bounds__(64) k_splat() {
    __shared__ __align__(16) float sgx[NB][16];
    __shared__ __align__(16) float sgy[NB][16];
    __shared__ __align__(16) float sgz[NB][16];
    __shared__ unsigned int scombo[NB];
    __shared__ int          spid[NB];
    __shared__ int          soff[NB];

    unsigned int total = d_total;
    unsigned int s = (unsigned int)blockIdx.x * CHUNK;
    if (s >= total) return;
    unsigned int e_end = s + CHUNK;
    if (e_end > total) e_end = total;

    int t   = threadIdx.x;
    int y2  = t & 7;          // y rows: 2*y2, 2*y2+1
    int u   = t >> 3;         // z rows: 2*u, 2*u+1 (warp0: z 0..7, warp1: z 8..15)
    int wId = t >> 5;         // warp id 0/1

    ull acc[4][8];            // [zz*2+yy][x-pair]
    #pragma unroll
    for (int r = 0; r < 4; r++)
        #pragma unroll
        for (int i = 0; i < 8; i++) acc[r][i] = 0ull;

    int curTile = -1;

    for (unsigned int base = s; base < e_end; base += NB) {
        int n = (int)(e_end - base);
        if (n > NB) n = NB;
        __syncthreads();
        // phase 1: per-entry combo / offsets
        if (t < n) {
            unsigned int ent = d_entries[base + (unsigned int)t];
            int pid  = (int)(ent & 0x1FFFFu);
            int tile = (int)(ent >> 17);
            int4 mt = d_meta[pid];
            int X0 =  (tile       & 7) << 4;
            int Y0 = ((tile >> 3) & 7) << 4;
            int Z0 = ((tile >> 6) & 7) << 4;
            int ox = X0 - mt.x, oy = Y0 - mt.y, oz = Z0 - mt.z;   // in [-15..13]
            int lox = max(0, -ox), hix = min(15, (WIN - 1) - ox);
            int loz = max(0, -oz), hiz = min(15, (WIN - 1) - oz);
            unsigned int c = (unsigned int)tile;
            if (loz <= 7) c |= 1u << 9;    // warp0 z-coverage
            if (hiz >= 8) c |= 1u << 10;   // warp1 z-coverage
            if (lox <= 7) c |= 1u << 11;   // x half 0
            if (hix >= 8) c |= 1u << 12;   // x half 1
            scombo[t] = c;
            spid[t]   = pid;
            soff[t]   = (ox + 16) | ((oy + 16) << 6) | ((oz + 16) << 12);
        }
        __syncthreads();
        // phase 2: tile-aligned gather with zero padding.
        // window slot for tile-local l is  l + o  (o = tile_origin - window_start)
        for (int s2 = t; s2 < n * 16; s2 += 64) {
            int b = s2 >> 4, l = s2 & 15;
            int pid = spid[b];
            int off = soff[b];
            int ix = l + ((off         & 63) - 16);
            int iy = l + (((off >> 6)  & 63) - 16);
            int iz = l + (((off >> 12) & 63) - 16);
            sgx[b][l] = ((unsigned)ix < (unsigned)WIN) ? d_gx[pid * 16 + ix] : 0.f;
            sgy[b][l] = ((unsigned)iy < (unsigned)WIN) ? d_gy[pid * 16 + iy] : 0.f;
            sgz[b][l] = ((unsigned)iz < (unsigned)WIN) ? d_gz[pid * 16 + iz] : 0.f;
        }
        __syncthreads();

        for (int k = 0; k < n; k++) {
            unsigned int c = scombo[k];
            int tile = (int)(c & 511u);
            if (tile != curTile) {
                if (curTile >= 0) {
                    int X0 =  (curTile       & 7) << 4;
                    int Y0 = ((curTile >> 3) & 7) << 4;
                    int Z0 = ((curTile >> 6) & 7) << 4;
                    #pragma unroll
                    for (int zz = 0; zz < 2; zz++)
                        #pragma unroll
                        for (int yy = 0; yy < 2; yy++) {
                            int rb = ((Z0 + 2 * u + zz) * 128 + (Y0 + 2 * y2 + yy)) * 128 + X0;
                            #pragma unroll
                            for (int i = 0; i < 8; i++)
                                if (acc[zz * 2 + yy][i]) red2(&d_vol[rb + 2 * i], acc[zz * 2 + yy][i]);
                        }
                    #pragma unroll
                    for (int r = 0; r < 4; r++)
                        #pragma unroll
                        for (int i = 0; i < 8; i++) acc[r][i] = 0ull;
                }
                curTile = tile;
            }
            if (!((c >> (9 + wId)) & 1u)) continue;   // warp z-skip

            float2 gyp = *(const float2*)&sgy[k][2 * y2];
            float2 gzp = *(const float2*)&sgz[k][2 * u];
            float a00 = gyp.x * gzp.x;   // yy0 zz0
            float a10 = gyp.y * gzp.x;   // yy1 zz0
            float a01 = gyp.x * gzp.y;   // yy0 zz1
            float a11 = gyp.y * gzp.y;   // yy1 zz1
            ull c00 = pack2(a00, a00), c10 = pack2(a10, a10);
            ull c01 = pack2(a01, a01), c11 = pack2(a11, a11);

            if (c & (1u << 11)) {
                ulonglong2 qa = *(const ulonglong2*)&sgx[k][0];
                ulonglong2 qb = *(const ulonglong2*)&sgx[k][4];
                acc[0][0] = fma2(c00, qa.x, acc[0][0]); acc[0][1] = fma2(c00, qa.y, acc[0][1]);
                acc[0][2] = fma2(c00, qb.x, acc[0][2]); acc[0][3] = fma2(c00, qb.y, acc[0][3]);
                acc[1][0] = fma2(c10, qa.x, acc[1][0]); acc[1][1] = fma2(c10, qa.y, acc[1][1]);
                acc[1][2] = fma2(c10, qb.x, acc[1][2]); acc[1][3] = fma2(c10, qb.y, acc[1][3]);
                acc[2][0] = fma2(c01, qa.x, acc[2][0]); acc[2][1] = fma2(c01, qa.y, acc[2][1]);
                acc[2][2] = fma2(c01, qb.x, acc[2][2]); acc[2][3] = fma2(c01, qb.y, acc[2][3]);
                acc[3][0] = fma2(c11, qa.x, acc[3][0]); acc[3][1] = fma2(c11, qa.y, acc[3][1]);
                acc[3][2] = fma2(c11, qb.x, acc[3][2]); acc[3][3] = fma2(c11, qb.y, acc[3][3]);
            }
            if (c & (1u << 12)) {
                ulonglong2 qc = *(const ulonglong2*)&sgx[k][8];
                ulonglong2 qd = *(const ulonglong2*)&sgx[k][12];
                acc[0][4] = fma2(c00, qc.x, acc[0][4]); acc[0][5] = fma2(c00, qc.y, acc[0][5]);
                acc[0][6] = fma2(c00, qd.x, acc[0][6]); acc[0][7] = fma2(c00, qd.y, acc[0][7]);
                acc[1][4] = fma2(c10, qc.x, acc[1][4]); acc[1][5] = fma2(c10, qc.y, acc[1][5]);
                acc[1][6] = fma2(c10, qd.x, acc[1][6]); acc[1][7] = fma2(c10, qd.y, acc[1][7]);
                acc[2][4] = fma2(c01, qc.x, acc[2][4]); acc[2][5] = fma2(c01, qc.y, acc[2][5]);
                acc[2][6] = fma2(c01, qd.x, acc[2][6]); acc[2][7] = fma2(c01, qd.y, acc[2][7]);
                acc[3][4] = fma2(c11, qc.x, acc[3][4]); acc[3][5] = fma2(c11, qc.y, acc[3][5]);
                acc[3][6] = fma2(c11, qd.x, acc[3][6]); acc[3][7] = fma2(c11, qd.y, acc[3][7]);
            }
        }
    }

    if (curTile >= 0) {
        int X0 =  (curTile       & 7) << 4;
        int Y0 = ((curTile >> 3) & 7) << 4;
        int Z0 = ((curTile >> 6) & 7) << 4;
        #pragma unroll
        for (int zz = 0; zz < 2; zz++)
            #pragma unroll
            for (int yy = 0; yy < 2; yy++) {
                int rb = ((Z0 + 2 * u + zz) * 128 + (Y0 + 2 * y2 + yy)) * 128 + X0;
                #pragma unroll
                for (int i = 0; i < 8; i++)
                    if (acc[zz * 2 + yy][i]) red2(&d_vol[rb + 2 * i], acc[zz * 2 + yy][i]);
            }
    }
}

// ---------------- K6: fused triple reduction (float inner, double tree) ----------------
__global__ void k_reduce(const float* __restrict__ grid) {
    __shared__ double sh0[256], sh1[256], sh2[256];
    int t = threadIdx.x;
    float s1 = 0.f, s2 = 0.f, s3 = 0.f;
    for (int i = blockIdx.x * 256 + t; i < NVOX; i += gridDim.x * 256) {
        float v = d_vol[i];
        float g = grid[i];
        s1 += v * g;
        s2 += v * v;
        s3 += g * g;
    }
    sh0[t] = (double)s1; sh1[t] = (double)s2; sh2[t] = (double)s3;
    __syncthreads();
    for (int off = 128; off > 0; off >>= 1) {
        if (t < off) {
            sh0[t] += sh0[t + off];
            sh1[t] += sh1[t + off];
            sh2[t] += sh2[t + off];
        }
        __syncthreads();
    }
    if (t == 0) {
        atomicAdd(&d_sums[0], sh0[0]);
        atomicAdd(&d_sums[1], sh1[0]);
        atomicAdd(&d_sums[2], sh2[0]);
    }
}

// ---------------- K7: scalar finish ----------------
__global__ void k_final(float* __restrict__ out) {
    out[0] = (float)(1.0 - d_sums[0] / sqrt(d_sums[1] * d_sums[2]));
}

extern "C" void kernel_launch(void* const* d_in, const int* in_sizes, int n_in,
                              void* d_out, int out_size) {
    const float* quat   = (const float*)d_in[0];
    const float* offset = (const float*)d_in[1];
    const float* pos    = (const float*)d_in[2];
    const float* amp    = (const float*)d_in[3];
    const float* var    = (const float*)d_in[4];
    const float* grid   = (const float*)d_in[5];
    float* out = (float*)d_out;

    k_zero<<<NVOX / 256, 256>>>();
    k_precompute<<<(P_N + 255) / 256, 256>>>(quat, offset, pos, amp, var);
    k_scan<<<1, 512>>>();
    k_fill<<<(P_N + 255) / 256, 256>>>();
    k_splat<<<MAXE / CHUNK, 64>>>();
    k_reduce<<<512, 256>>>(grid);
    k_final<<<1, 1>>>(out);
}

// round 6
// speedup vs baseline: 1.9708x; 1.0909x over previous
#include <cuda_runtime.h>
#include <math.h>

#define A_N   20480
#define G_N   5
#define P_N   (A_N * G_N)           // 102400 pairs
#define NVOX  (128 * 128 * 128)
#define WIN   14                    // gaussian window width (slots 0..13)
#define MAXE  (P_N * 8)
#define CHUNK 512
#define NB    32

typedef unsigned long long ull;

// ---------------- device scratch ----------------
__device__ float        d_gx[P_N * 16];
__device__ float        d_gy[P_N * 16];
__device__ float        d_gz[P_N * 16];     // prefactor folded in
__device__ int4         d_meta[P_N];        // ix0, iy0, iz0, packed tile spans (w=-1: none)
__device__ float        d_vol[NVOX];
__device__ unsigned int d_counts[512];
__device__ unsigned int d_cursor[512];
__device__ unsigned int d_entries[MAXE];    // (tile << 17) | pair
__device__ unsigned int d_total;
__device__ double       d_sums[3];          // S1, S2, S3

// ---------------- f32x2 helpers ----------------
__device__ __forceinline__ ull pack2(float lo, float hi) {
    ull r; asm("mov.b64 %0, {%1, %2};" : "=l"(r) : "f"(lo), "f"(hi)); return r;
}
__device__ __forceinline__ void unpack2(ull v, float& lo, float& hi) {
    asm("mov.b64 {%0, %1}, %2;" : "=f"(lo), "=f"(hi) : "l"(v));
}
__device__ __forceinline__ ull fma2(ull a, ull b, ull c) {
    ull d; asm("fma.rn.f32x2 %0, %1, %2, %3;" : "=l"(d) : "l"(a), "l"(b), "l"(c)); return d;
}
__device__ __forceinline__ void red2(float* p, ull v) {
    float lo, hi; unpack2(v, lo, hi);
    asm volatile("red.global.add.v2.f32 [%0], {%1, %2};" :: "l"(p), "f"(lo), "f"(hi) : "memory");
}

// ---------------- K0: zero ----------------
__global__ void k_zero() {
    int i = blockIdx.x * blockDim.x + threadIdx.x;
    d_vol[i] = 0.0f;
    if (i < 512) d_counts[i] = 0u;
    if (i < 3)   d_sums[i] = 0.0;
}

// ---------------- K2: rotate + 1D gaussians (exp recurrence) + tile counting ----------------
__global__ void k_precompute(const float* __restrict__ quat,
                             const float* __restrict__ offset,
                             const float* __restrict__ pos,
                             const float* __restrict__ amp,
                             const float* __restrict__ var) {
    int p = blockIdx.x * blockDim.x + threadIdx.x;
    if (p >= P_N) return;

    float qw = quat[0], qx = quat[1], qy = quat[2], qz = quat[3];
    float qn = rsqrtf(qw * qw + qx * qx + qy * qy + qz * qz);
    qw *= qn; qx *= qn; qy *= qn; qz *= qn;
    float R00 = 1.f - 2.f * (qy * qy + qz * qz);
    float R01 = 2.f * (qx * qy - qw * qz);
    float R02 = 2.f * (qx * qz + qw * qy);
    float R10 = 2.f * (qx * qy + qw * qz);
    float R11 = 1.f - 2.f * (qx * qx + qz * qz);
    float R12 = 2.f * (qy * qz - qw * qx);
    float R20 = 2.f * (qx * qz - qw * qy);
    float R21 = 2.f * (qy * qz + qw * qx);
    float R22 = 1.f - 2.f * (qx * qx + qy * qy);

    int a = p / G_N;
    float px = pos[a * 3 + 0], py = pos[a * 3 + 1], pz = pos[a * 3 + 2];
    float cx = px * R00 + py * R10 + pz * R20 + offset[0];
    float cy = px * R01 + py * R11 + pz * R21 + offset[1];
    float cz = px * R02 + py * R12 + pz * R22 + offset[2];

    float v    = var[p];
    float am   = amp[p];
    float r    = rsqrtf(6.283185307179586f * v);
    float pref = am * r * r * r;            // amp * (2*pi*var)^(-3/2)
    float ninv = -0.5f / v;

    // even-aligned window start; covers [ix0 .. ix0+13], margin >= 5 voxels
    int ix0 = ((int)floorf(cx) + 58) & ~1;
    int iy0 = ((int)floorf(cy) + 58) & ~1;
    int iz0 = ((int)floorf(cz) + 58) & ~1;

    float q2 = __expf(2.f * ninv);
    {
        float d0 = (float)(ix0 - 64) - cx;
        float e  = __expf(ninv * d0 * d0);
        float rr = __expf(ninv * (2.f * d0 + 1.f));
        #pragma unroll
        for (int i = 0; i < WIN; i++) { d_gx[p * 16 + i] = e; e *= rr; rr *= q2; }
    }
    {
        float d0 = (float)(iy0 - 64) - cy;
        float e  = __expf(ninv * d0 * d0);
        float rr = __expf(ninv * (2.f * d0 + 1.f));
        #pragma unroll
        for (int i = 0; i < WIN; i++) { d_gy[p * 16 + i] = e; e *= rr; rr *= q2; }
    }
    {
        float d0 = (float)(iz0 - 64) - cz;
        float e  = pref * __expf(ninv * d0 * d0);
        float rr = __expf(ninv * (2.f * d0 + 1.f));
        #pragma unroll
        for (int i = 0; i < WIN; i++) { d_gz[p * 16 + i] = e; e *= rr; rr *= q2; }
    }

    int xlo = max(ix0, 0), xhi = min(ix0 + WIN - 1, 127);
    int ylo = max(iy0, 0), yhi = min(iy0 + WIN - 1, 127);
    int zlo = max(iz0, 0), zhi = min(iz0 + WIN - 1, 127);
    int w = -1;
    if (xlo <= xhi && ylo <= yhi && zlo <= zhi) {
        int txlo = xlo >> 4, txhi = xhi >> 4;
        int tylo = ylo >> 4, tyhi = yhi >> 4;
        int tzlo = zlo >> 4, tzhi = zhi >> 4;
        w = txlo | (txhi << 3) | (tylo << 6) | (tyhi << 9) | (tzlo << 12) | (tzhi << 15);
        for (int tz = tzlo; tz <= tzhi; tz++)
            for (int ty = tylo; ty <= tyhi; ty++)
                for (int tx = txlo; tx <= txhi; tx++)
                    atomicAdd(&d_counts[(tz << 6) | (ty << 3) | tx], 1u);
    }
    d_meta[p] = make_int4(ix0, iy0, iz0, w);
}

// ---------------- K3: exclusive scan over 512 tiles ----------------
__global__ void k_scan() {
    __shared__ unsigned int s[512];
    int t = threadIdx.x;
    unsigned int own = d_counts[t];
    s[t] = own;
    __syncthreads();
    for (int off = 1; off < 512; off <<= 1) {
        unsigned int v = (t >= off) ? s[t - off] : 0u;
        __syncthreads();
        s[t] += v;
        __syncthreads();
    }
    d_cursor[t] = s[t] - own;
    if (t == 511) d_total = s[511];
}

// ---------------- K4: fill entry list, block-aggregated cursors ----------------
__global__ void k_fill() {
    __shared__ unsigned int scount[512];
    __shared__ unsigned int sbase[512];
    int t = threadIdx.x;
    scount[t] = 0u; scount[t + 256] = 0u;
    __syncthreads();

    int p = blockIdx.x * 256 + t;
    int w = (p < P_N) ? d_meta[p].w : -1;
    int txlo = 0, txhi = -1, tylo = 0, tyhi = -1, tzlo = 0, tzhi = -1;
    if (w >= 0) {
        txlo =  w        & 7; txhi = (w >> 3)  & 7;
        tylo = (w >> 6)  & 7; tyhi = (w >> 9)  & 7;
        tzlo = (w >> 12) & 7; tzhi = (w >> 15) & 7;
        for (int tz = tzlo; tz <= tzhi; tz++)
            for (int ty = tylo; ty <= tyhi; ty++)
                for (int tx = txlo; tx <= txhi; tx++)
                    atomicAdd(&scount[(tz << 6) | (ty << 3) | tx], 1u);
    }
    __syncthreads();
    for (int i = t; i < 512; i += 256) {
        unsigned int c = scount[i];
        sbase[i] = c ? atomicAdd(&d_cursor[i], c) : 0u;
    }
    __syncthreads();
    if (w >= 0) {
        for (int tz = tzlo; tz <= tzhi; tz++)
            for (int ty = tylo; ty <= tyhi; ty++)
                for (int tx = txlo; tx <= txhi; tx++) {
                    int tile = (tz << 6) | (ty << 3) | tx;
                    unsigned int posn = atomicAdd(&sbase[tile], 1u);
                    d_entries[posn] = ((unsigned int)tile << 17) | (unsigned int)p;
                }
    }
}

// ---------------- K5: splat — 128 thr, double-buffered staging, 1 barrier/batch ----------------
__global__ void __launch_bounds__(128) k_splat() {
    __shared__ __align__(16) float sgx[2][NB][16];
    __shared__ __align__(16) float sgy[2][NB][16];
    __shared__ __align__(16) float sgz[2][NB][16];
    __shared__ unsigned int scombo[2][NB];

    unsigned int total = d_total;
    unsigned int s = (unsigned int)blockIdx.x * CHUNK;
    if (s >= total) return;
    unsigned int e_end = s + CHUNK;
    if (e_end > total) e_end = total;

    int t   = threadIdx.x;
    int y   = t & 15;         // owned y row
    int zp  = t >> 4;         // owned z rows: 2*zp, 2*zp+1
    int wid = t >> 5;         // warp id 0..3, covers z in [4w, 4w+4)

    ull acc[2][8];            // [zz][x-pair]
    #pragma unroll
    for (int r = 0; r < 2; r++)
        #pragma unroll
        for (int i = 0; i < 8; i++) acc[r][i] = 0ull;

    // stage batch j into buffer buf: tile-aligned, zero-padded gaussians
    auto stage = [&](int buf, unsigned int base, int n) {
        for (int s2 = t; s2 < n * 16; s2 += 128) {
            int b = s2 >> 4, l = s2 & 15;
            unsigned int ent = d_entries[base + (unsigned int)b];
            int pid  = (int)(ent & 0x1FFFFu);
            int tile = (int)(ent >> 17);
            int4 mt = d_meta[pid];
            int X0 =  (tile       & 7) << 4;
            int Y0 = ((tile >> 3) & 7) << 4;
            int Z0 = ((tile >> 6) & 7) << 4;
            int ox = X0 - mt.x, oy = Y0 - mt.y, oz = Z0 - mt.z;
            int ix = l + ox, iy = l + oy, iz = l + oz;   // window slot per tile-local l
            sgx[buf][b][l] = ((unsigned)ix < (unsigned)WIN) ? d_gx[pid * 16 + ix] : 0.f;
            sgy[buf][b][l] = ((unsigned)iy < (unsigned)WIN) ? d_gy[pid * 16 + iy] : 0.f;
            sgz[buf][b][l] = ((unsigned)iz < (unsigned)WIN) ? d_gz[pid * 16 + iz] : 0.f;
            if (l == 0) {
                int loz = max(0, -oz), hiz = min(15, (WIN - 1) - oz);
                int lox = max(0, -ox), hix = min(15, (WIN - 1) - ox);
                unsigned int c = (unsigned int)tile;
                #pragma unroll
                for (int w = 0; w < 4; w++)
                    if (loz <= 4 * w + 3 && hiz >= 4 * w) c |= 1u << (9 + w);
                if (lox <= 7) c |= 1u << 13;
                if (hix >= 8) c |= 1u << 14;
                scombo[buf][b] = c;
            }
        }
    };

    int curTile = -1;
    int nbatch = (int)((e_end - s + NB - 1) / NB);

    // prologue: stage batch 0
    stage(0, s, (int)min((unsigned int)NB, e_end - s));

    for (int i = 0; i < nbatch; i++) {
        __syncthreads();                 // buf[i&1] staged; buf[(i+1)&1] free (batch i-1 consumed)
        int cur = i & 1;
        if (i + 1 < nbatch) {
            unsigned int bnext = s + (unsigned int)(i + 1) * NB;
            stage(cur ^ 1, bnext, (int)min((unsigned int)NB, e_end - bnext));
        }
        int n = (int)min((unsigned int)NB, e_end - (s + (unsigned int)i * NB));

        for (int k = 0; k < n; k++) {
            unsigned int c = scombo[cur][k];
            int tile = (int)(c & 511u);
            if (tile != curTile) {
                if (curTile >= 0) {
                    int X0 =  (curTile       & 7) << 4;
                    int Y0 = ((curTile >> 3) & 7) << 4;
                    int Z0 = ((curTile >> 6) & 7) << 4;
                    #pragma unroll
                    for (int zz = 0; zz < 2; zz++) {
                        int rb = ((Z0 + 2 * zp + zz) * 128 + (Y0 + y)) * 128 + X0;
                        #pragma unroll
                        for (int i2 = 0; i2 < 8; i2++)
                            if (acc[zz][i2]) red2(&d_vol[rb + 2 * i2], acc[zz][i2]);
                    }
                    #pragma unroll
                    for (int r = 0; r < 2; r++)
                        #pragma unroll
                        for (int i2 = 0; i2 < 8; i2++) acc[r][i2] = 0ull;
                }
                curTile = tile;
            }
            if (!((c >> (9 + wid)) & 1u)) continue;   // warp z-skip

            float  gyv = sgy[cur][k][y];
            float2 gzp = *(const float2*)&sgz[cur][k][2 * zp];
            float a0 = gyv * gzp.x;
            float a1 = gyv * gzp.y;
            ull c0 = pack2(a0, a0), c1 = pack2(a1, a1);

            if (c & (1u << 13)) {
                ulonglong2 qa = *(const ulonglong2*)&sgx[cur][k][0];
                ulonglong2 qb = *(const ulonglong2*)&sgx[cur][k][4];
                acc[0][0] = fma2(c0, qa.x, acc[0][0]); acc[0][1] = fma2(c0, qa.y, acc[0][1]);
                acc[0][2] = fma2(c0, qb.x, acc[0][2]); acc[0][3] = fma2(c0, qb.y, acc[0][3]);
                acc[1][0] = fma2(c1, qa.x, acc[1][0]); acc[1][1] = fma2(c1, qa.y, acc[1][1]);
                acc[1][2] = fma2(c1, qb.x, acc[1][2]); acc[1][3] = fma2(c1, qb.y, acc[1][3]);
            }
            if (c & (1u << 14)) {
                ulonglong2 qc = *(const ulonglong2*)&sgx[cur][k][8];
                ulonglong2 qd = *(const ulonglong2*)&sgx[cur][k][12];
                acc[0][4] = fma2(c0, qc.x, acc[0][4]); acc[0][5] = fma2(c0, qc.y, acc[0][5]);
                acc[0][6] = fma2(c0, qd.x, acc[0][6]); acc[0][7] = fma2(c0, qd.y, acc[0][7]);
                acc[1][4] = fma2(c1, qc.x, acc[1][4]); acc[1][5] = fma2(c1, qc.y, acc[1][5]);
                acc[1][6] = fma2(c1, qd.x, acc[1][6]); acc[1][7] = fma2(c1, qd.y, acc[1][7]);
            }
        }
    }

    if (curTile >= 0) {
        int X0 =  (curTile       & 7) << 4;
        int Y0 = ((curTile >> 3) & 7) << 4;
        int Z0 = ((curTile >> 6) & 7) << 4;
        #pragma unroll
        for (int zz = 0; zz < 2; zz++) {
            int rb = ((Z0 + 2 * zp + zz) * 128 + (Y0 + y)) * 128 + X0;
            #pragma unroll
            for (int i2 = 0; i2 < 8; i2++)
                if (acc[zz][i2]) red2(&d_vol[rb + 2 * i2], acc[zz][i2]);
        }
    }
}

// ---------------- K6: fused triple reduction (float inner, double tree) ----------------
__global__ void k_reduce(const float* __restrict__ grid) {
    __shared__ double sh0[256], sh1[256], sh2[256];
    int t = threadIdx.x;
    float s1 = 0.f, s2 = 0.f, s3 = 0.f;
    for (int i = blockIdx.x * 256 + t; i < NVOX; i += gridDim.x * 256) {
        float v = d_vol[i];
        float g = grid[i];
        s1 += v * g;
        s2 += v * v;
        s3 += g * g;
    }
    sh0[t] = (double)s1; sh1[t] = (double)s2; sh2[t] = (double)s3;
    __syncthreads();
    for (int off = 128; off > 0; off >>= 1) {
        if (t < off) {
            sh0[t] += sh0[t + off];
            sh1[t] += sh1[t + off];
            sh2[t] += sh2[t + off];
        }
        __syncthreads();
    }
    if (t == 0) {
        atomicAdd(&d_sums[0], sh0[0]);
        atomicAdd(&d_sums[1], sh1[0]);
        atomicAdd(&d_sums[2], sh2[0]);
    }
}

// ---------------- K7: scalar finish ----------------
__global__ void k_final(float* __restrict__ out) {
    out[0] = (float)(1.0 - d_sums[0] / sqrt(d_sums[1] * d_sums[2]));
}

extern "C" void kernel_launch(void* const* d_in, const int* in_sizes, int n_in,
                              void* d_out, int out_size) {
    const float* quat   = (const float*)d_in[0];
    const float* offset = (const float*)d_in[1];
    const float* pos    = (const float*)d_in[2];
    const float* amp    = (const float*)d_in[3];
    const float* var    = (const float*)d_in[4];
    const float* grid   = (const float*)d_in[5];
    float* out = (float*)d_out;

    k_zero<<<NVOX / 256, 256>>>();
    k_precompute<<<(P_N + 255) / 256, 256>>>(quat, offset, pos, amp, var);
    k_scan<<<1, 512>>>();
    k_fill<<<(P_N + 255) / 256, 256>>>();
    k_splat<<<MAXE / CHUNK, 128>>>();
    k_reduce<<<512, 256>>>(grid);
    k_final<<<1, 1>>>(out);
}

// round 7
// speedup vs baseline: 2.6288x; 1.3338x over previous
#include <cuda_runtime.h>
#include <math.h>

#define A_N   20480
#define G_N   5
#define P_N   (A_N * G_N)           // 102400 pairs
#define NVOX  (128 * 128 * 128)
#define WIN   14                    // gaussian window width (slots 0..13)
#define MAXE  (P_N * 8)
#define CHUNK 512
#define NB    32

typedef unsigned long long ull;

// ---------------- device scratch ----------------
__device__ float        d_gx[P_N * 16];
__device__ float        d_gy[P_N * 16];
__device__ float        d_gz[P_N * 16];     // prefactor folded in
__device__ int4         d_meta[P_N];        // ix0, iy0, iz0, packed tile spans (w=-1: none)
__device__ float        d_vol[NVOX];
__device__ unsigned int d_counts[512];
__device__ unsigned int d_cursor[512];
__device__ unsigned int d_entries[MAXE];    // (tile << 17) | pair
__device__ unsigned int d_total;
__device__ double       d_sums[3];          // S1, S2, S3

// ---------------- f32x2 helpers ----------------
__device__ __forceinline__ ull pack2(float lo, float hi) {
    ull r; asm("mov.b64 %0, {%1, %2};" : "=l"(r) : "f"(lo), "f"(hi)); return r;
}
__device__ __forceinline__ void unpack2(ull v, float& lo, float& hi) {
    asm("mov.b64 {%0, %1}, %2;" : "=f"(lo), "=f"(hi) : "l"(v));
}
__device__ __forceinline__ ull fma2(ull a, ull b, ull c) {
    ull d; asm("fma.rn.f32x2 %0, %1, %2, %3;" : "=l"(d) : "l"(a), "l"(b), "l"(c)); return d;
}
__device__ __forceinline__ void red2(float* p, ull v) {
    float lo, hi; unpack2(v, lo, hi);
    asm volatile("red.global.add.v2.f32 [%0], {%1, %2};" :: "l"(p), "f"(lo), "f"(hi) : "memory");
}

// ---------------- K0: zero ----------------
__global__ void k_zero() {
    int i = blockIdx.x * blockDim.x + threadIdx.x;
    d_vol[i] = 0.0f;
    if (i < 512) d_counts[i] = 0u;
    if (i < 3)   d_sums[i] = 0.0;
}

// ---------------- K2: rotate + 1D gaussians + block-aggregated tile counting ----------------
__global__ void k_precompute(const float* __restrict__ quat,
                             const float* __restrict__ offset,
                             const float* __restrict__ pos,
                             const float* __restrict__ amp,
                             const float* __restrict__ var) {
    __shared__ unsigned int scount[512];
    int t = threadIdx.x;
    scount[t] = 0u; scount[t + 256] = 0u;
    __syncthreads();

    int p = blockIdx.x * 256 + t;
    int w = -1;
    if (p < P_N) {
        float qw = quat[0], qx = quat[1], qy = quat[2], qz = quat[3];
        float qn = rsqrtf(qw * qw + qx * qx + qy * qy + qz * qz);
        qw *= qn; qx *= qn; qy *= qn; qz *= qn;
        float R00 = 1.f - 2.f * (qy * qy + qz * qz);
        float R01 = 2.f * (qx * qy - qw * qz);
        float R02 = 2.f * (qx * qz + qw * qy);
        float R10 = 2.f * (qx * qy + qw * qz);
        float R11 = 1.f - 2.f * (qx * qx + qz * qz);
        float R12 = 2.f * (qy * qz - qw * qx);
        float R20 = 2.f * (qx * qz - qw * qy);
        float R21 = 2.f * (qy * qz + qw * qx);
        float R22 = 1.f - 2.f * (qx * qx + qy * qy);

        int a = p / G_N;
        float px = pos[a * 3 + 0], py = pos[a * 3 + 1], pz = pos[a * 3 + 2];
        float cx = px * R00 + py * R10 + pz * R20 + offset[0];
        float cy = px * R01 + py * R11 + pz * R21 + offset[1];
        float cz = px * R02 + py * R12 + pz * R22 + offset[2];

        float v    = var[p];
        float am   = amp[p];
        float r    = rsqrtf(6.283185307179586f * v);
        float pref = am * r * r * r;            // amp * (2*pi*var)^(-3/2)
        float ninv = -0.5f / v;

        // even-aligned window start; covers [ix0 .. ix0+13], margin >= 5 voxels
        int ix0 = ((int)floorf(cx) + 58) & ~1;
        int iy0 = ((int)floorf(cy) + 58) & ~1;
        int iz0 = ((int)floorf(cz) + 58) & ~1;

        float q2 = __expf(2.f * ninv);
        {
            float d0 = (float)(ix0 - 64) - cx;
            float e  = __expf(ninv * d0 * d0);
            float rr = __expf(ninv * (2.f * d0 + 1.f));
            #pragma unroll
            for (int i = 0; i < WIN; i++) { d_gx[p * 16 + i] = e; e *= rr; rr *= q2; }
        }
        {
            float d0 = (float)(iy0 - 64) - cy;
            float e  = __expf(ninv * d0 * d0);
            float rr = __expf(ninv * (2.f * d0 + 1.f));
            #pragma unroll
            for (int i = 0; i < WIN; i++) { d_gy[p * 16 + i] = e; e *= rr; rr *= q2; }
        }
        {
            float d0 = (float)(iz0 - 64) - cz;
            float e  = pref * __expf(ninv * d0 * d0);
            float rr = __expf(ninv * (2.f * d0 + 1.f));
            #pragma unroll
            for (int i = 0; i < WIN; i++) { d_gz[p * 16 + i] = e; e *= rr; rr *= q2; }
        }

        int xlo = max(ix0, 0), xhi = min(ix0 + WIN - 1, 127);
        int ylo = max(iy0, 0), yhi = min(iy0 + WIN - 1, 127);
        int zlo = max(iz0, 0), zhi = min(iz0 + WIN - 1, 127);
        if (xlo <= xhi && ylo <= yhi && zlo <= zhi) {
            int txlo = xlo >> 4, txhi = xhi >> 4;
            int tylo = ylo >> 4, tyhi = yhi >> 4;
            int tzlo = zlo >> 4, tzhi = zhi >> 4;
            w = txlo | (txhi << 3) | (tylo << 6) | (tyhi << 9) | (tzlo << 12) | (tzhi << 15);
            for (int tz = tzlo; tz <= tzhi; tz++)
                for (int ty = tylo; ty <= tyhi; ty++)
                    for (int tx = txlo; tx <= txhi; tx++)
                        atomicAdd(&scount[(tz << 6) | (ty << 3) | tx], 1u);
        }
        d_meta[p] = make_int4(ix0, iy0, iz0, w);
    }
    __syncthreads();
    for (int i = t; i < 512; i += 256) {
        unsigned int c = scount[i];
        if (c) atomicAdd(&d_counts[i], c);
    }
}

// ---------------- K3: exclusive scan over 512 tiles ----------------
__global__ void k_scan() {
    __shared__ unsigned int s[512];
    int t = threadIdx.x;
    unsigned int own = d_counts[t];
    s[t] = own;
    __syncthreads();
    for (int off = 1; off < 512; off <<= 1) {
        unsigned int v = (t >= off) ? s[t - off] : 0u;
        __syncthreads();
        s[t] += v;
        __syncthreads();
    }
    d_cursor[t] = s[t] - own;
    if (t == 511) d_total = s[511];
}

// ---------------- K4: fill entry list, block-aggregated cursors ----------------
__global__ void k_fill() {
    __shared__ unsigned int scount[512];
    __shared__ unsigned int sbase[512];
    int t = threadIdx.x;
    scount[t] = 0u; scount[t + 256] = 0u;
    __syncthreads();

    int p = blockIdx.x * 256 + t;
    int w = (p < P_N) ? d_meta[p].w : -1;
    int txlo = 0, txhi = -1, tylo = 0, tyhi = -1, tzlo = 0, tzhi = -1;
    if (w >= 0) {
        txlo =  w        & 7; txhi = (w >> 3)  & 7;
        tylo = (w >> 6)  & 7; tyhi = (w >> 9)  & 7;
        tzlo = (w >> 12) & 7; tzhi = (w >> 15) & 7;
        for (int tz = tzlo; tz <= tzhi; tz++)
            for (int ty = tylo; ty <= tyhi; ty++)
                for (int tx = txlo; tx <= txhi; tx++)
                    atomicAdd(&scount[(tz << 6) | (ty << 3) | tx], 1u);
    }
    __syncthreads();
    for (int i = t; i < 512; i += 256) {
        unsigned int c = scount[i];
        sbase[i] = c ? atomicAdd(&d_cursor[i], c) : 0u;
    }
    __syncthreads();
    if (w >= 0) {
        for (int tz = tzlo; tz <= tzhi; tz++)
            for (int ty = tylo; ty <= tyhi; ty++)
                for (int tx = txlo; tx <= txhi; tx++) {
                    int tile = (tz << 6) | (ty << 3) | tx;
                    unsigned int posn = atomicAdd(&sbase[tile], 1u);
                    d_entries[posn] = ((unsigned int)tile << 17) | (unsigned int)p;
                }
    }
}

// ---------------- K5: splat — 128 thr, double-buffered, branchless-x inner loop ----------------
__global__ void __launch_bounds__(128) k_splat() {
    __shared__ __align__(16) float sgx[2][NB][16];
    __shared__ __align__(16) float sgy[2][NB][16];
    __shared__ __align__(16) float sgz[2][NB][16];
    __shared__ unsigned int scombo[2][NB];

    unsigned int total = d_total;
    unsigned int s = (unsigned int)blockIdx.x * CHUNK;
    if (s >= total) return;
    unsigned int e_end = s + CHUNK;
    if (e_end > total) e_end = total;

    int t   = threadIdx.x;
    int y   = t & 15;         // owned y row
    int zp  = t >> 4;         // owned z rows: 2*zp, 2*zp+1
    int wid = t >> 5;         // warp id 0..3, covers z in [4w, 4w+4)

    ull acc[2][8];            // [zz][x-pair]
    #pragma unroll
    for (int r = 0; r < 2; r++)
        #pragma unroll
        for (int i = 0; i < 8; i++) acc[r][i] = 0ull;

    // stage batch into buffer buf: tile-aligned, zero-padded gaussians
    auto stage = [&](int buf, unsigned int base, int n) {
        for (int s2 = t; s2 < n * 16; s2 += 128) {
            int b = s2 >> 4, l = s2 & 15;
            unsigned int ent = d_entries[base + (unsigned int)b];
            int pid  = (int)(ent & 0x1FFFFu);
            int tile = (int)(ent >> 17);
            int4 mt = d_meta[pid];
            int X0 =  (tile       & 7) << 4;
            int Y0 = ((tile >> 3) & 7) << 4;
            int Z0 = ((tile >> 6) & 7) << 4;
            int ox = X0 - mt.x, oy = Y0 - mt.y, oz = Z0 - mt.z;
            int ix = l + ox, iy = l + oy, iz = l + oz;   // window slot per tile-local l
            sgx[buf][b][l] = ((unsigned)ix < (unsigned)WIN) ? d_gx[pid * 16 + ix] : 0.f;
            sgy[buf][b][l] = ((unsigned)iy < (unsigned)WIN) ? d_gy[pid * 16 + iy] : 0.f;
            sgz[buf][b][l] = ((unsigned)iz < (unsigned)WIN) ? d_gz[pid * 16 + iz] : 0.f;
            if (l == 0) {
                int loz = max(0, -oz), hiz = min(15, (WIN - 1) - oz);
                unsigned int c = (unsigned int)tile;
                #pragma unroll
                for (int w = 0; w < 4; w++)
                    if (loz <= 4 * w + 3 && hiz >= 4 * w) c |= 1u << (9 + w);
                scombo[buf][b] = c;
            }
        }
    };

    int curTile = -1;
    int nbatch = (int)((e_end - s + NB - 1) / NB);

    stage(0, s, (int)min((unsigned int)NB, e_end - s));

    for (int i = 0; i < nbatch; i++) {
        __syncthreads();                 // buf[i&1] staged; other buf consumed
        int cur = i & 1;
        if (i + 1 < nbatch) {
            unsigned int bnext = s + (unsigned int)(i + 1) * NB;
            stage(cur ^ 1, bnext, (int)min((unsigned int)NB, e_end - bnext));
        }
        int n = (int)min((unsigned int)NB, e_end - (s + (unsigned int)i * NB));

        for (int k = 0; k < n; k++) {
            unsigned int c = scombo[cur][k];
            int tile = (int)(c & 511u);
            if (tile != curTile) {
                if (curTile >= 0) {
                    int X0 =  (curTile       & 7) << 4;
                    int Y0 = ((curTile >> 3) & 7) << 4;
                    int Z0 = ((curTile >> 6) & 7) << 4;
                    #pragma unroll
                    for (int zz = 0; zz < 2; zz++) {
                        int rb = ((Z0 + 2 * zp + zz) * 128 + (Y0 + y)) * 128 + X0;
                        #pragma unroll
                        for (int i2 = 0; i2 < 8; i2++)
                            if (acc[zz][i2]) red2(&d_vol[rb + 2 * i2], acc[zz][i2]);
                    }
                    #pragma unroll
                    for (int r = 0; r < 2; r++)
                        #pragma unroll
                        for (int i2 = 0; i2 < 8; i2++) acc[r][i2] = 0ull;
                }
                curTile = tile;
            }
            if (!((c >> (9 + wid)) & 1u)) continue;   // warp z-skip (~1/3 rejected)

            // branchless x: buffers are zero-padded, uncovered cells FMA zeros
            float  gyv = sgy[cur][k][y];
            float2 gzp = *(const float2*)&sgz[cur][k][2 * zp];
            float a0 = gyv * gzp.x;
            float a1 = gyv * gzp.y;
            ull c0 = pack2(a0, a0), c1 = pack2(a1, a1);

            ulonglong2 qa = *(const ulonglong2*)&sgx[cur][k][0];
            ulonglong2 qb = *(const ulonglong2*)&sgx[cur][k][4];
            ulonglong2 qc = *(const ulonglong2*)&sgx[cur][k][8];
            ulonglong2 qd = *(const ulonglong2*)&sgx[cur][k][12];
            acc[0][0] = fma2(c0, qa.x, acc[0][0]); acc[0][1] = fma2(c0, qa.y, acc[0][1]);
            acc[0][2] = fma2(c0, qb.x, acc[0][2]); acc[0][3] = fma2(c0, qb.y, acc[0][3]);
            acc[0][4] = fma2(c0, qc.x, acc[0][4]); acc[0][5] = fma2(c0, qc.y, acc[0][5]);
            acc[0][6] = fma2(c0, qd.x, acc[0][6]); acc[0][7] = fma2(c0, qd.y, acc[0][7]);
            acc[1][0] = fma2(c1, qa.x, acc[1][0]); acc[1][1] = fma2(c1, qa.y, acc[1][1]);
            acc[1][2] = fma2(c1, qb.x, acc[1][2]); acc[1][3] = fma2(c1, qb.y, acc[1][3]);
            acc[1][4] = fma2(c1, qc.x, acc[1][4]); acc[1][5] = fma2(c1, qc.y, acc[1][5]);
            acc[1][6] = fma2(c1, qd.x, acc[1][6]); acc[1][7] = fma2(c1, qd.y, acc[1][7]);
        }
    }

    if (curTile >= 0) {
        int X0 =  (curTile       & 7) << 4;
        int Y0 = ((curTile >> 3) & 7) << 4;
        int Z0 = ((curTile >> 6) & 7) << 4;
        #pragma unroll
        for (int zz = 0; zz < 2; zz++) {
            int rb = ((Z0 + 2 * zp + zz) * 128 + (Y0 + y)) * 128 + X0;
            #pragma unroll
            for (int i2 = 0; i2 < 8; i2++)
                if (acc[zz][i2]) red2(&d_vol[rb + 2 * i2], acc[zz][i2]);
        }
    }
}

// ---------------- K6: fused triple reduction (float inner, double tree) ----------------
__global__ void k_reduce(const float* __restrict__ grid) {
    __shared__ double sh0[256], sh1[256], sh2[256];
    int t = threadIdx.x;
    float s1 = 0.f, s2 = 0.f, s3 = 0.f;
    for (int i = blockIdx.x * 256 + t; i < NVOX; i += gridDim.x * 256) {
        float v = d_vol[i];
        float g = grid[i];
        s1 += v * g;
        s2 += v * v;
        s3 += g * g;
    }
    sh0[t] = (double)s1; sh1[t] = (double)s2; sh2[t] = (double)s3;
    __syncthreads();
    for (int off = 128; off > 0; off >>= 1) {
        if (t < off) {
            sh0[t] += sh0[t + off];
            sh1[t] += sh1[t + off];
            sh2[t] += sh2[t + off];
        }
        __syncthreads();
    }
    if (t == 0) {
        atomicAdd(&d_sums[0], sh0[0]);
        atomicAdd(&d_sums[1], sh1[0]);
        atomicAdd(&d_sums[2], sh2[0]);
    }
}

// ---------------- K7: scalar finish ----------------
__global__ void k_final(float* __restrict__ out) {
    out[0] = (float)(1.0 - d_sums[0] / sqrt(d_sums[1] * d_sums[2]));
}

extern "C" void kernel_launch(void* const* d_in, const int* in_sizes, int n_in,
                              void* d_out, int out_size) {
    const float* quat   = (const float*)d_in[0];
    const float* offset = (const float*)d_in[1];
    const float* pos    = (const float*)d_in[2];
    const float* amp    = (const float*)d_in[3];
    const float* var    = (const float*)d_in[4];
    const float* grid   = (const float*)d_in[5];
    float* out = (float*)d_out;

    k_zero<<<NVOX / 256, 256>>>();
    k_precompute<<<(P_N + 255) / 256, 256>>>(quat, offset, pos, amp, var);
    k_scan<<<1, 512>>>();
    k_fill<<<(P_N + 255) / 256, 256>>>();
    k_splat<<<MAXE / CHUNK, 128>>>();
    k_reduce<<<512, 256>>>(grid);
    k_final<<<1, 1>>>(out);
}

// round 8
// speedup vs baseline: 3.1573x; 1.2011x over previous
#include <cuda_runtime.h>
#include <math.h>

#define A_N   20480
#define G_N   5
#define P_N   (A_N * G_N)           // 102400 pairs
#define NVOX  (128 * 128 * 128)
#define WIN   14                    // gaussian window width (slots 0..13)
#define MAXE  (P_N * 8)
#define CHUNK 512
#define NB    32
#define MAXC  (512 + MAXE / CHUNK)  // max chunk descriptors (2112)

typedef unsigned long long ull;

// ---------------- device scratch ----------------
__device__ float        d_gx[P_N * 16];
__device__ float        d_gy[P_N * 16];
__device__ float        d_gz[P_N * 16];     // prefactor folded in
__device__ int4         d_meta[P_N];        // ix0, iy0, iz0, packed tile spans (w=-1: none)
__device__ float        d_vol[NVOX];
__device__ unsigned int d_counts[512];
__device__ unsigned int d_segstart[512];
__device__ unsigned int d_cursor[512];
__device__ unsigned int d_chunkbase[512];
__device__ uint2        d_chunkdesc[MAXC];  // {entry start, tile | (len<<16)}
__device__ unsigned int d_nchunks;
__device__ unsigned int d_entries[MAXE];    // (tile << 17) | pair
__device__ unsigned int d_total;
__device__ double       d_sums[3];          // S1, S2, S3

// ---------------- f32x2 helpers ----------------
__device__ __forceinline__ ull pack2(float lo, float hi) {
    ull r; asm("mov.b64 %0, {%1, %2};" : "=l"(r) : "f"(lo), "f"(hi)); return r;
}
__device__ __forceinline__ void unpack2(ull v, float& lo, float& hi) {
    asm("mov.b64 {%0, %1}, %2;" : "=f"(lo), "=f"(hi) : "l"(v));
}
__device__ __forceinline__ ull fma2(ull a, ull b, ull c) {
    ull d; asm("fma.rn.f32x2 %0, %1, %2, %3;" : "=l"(d) : "l"(a), "l"(b), "l"(c)); return d;
}
__device__ __forceinline__ void red2(float* p, ull v) {
    float lo, hi; unpack2(v, lo, hi);
    asm volatile("red.global.add.v2.f32 [%0], {%1, %2};" :: "l"(p), "f"(lo), "f"(hi) : "memory");
}

// ---------------- K0: zero ----------------
__global__ void k_zero() {
    int i = blockIdx.x * blockDim.x + threadIdx.x;
    d_vol[i] = 0.0f;
    if (i < 512) d_counts[i] = 0u;
    if (i < 3)   d_sums[i] = 0.0;
}

// ---------------- K2: rotate + 1D gaussians + block-aggregated tile counting ----------------
__global__ void k_precompute(const float* __restrict__ quat,
                             const float* __restrict__ offset,
                             const float* __restrict__ pos,
                             const float* __restrict__ amp,
                             const float* __restrict__ var) {
    __shared__ unsigned int scount[512];
    int t = threadIdx.x;
    scount[t] = 0u; scount[t + 256] = 0u;
    __syncthreads();

    int p = blockIdx.x * 256 + t;
    int w = -1;
    if (p < P_N) {
        float qw = quat[0], qx = quat[1], qy = quat[2], qz = quat[3];
        float qn = rsqrtf(qw * qw + qx * qx + qy * qy + qz * qz);
        qw *= qn; qx *= qn; qy *= qn; qz *= qn;
        float R00 = 1.f - 2.f * (qy * qy + qz * qz);
        float R01 = 2.f * (qx * qy - qw * qz);
        float R02 = 2.f * (qx * qz + qw * qy);
        float R10 = 2.f * (qx * qy + qw * qz);
        float R11 = 1.f - 2.f * (qx * qx + qz * qz);
        float R12 = 2.f * (qy * qz - qw * qx);
        float R20 = 2.f * (qx * qz - qw * qy);
        float R21 = 2.f * (qy * qz + qw * qx);
        float R22 = 1.f - 2.f * (qx * qx + qy * qy);

        int a = p / G_N;
        float px = pos[a * 3 + 0], py = pos[a * 3 + 1], pz = pos[a * 3 + 2];
        float cx = px * R00 + py * R10 + pz * R20 + offset[0];
        float cy = px * R01 + py * R11 + pz * R21 + offset[1];
        float cz = px * R02 + py * R12 + pz * R22 + offset[2];

        float v    = var[p];
        float am   = amp[p];
        float r    = rsqrtf(6.283185307179586f * v);
        float pref = am * r * r * r;            // amp * (2*pi*var)^(-3/2)
        float ninv = -0.5f / v;

        // even-aligned window start; covers [ix0 .. ix0+13], margin >= 5 voxels
        int ix0 = ((int)floorf(cx) + 58) & ~1;
        int iy0 = ((int)floorf(cy) + 58) & ~1;
        int iz0 = ((int)floorf(cz) + 58) & ~1;

        float q2 = __expf(2.f * ninv);
        {
            float d0 = (float)(ix0 - 64) - cx;
            float e  = __expf(ninv * d0 * d0);
            float rr = __expf(ninv * (2.f * d0 + 1.f));
            #pragma unroll
            for (int i = 0; i < WIN; i++) { d_gx[p * 16 + i] = e; e *= rr; rr *= q2; }
        }
        {
            float d0 = (float)(iy0 - 64) - cy;
            float e  = __expf(ninv * d0 * d0);
            float rr = __expf(ninv * (2.f * d0 + 1.f));
            #pragma unroll
            for (int i = 0; i < WIN; i++) { d_gy[p * 16 + i] = e; e *= rr; rr *= q2; }
        }
        {
            float d0 = (float)(iz0 - 64) - cz;
            float e  = pref * __expf(ninv * d0 * d0);
            float rr = __expf(ninv * (2.f * d0 + 1.f));
            #pragma unroll
            for (int i = 0; i < WIN; i++) { d_gz[p * 16 + i] = e; e *= rr; rr *= q2; }
        }

        int xlo = max(ix0, 0), xhi = min(ix0 + WIN - 1, 127);
        int ylo = max(iy0, 0), yhi = min(iy0 + WIN - 1, 127);
        int zlo = max(iz0, 0), zhi = min(iz0 + WIN - 1, 127);
        if (xlo <= xhi && ylo <= yhi && zlo <= zhi) {
            int txlo = xlo >> 4, txhi = xhi >> 4;
            int tylo = ylo >> 4, tyhi = yhi >> 4;
            int tzlo = zlo >> 4, tzhi = zhi >> 4;
            w = txlo | (txhi << 3) | (tylo << 6) | (tyhi << 9) | (tzlo << 12) | (tzhi << 15);
            for (int tz = tzlo; tz <= tzhi; tz++)
                for (int ty = tylo; ty <= tyhi; ty++)
                    for (int tx = txlo; tx <= txhi; tx++)
                        atomicAdd(&scount[(tz << 6) | (ty << 3) | tx], 1u);
        }
        d_meta[p] = make_int4(ix0, iy0, iz0, w);
    }
    __syncthreads();
    for (int i = t; i < 512; i += 256) {
        unsigned int c = scount[i];
        if (c) atomicAdd(&d_counts[i], c);
    }
}

// ---------------- K3: scans (segments + chunk descriptors base) ----------------
__global__ void k_scan() {
    __shared__ unsigned int s[512];
    int t = threadIdx.x;
    unsigned int own = d_counts[t];
    s[t] = own;
    __syncthreads();
    for (int off = 1; off < 512; off <<= 1) {
        unsigned int v = (t >= off) ? s[t - off] : 0u;
        __syncthreads();
        s[t] += v;
        __syncthreads();
    }
    unsigned int segstart = s[t] - own;
    d_segstart[t] = segstart;
    d_cursor[t]   = segstart;
    if (t == 511) d_total = s[511];
    __syncthreads();

    // second scan: chunk counts
    unsigned int nch = (own + CHUNK - 1) / CHUNK;
    s[t] = nch;
    __syncthreads();
    for (int off = 1; off < 512; off <<= 1) {
        unsigned int v = (t >= off) ? s[t - off] : 0u;
        __syncthreads();
        s[t] += v;
        __syncthreads();
    }
    d_chunkbase[t] = s[t] - nch;
    if (t == 511) d_nchunks = s[511];
}

// ---------------- K3b: emit per-tile chunk descriptors ----------------
__global__ void k_chunks() {
    int t = threadIdx.x;
    unsigned int cnt = d_counts[t];
    unsigned int st  = d_segstart[t];
    unsigned int cb  = d_chunkbase[t];
    for (unsigned int j = 0; j * CHUNK < cnt; j++) {
        unsigned int len = min((unsigned int)CHUNK, cnt - j * CHUNK);
        d_chunkdesc[cb + j] = make_uint2(st + j * CHUNK,
                                         (unsigned int)t | (len << 16));
    }
}

// ---------------- K4: fill entry list, block-aggregated cursors ----------------
__global__ void k_fill() {
    __shared__ unsigned int scount[512];
    __shared__ unsigned int sbase[512];
    int t = threadIdx.x;
    scount[t] = 0u; scount[t + 256] = 0u;
    __syncthreads();

    int p = blockIdx.x * 256 + t;
    int w = (p < P_N) ? d_meta[p].w : -1;
    int txlo = 0, txhi = -1, tylo = 0, tyhi = -1, tzlo = 0, tzhi = -1;
    if (w >= 0) {
        txlo =  w        & 7; txhi = (w >> 3)  & 7;
        tylo = (w >> 6)  & 7; tyhi = (w >> 9)  & 7;
        tzlo = (w >> 12) & 7; tzhi = (w >> 15) & 7;
        for (int tz = tzlo; tz <= tzhi; tz++)
            for (int ty = tylo; ty <= tyhi; ty++)
                for (int tx = txlo; tx <= txhi; tx++)
                    atomicAdd(&scount[(tz << 6) | (ty << 3) | tx], 1u);
    }
    __syncthreads();
    for (int i = t; i < 512; i += 256) {
        unsigned int c = scount[i];
        sbase[i] = c ? atomicAdd(&d_cursor[i], c) : 0u;
    }
    __syncthreads();
    if (w >= 0) {
        for (int tz = tzlo; tz <= tzhi; tz++)
            for (int ty = tylo; ty <= tyhi; ty++)
                for (int tx = txlo; tx <= txhi; tx++) {
                    int tile = (tz << 6) | (ty << 3) | tx;
                    unsigned int posn = atomicAdd(&sbase[tile], 1u);
                    d_entries[posn] = ((unsigned int)tile << 17) | (unsigned int)p;
                }
    }
}

// ---------------- K5: splat — one tile per CTA chunk, no mid-loop flush ----------------
__global__ void __launch_bounds__(128) k_splat() {
    __shared__ __align__(16) float sgx[2][NB][16];
    __shared__ __align__(16) float sgy[2][NB][16];
    __shared__ __align__(16) float sgz[2][NB][16];
    __shared__ unsigned int szmask[2][NB];

    if (blockIdx.x >= d_nchunks) return;
    uint2 desc = d_chunkdesc[blockIdx.x];
    unsigned int s   = desc.x;
    int tile         = (int)(desc.y & 0x1FFu);
    unsigned int len = desc.y >> 16;
    unsigned int e_end = s + len;

    int X0 =  (tile       & 7) << 4;
    int Y0 = ((tile >> 3) & 7) << 4;
    int Z0 = ((tile >> 6) & 7) << 4;

    int t   = threadIdx.x;
    int y   = t & 15;         // owned y row
    int zp  = t >> 4;         // owned z rows: 2*zp, 2*zp+1
    int wid = t >> 5;         // warp id 0..3, covers z in [4w, 4w+4)

    ull acc[2][8];            // [zz][x-pair]
    #pragma unroll
    for (int r = 0; r < 2; r++)
        #pragma unroll
        for (int i = 0; i < 8; i++) acc[r][i] = 0ull;

    // stage batch into buffer buf: tile-aligned, zero-padded gaussians
    auto stage = [&](int buf, unsigned int base, int n) {
        for (int s2 = t; s2 < n * 16; s2 += 128) {
            int b = s2 >> 4, l = s2 & 15;
            unsigned int ent = d_entries[base + (unsigned int)b];
            int pid = (int)(ent & 0x1FFFFu);
            int4 mt = d_meta[pid];
            int ox = X0 - mt.x, oy = Y0 - mt.y, oz = Z0 - mt.z;
            int ix = l + ox, iy = l + oy, iz = l + oz;   // window slot per tile-local l
            sgx[buf][b][l] = ((unsigned)ix < (unsigned)WIN) ? d_gx[pid * 16 + ix] : 0.f;
            sgy[buf][b][l] = ((unsigned)iy < (unsigned)WIN) ? d_gy[pid * 16 + iy] : 0.f;
            sgz[buf][b][l] = ((unsigned)iz < (unsigned)WIN) ? d_gz[pid * 16 + iz] : 0.f;
            if (l == 0) {
                int loz = max(0, -oz), hiz = min(15, (WIN - 1) - oz);
                unsigned int c = 0u;
                #pragma unroll
                for (int w = 0; w < 4; w++)
                    if (loz <= 4 * w + 3 && hiz >= 4 * w) c |= 1u << w;
                szmask[buf][b] = c;
            }
        }
    };

    int nbatch = (int)((len + NB - 1) / NB);
    stage(0, s, (int)min((unsigned int)NB, len));

    for (int i = 0; i < nbatch; i++) {
        __syncthreads();                 // buf[i&1] staged; other buf consumed
        int cur = i & 1;
        if (i + 1 < nbatch) {
            unsigned int bnext = s + (unsigned int)(i + 1) * NB;
            stage(cur ^ 1, bnext, (int)min((unsigned int)NB, e_end - bnext));
        }
        int n = (int)min((unsigned int)NB, e_end - (s + (unsigned int)i * NB));

        for (int k = 0; k < n; k++) {
            if (!((szmask[cur][k] >> wid) & 1u)) continue;   // warp z-skip (~1/3)

            float  gyv = sgy[cur][k][y];
            float2 gzp = *(const float2*)&sgz[cur][k][2 * zp];
            float a0 = gyv * gzp.x;
            float a1 = gyv * gzp.y;
            ull c0 = pack2(a0, a0), c1 = pack2(a1, a1);

            ulonglong2 qa = *(const ulonglong2*)&sgx[cur][k][0];
            ulonglong2 qb = *(const ulonglong2*)&sgx[cur][k][4];
            ulonglong2 qc = *(const ulonglong2*)&sgx[cur][k][8];
            ulonglong2 qd = *(const ulonglong2*)&sgx[cur][k][12];
            acc[0][0] = fma2(c0, qa.x, acc[0][0]); acc[0][1] = fma2(c0, qa.y, acc[0][1]);
            acc[0][2] = fma2(c0, qb.x, acc[0][2]); acc[0][3] = fma2(c0, qb.y, acc[0][3]);
            acc[0][4] = fma2(c0, qc.x, acc[0][4]); acc[0][5] = fma2(c0, qc.y, acc[0][5]);
            acc[0][6] = fma2(c0, qd.x, acc[0][6]); acc[0][7] = fma2(c0, qd.y, acc[0][7]);
            acc[1][0] = fma2(c1, qa.x, acc[1][0]); acc[1][1] = fma2(c1, qa.y, acc[1][1]);
            acc[1][2] = fma2(c1, qb.x, acc[1][2]); acc[1][3] = fma2(c1, qb.y, acc[1][3]);
            acc[1][4] = fma2(c1, qc.x, acc[1][4]); acc[1][5] = fma2(c1, qc.y, acc[1][5]);
            acc[1][6] = fma2(c1, qd.x, acc[1][6]); acc[1][7] = fma2(c1, qd.y, acc[1][7]);
        }
    }

    // single flush at CTA end
    #pragma unroll
    for (int zz = 0; zz < 2; zz++) {
        int rb = ((Z0 + 2 * zp + zz) * 128 + (Y0 + y)) * 128 + X0;
        #pragma unroll
        for (int i2 = 0; i2 < 8; i2++)
            if (acc[zz][i2]) red2(&d_vol[rb + 2 * i2], acc[zz][i2]);
    }
}

// ---------------- K6: fused triple reduction (float inner, double tree) ----------------
__global__ void k_reduce(const float* __restrict__ grid) {
    __shared__ double sh0[256], sh1[256], sh2[256];
    int t = threadIdx.x;
    float s1 = 0.f, s2 = 0.f, s3 = 0.f;
    for (int i = blockIdx.x * 256 + t; i < NVOX; i += gridDim.x * 256) {
        float v = d_vol[i];
        float g = grid[i];
        s1 += v * g;
        s2 += v * v;
        s3 += g * g;
    }
    sh0[t] = (double)s1; sh1[t] = (double)s2; sh2[t] = (double)s3;
    __syncthreads();
    for (int off = 128; off > 0; off >>= 1) {
        if (t < off) {
            sh0[t] += sh0[t + off];
            sh1[t] += sh1[t + off];
            sh2[t] += sh2[t + off];
        }
        __syncthreads();
    }
    if (t == 0) {
        atomicAdd(&d_sums[0], sh0[0]);
        atomicAdd(&d_sums[1], sh1[0]);
        atomicAdd(&d_sums[2], sh2[0]);
    }
}

// ---------------- K7: scalar finish ----------------
__global__ void k_final(float* __restrict__ out) {
    out[0] = (float)(1.0 - d_sums[0] / sqrt(d_sums[1] * d_sums[2]));
}

extern "C" void kernel_launch(void* const* d_in, const int* in_sizes, int n_in,
                              void* d_out, int out_size) {
    const float* quat   = (const float*)d_in[0];
    const float* offset = (const float*)d_in[1];
    const float* pos    = (const float*)d_in[2];
    const float* amp    = (const float*)d_in[3];
    const float* var    = (const float*)d_in[4];
    const float* grid   = (const float*)d_in[5];
    float* out = (float*)d_out;

    k_zero<<<NVOX / 256, 256>>>();
    k_precompute<<<(P_N + 255) / 256, 256>>>(quat, offset, pos, amp, var);
    k_scan<<<1, 512>>>();
    k_chunks<<<1, 512>>>();
    k_fill<<<(P_N + 255) / 256, 256>>>();
    k_splat<<<MAXC, 128>>>();
    k_reduce<<<512, 256>>>(grid);
    k_final<<<1, 1>>>(out);
}

// round 9
// speedup vs baseline: 3.2282x; 1.0224x over previous
#include <cuda_runtime.h>
#include <math.h>

#define A_N   20480
#define G_N   5
#define P_N   (A_N * G_N)           // 102400 pairs
#define NVOX  (128 * 128 * 128)
#define WIN   14                    // gaussian window width (slots 0..13)
#define MAXE  (P_N * 8)
#define CHUNK 512
#define NB    32                    // batch size == warp width (ballot compaction)
#define MAXC  (512 + MAXE / CHUNK)  // max chunk descriptors (2112)

typedef unsigned long long ull;

// ---------------- device scratch ----------------
__device__ float        d_gx[P_N * 16];
__device__ float        d_gy[P_N * 16];
__device__ float        d_gz[P_N * 16];     // prefactor folded in
__device__ int4         d_meta[P_N];        // ix0, iy0, iz0, packed tile spans (w=-1: none)
__device__ float        d_vol[NVOX];
__device__ unsigned int d_counts[512];
__device__ unsigned int d_segstart[512];
__device__ unsigned int d_cursor[512];
__device__ uint2        d_chunkdesc[MAXC];  // {entry start, tile | (len<<16)}
__device__ unsigned int d_nchunks;
__device__ unsigned int d_entries[MAXE];    // (tile << 17) | pair
__device__ unsigned int d_total;
__device__ double       d_sums[3];          // S1, S2, S3

// ---------------- f32x2 helpers ----------------
__device__ __forceinline__ ull pack2(float lo, float hi) {
    ull r; asm("mov.b64 %0, {%1, %2};" : "=l"(r) : "f"(lo), "f"(hi)); return r;
}
__device__ __forceinline__ void unpack2(ull v, float& lo, float& hi) {
    asm("mov.b64 {%0, %1}, %2;" : "=f"(lo), "=f"(hi) : "l"(v));
}
__device__ __forceinline__ ull fma2(ull a, ull b, ull c) {
    ull d; asm("fma.rn.f32x2 %0, %1, %2, %3;" : "=l"(d) : "l"(a), "l"(b), "l"(c)); return d;
}
__device__ __forceinline__ void red2(float* p, ull v) {
    float lo, hi; unpack2(v, lo, hi);
    asm volatile("red.global.add.v2.f32 [%0], {%1, %2};" :: "l"(p), "f"(lo), "f"(hi) : "memory");
}

// ---------------- K0: zero (vectorized) ----------------
__global__ void k_zero() {
    int i = blockIdx.x * blockDim.x + threadIdx.x;
    ((float4*)d_vol)[i] = make_float4(0.f, 0.f, 0.f, 0.f);
    if (i < 512) d_counts[i] = 0u;
}

// ---------------- K2: rotate + 1D gaussians (reg rows, float4 stores) + tile counting ----------------
__global__ void k_precompute(const float* __restrict__ quat,
                             const float* __restrict__ offset,
                             const float* __restrict__ pos,
                             const float* __restrict__ amp,
                             const float* __restrict__ var) {
    __shared__ unsigned int scount[512];
    int t = threadIdx.x;
    scount[t] = 0u; scount[t + 256] = 0u;
    __syncthreads();

    int p = blockIdx.x * 256 + t;
    int w = -1;
    if (p < P_N) {
        float qw = quat[0], qx = quat[1], qy = quat[2], qz = quat[3];
        float qn = rsqrtf(qw * qw + qx * qx + qy * qy + qz * qz);
        qw *= qn; qx *= qn; qy *= qn; qz *= qn;
        float R00 = 1.f - 2.f * (qy * qy + qz * qz);
        float R01 = 2.f * (qx * qy - qw * qz);
        float R02 = 2.f * (qx * qz + qw * qy);
        float R10 = 2.f * (qx * qy + qw * qz);
        float R11 = 1.f - 2.f * (qx * qx + qz * qz);
        float R12 = 2.f * (qy * qz - qw * qx);
        float R20 = 2.f * (qx * qz - qw * qy);
        float R21 = 2.f * (qy * qz + qw * qx);
        float R22 = 1.f - 2.f * (qx * qx + qy * qy);

        int a = p / G_N;
        float px = pos[a * 3 + 0], py = pos[a * 3 + 1], pz = pos[a * 3 + 2];
        float cx = px * R00 + py * R10 + pz * R20 + offset[0];
        float cy = px * R01 + py * R11 + pz * R21 + offset[1];
        float cz = px * R02 + py * R12 + pz * R22 + offset[2];

        float v    = var[p];
        float am   = amp[p];
        float r    = rsqrtf(6.283185307179586f * v);
        float pref = am * r * r * r;            // amp * (2*pi*var)^(-3/2)
        float ninv = -0.5f / v;

        // even-aligned window start; covers [ix0 .. ix0+13], margin >= 5 voxels
        int ix0 = ((int)floorf(cx) + 58) & ~1;
        int iy0 = ((int)floorf(cy) + 58) & ~1;
        int iz0 = ((int)floorf(cz) + 58) & ~1;

        float q2 = __expf(2.f * ninv);
        float g[16];
        {
            float d0 = (float)(ix0 - 64) - cx;
            float e  = __expf(ninv * d0 * d0);
            float rr = __expf(ninv * (2.f * d0 + 1.f));
            #pragma unroll
            for (int i = 0; i < 16; i++) { g[i] = (i < WIN) ? e : 0.f; e *= rr; rr *= q2; }
            float4* dst = (float4*)&d_gx[p * 16];
            dst[0] = make_float4(g[0], g[1], g[2], g[3]);
            dst[1] = make_float4(g[4], g[5], g[6], g[7]);
            dst[2] = make_float4(g[8], g[9], g[10], g[11]);
            dst[3] = make_float4(g[12], g[13], 0.f, 0.f);
        }
        {
            float d0 = (float)(iy0 - 64) - cy;
            float e  = __expf(ninv * d0 * d0);
            float rr = __expf(ninv * (2.f * d0 + 1.f));
            #pragma unroll
            for (int i = 0; i < 16; i++) { g[i] = (i < WIN) ? e : 0.f; e *= rr; rr *= q2; }
            float4* dst = (float4*)&d_gy[p * 16];
            dst[0] = make_float4(g[0], g[1], g[2], g[3]);
            dst[1] = make_float4(g[4], g[5], g[6], g[7]);
            dst[2] = make_float4(g[8], g[9], g[10], g[11]);
            dst[3] = make_float4(g[12], g[13], 0.f, 0.f);
        }
        {
            float d0 = (float)(iz0 - 64) - cz;
            float e  = pref * __expf(ninv * d0 * d0);
            float rr = __expf(ninv * (2.f * d0 + 1.f));
            #pragma unroll
            for (int i = 0; i < 16; i++) { g[i] = (i < WIN) ? e : 0.f; e *= rr; rr *= q2; }
            float4* dst = (float4*)&d_gz[p * 16];
            dst[0] = make_float4(g[0], g[1], g[2], g[3]);
            dst[1] = make_float4(g[4], g[5], g[6], g[7]);
            dst[2] = make_float4(g[8], g[9], g[10], g[11]);
            dst[3] = make_float4(g[12], g[13], 0.f, 0.f);
        }

        int xlo = max(ix0, 0), xhi = min(ix0 + WIN - 1, 127);
        int ylo = max(iy0, 0), yhi = min(iy0 + WIN - 1, 127);
        int zlo = max(iz0, 0), zhi = min(iz0 + WIN - 1, 127);
        if (xlo <= xhi && ylo <= yhi && zlo <= zhi) {
            int txlo = xlo >> 4, txhi = xhi >> 4;
            int tylo = ylo >> 4, tyhi = yhi >> 4;
            int tzlo = zlo >> 4, tzhi = zhi >> 4;
            w = txlo | (txhi << 3) | (tylo << 6) | (tyhi << 9) | (tzlo << 12) | (tzhi << 15);
            for (int tz = tzlo; tz <= tzhi; tz++)
                for (int ty = tylo; ty <= tyhi; ty++)
                    for (int tx = txlo; tx <= txhi; tx++)
                        atomicAdd(&scount[(tz << 6) | (ty << 3) | tx], 1u);
        }
        d_meta[p] = make_int4(ix0, iy0, iz0, w);
    }
    __syncthreads();
    for (int i = t; i < 512; i += 256) {
        unsigned int c = scount[i];
        if (c) atomicAdd(&d_counts[i], c);
    }
}

// ---------------- K3: scans + chunk descriptor emission + sums zero ----------------
__global__ void k_scan() {
    __shared__ unsigned int s[512];
    int t = threadIdx.x;
    unsigned int own = d_counts[t];
    s[t] = own;
    __syncthreads();
    for (int off = 1; off < 512; off <<= 1) {
        unsigned int v = (t >= off) ? s[t - off] : 0u;
        __syncthreads();
        s[t] += v;
        __syncthreads();
    }
    unsigned int segstart = s[t] - own;
    d_segstart[t] = segstart;
    d_cursor[t]   = segstart;
    if (t == 511) d_total = s[511];
    if (t < 3)    d_sums[t] = 0.0;
    __syncthreads();

    // second scan: chunk counts
    unsigned int nch = (own + CHUNK - 1) / CHUNK;
    s[t] = nch;
    __syncthreads();
    for (int off = 1; off < 512; off <<= 1) {
        unsigned int v = (t >= off) ? s[t - off] : 0u;
        __syncthreads();
        s[t] += v;
        __syncthreads();
    }
    unsigned int cb = s[t] - nch;
    if (t == 511) d_nchunks = s[511];

    // emit this tile's chunk descriptors
    for (unsigned int j = 0; j * CHUNK < own; j++) {
        unsigned int len = min((unsigned int)CHUNK, own - j * CHUNK);
        d_chunkdesc[cb + j] = make_uint2(segstart + j * CHUNK,
                                         (unsigned int)t | (len << 16));
    }
}

// ---------------- K4: fill entry list, block-aggregated cursors ----------------
__global__ void k_fill() {
    __shared__ unsigned int scount[512];
    __shared__ unsigned int sbase[512];
    int t = threadIdx.x;
    scount[t] = 0u; scount[t + 256] = 0u;
    __syncthreads();

    int p = blockIdx.x * 256 + t;
    int w = (p < P_N) ? d_meta[p].w : -1;
    int txlo = 0, txhi = -1, tylo = 0, tyhi = -1, tzlo = 0, tzhi = -1;
    if (w >= 0) {
        txlo =  w        & 7; txhi = (w >> 3)  & 7;
        tylo = (w >> 6)  & 7; tyhi = (w >> 9)  & 7;
        tzlo = (w >> 12) & 7; tzhi = (w >> 15) & 7;
        for (int tz = tzlo; tz <= tzhi; tz++)
            for (int ty = tylo; ty <= tyhi; ty++)
                for (int tx = txlo; tx <= txhi; tx++)
                    atomicAdd(&scount[(tz << 6) | (ty << 3) | tx], 1u);
    }
    __syncthreads();
    for (int i = t; i < 512; i += 256) {
        unsigned int c = scount[i];
        sbase[i] = c ? atomicAdd(&d_cursor[i], c) : 0u;
    }
    __syncthreads();
    if (w >= 0) {
        for (int tz = tzlo; tz <= tzhi; tz++)
            for (int ty = tylo; ty <= tyhi; ty++)
                for (int tx = txlo; tx <= txhi; tx++) {
                    int tile = (tz << 6) | (ty << 3) | tx;
                    unsigned int posn = atomicAdd(&sbase[tile], 1u);
                    d_entries[posn] = ((unsigned int)tile << 17) | (unsigned int)p;
                }
    }
}

// ---------------- K5: splat — one tile/CTA, ballot-compacted branchless k-loop ----------------
__global__ void __launch_bounds__(128) k_splat() {
    __shared__ __align__(16) float sgx[2][NB][16];
    __shared__ __align__(16) float sgy[2][NB][16];
    __shared__ __align__(16) float sgz[2][NB][16];
    __shared__ unsigned int szmask[2][NB];

    if (blockIdx.x >= d_nchunks) return;
    uint2 desc = d_chunkdesc[blockIdx.x];
    unsigned int s   = desc.x;
    int tile         = (int)(desc.y & 0x1FFu);
    unsigned int len = desc.y >> 16;
    unsigned int e_end = s + len;

    int X0 =  (tile       & 7) << 4;
    int Y0 = ((tile >> 3) & 7) << 4;
    int Z0 = ((tile >> 6) & 7) << 4;

    int t    = threadIdx.x;
    int y    = t & 15;        // owned y row
    int zp   = t >> 4;        // owned z rows: 2*zp, 2*zp+1
    int wid  = t >> 5;        // warp id 0..3, covers z in [4w, 4w+4)
    int lane = t & 31;

    ull acc[2][8];            // [zz][x-pair]
    #pragma unroll
    for (int r = 0; r < 2; r++)
        #pragma unroll
        for (int i = 0; i < 8; i++) acc[r][i] = 0ull;

    // stage batch into buffer buf: tile-aligned, zero-padded gaussians
    auto stage = [&](int buf, unsigned int base, int n) {
        #pragma unroll
        for (int s2 = t; s2 < NB * 16; s2 += 128) {
            int b = s2 >> 4, l = s2 & 15;
            if (b < n) {
                unsigned int ent = d_entries[base + (unsigned int)b];
                int pid = (int)(ent & 0x1FFFFu);
                int4 mt = d_meta[pid];
                int ox = X0 - mt.x, oy = Y0 - mt.y, oz = Z0 - mt.z;
                int ix = l + ox, iy = l + oy, iz = l + oz;   // window slot per tile-local l
                sgx[buf][b][l] = ((unsigned)ix < (unsigned)WIN) ? d_gx[pid * 16 + ix] : 0.f;
                sgy[buf][b][l] = ((unsigned)iy < (unsigned)WIN) ? d_gy[pid * 16 + iy] : 0.f;
                sgz[buf][b][l] = ((unsigned)iz < (unsigned)WIN) ? d_gz[pid * 16 + iz] : 0.f;
                if (l == 0) {
                    int loz = max(0, -oz), hiz = min(15, (WIN - 1) - oz);
                    unsigned int c = 0u;
                    #pragma unroll
                    for (int w2 = 0; w2 < 4; w2++)
                        if (loz <= 4 * w2 + 3 && hiz >= 4 * w2) c |= 1u << w2;
                    szmask[buf][b] = c;
                }
            } else if (l == 0) {
                szmask[buf][b] = 0u;   // stale-mask guard for partial batches
            }
        }
    };

    int nbatch = (int)((len + NB - 1) / NB);
    stage(0, s, (int)min((unsigned int)NB, len));

    for (int i = 0; i < nbatch; i++) {
        __syncthreads();                 // buf[i&1] staged; other buf consumed
        int cur = i & 1;
        if (i + 1 < nbatch) {
            unsigned int bnext = s + (unsigned int)(i + 1) * NB;
            stage(cur ^ 1, bnext, (int)min((unsigned int)NB, e_end - bnext));
        }

        // warp-wide pass mask: bit k set iff entry k covers this warp's z range
        unsigned int em = szmask[cur][lane];
        unsigned int m  = __ballot_sync(0xFFFFFFFFu, (em >> wid) & 1u);

        while (m) {
            int k = __ffs(m) - 1;
            m &= m - 1;

            float  gyv = sgy[cur][k][y];
            float2 gzp = *(const float2*)&sgz[cur][k][2 * zp];
            float a0 = gyv * gzp.x;
            float a1 = gyv * gzp.y;
            ull c0 = pack2(a0, a0), c1 = pack2(a1, a1);

            ulonglong2 qa = *(const ulonglong2*)&sgx[cur][k][0];
            ulonglong2 qb = *(const ulonglong2*)&sgx[cur][k][4];
            ulonglong2 qc = *(const ulonglong2*)&sgx[cur][k][8];
            ulonglong2 qd = *(const ulonglong2*)&sgx[cur][k][12];
            acc[0][0] = fma2(c0, qa.x, acc[0][0]); acc[0][1] = fma2(c0, qa.y, acc[0][1]);
            acc[0][2] = fma2(c0, qb.x, acc[0][2]); acc[0][3] = fma2(c0, qb.y, acc[0][3]);
            acc[0][4] = fma2(c0, qc.x, acc[0][4]); acc[0][5] = fma2(c0, qc.y, acc[0][5]);
            acc[0][6] = fma2(c0, qd.x, acc[0][6]); acc[0][7] = fma2(c0, qd.y, acc[0][7]);
            acc[1][0] = fma2(c1, qa.x, acc[1][0]); acc[1][1] = fma2(c1, qa.y, acc[1][1]);
            acc[1][2] = fma2(c1, qb.x, acc[1][2]); acc[1][3] = fma2(c1, qb.y, acc[1][3]);
            acc[1][4] = fma2(c1, qc.x, acc[1][4]); acc[1][5] = fma2(c1, qc.y, acc[1][5]);
            acc[1][6] = fma2(c1, qd.x, acc[1][6]); acc[1][7] = fma2(c1, qd.y, acc[1][7]);
        }
    }

    // single flush at CTA end
    #pragma unroll
    for (int zz = 0; zz < 2; zz++) {
        int rb = ((Z0 + 2 * zp + zz) * 128 + (Y0 + y)) * 128 + X0;
        #pragma unroll
        for (int i2 = 0; i2 < 8; i2++)
            if (acc[zz][i2]) red2(&d_vol[rb + 2 * i2], acc[zz][i2]);
    }
}

// ---------------- K6: fused triple reduction (float inner, double tree) ----------------
__global__ void k_reduce(const float* __restrict__ grid) {
    __shared__ double sh0[256], sh1[256], sh2[256];
    int t = threadIdx.x;
    float s1 = 0.f, s2 = 0.f, s3 = 0.f;
    for (int i = blockIdx.x * 256 + t; i < NVOX; i += gridDim.x * 256) {
        float v = d_vol[i];
        float g = grid[i];
        s1 += v * g;
        s2 += v * v;
        s3 += g * g;
    }
    sh0[t] = (double)s1; sh1[t] = (double)s2; sh2[t] = (double)s3;
    __syncthreads();
    for (int off = 128; off > 0; off >>= 1) {
        if (t < off) {
            sh0[t] += sh0[t + off];
            sh1[t] += sh1[t + off];
            sh2[t] += sh2[t + off];
        }
        __syncthreads();
    }
    if (t == 0) {
        atomicAdd(&d_sums[0], sh0[0]);
        atomicAdd(&d_sums[1], sh1[0]);
        atomicAdd(&d_sums[2], sh2[0]);
    }
}

// ---------------- K7: scalar finish ----------------
__global__ void k_final(float* __restrict__ out) {
    out[0] = (float)(1.0 - d_sums[0] / sqrt(d_sums[1] * d_sums[2]));
}

extern "C" void kernel_launch(void* const* d_in, const int* in_sizes, int n_in,
                              void* d_out, int out_size) {
    const float* quat   = (const float*)d_in[0];
    const float* offset = (const float*)d_in[1];
    const float* pos    = (const float*)d_in[2];
    const float* amp    = (const float*)d_in[3];
    const float* var    = (const float*)d_in[4];
    const float* grid   = (const float*)d_in[5];
    float* out = (float*)d_out;

    k_zero<<<NVOX / 4 / 256, 256>>>();
    k_precompute<<<(P_N + 255) / 256, 256>>>(quat, offset, pos, amp, var);
    k_scan<<<1, 512>>>();
    k_fill<<<(P_N + 255) / 256, 256>>>();
    k_splat<<<MAXC, 128>>>();
    k_reduce<<<512, 256>>>(grid);
    k_final<<<1, 1>>>(out);
}

// round 10
// speedup vs baseline: 3.6595x; 1.1336x over previous
#include <cuda_runtime.h>
#include <math.h>

#define A_N   20480
#define G_N   5
#define P_N   (A_N * G_N)           // 102400 pairs
#define NVOX  (128 * 128 * 128)
#define WIN   12                    // gaussian window width (slots 0..11), min margin >4 voxels
#define MAXE  (P_N * 8)
#define CHUNK 512
#define NB    32                    // batch size == warp width (ballot compaction)
#define MAXC  (512 + MAXE / CHUNK)  // max chunk descriptors
#define PRE_BLOCKS ((P_N + 255) / 256)          // 400
#define ZERO_BLOCKS (NVOX / 4 / 256)            // 2048

typedef unsigned long long ull;

// ---------------- device scratch (zero-initialized at load; d_counts invariant: ----------------
// ---------------- zeroed at end of every run by k_final, so each run sees zeros) ----------------
__device__ float        d_gx[P_N * 16];
__device__ float        d_gy[P_N * 16];
__device__ float        d_gz[P_N * 16];     // prefactor folded in
__device__ int4         d_meta[P_N];        // ix0, iy0, iz0, packed tile spans (w=-1: none)
__device__ float        d_vol[NVOX];
__device__ unsigned int d_counts[512];
__device__ unsigned int d_segstart[512];
__device__ unsigned int d_cursor[512];
__device__ uint2        d_chunkdesc[MAXC];  // {entry start, tile | (len<<16)}
__device__ unsigned int d_nchunks;
__device__ unsigned int d_entries[MAXE];    // (tile << 17) | pair
__device__ unsigned int d_total;
__device__ double       d_sums[3];          // S1, S2, S3

// ---------------- f32x2 helpers ----------------
__device__ __forceinline__ ull pack2(float lo, float hi) {
    ull r; asm("mov.b64 %0, {%1, %2};" : "=l"(r) : "f"(lo), "f"(hi)); return r;
}
__device__ __forceinline__ void unpack2(ull v, float& lo, float& hi) {
    asm("mov.b64 {%0, %1}, %2;" : "=f"(lo), "=f"(hi) : "l"(v));
}
__device__ __forceinline__ ull fma2(ull a, ull b, ull c) {
    ull d; asm("fma.rn.f32x2 %0, %1, %2, %3;" : "=l"(d) : "l"(a), "l"(b), "l"(c)); return d;
}
__device__ __forceinline__ void red2(float* p, ull v) {
    float lo, hi; unpack2(v, lo, hi);
    asm volatile("red.global.add.v2.f32 [%0], {%1, %2};" :: "l"(p), "f"(lo), "f"(hi) : "memory");
}

// ---------------- K2: rotate + 1D gaussians + tile counting, fused d_vol zeroing ----------------
__global__ void k_precompute(const float* __restrict__ quat,
                             const float* __restrict__ offset,
                             const float* __restrict__ pos,
                             const float* __restrict__ amp,
                             const float* __restrict__ var) {
    int t = threadIdx.x;

    // tail blocks: zero the volume (runs concurrently; splat is 2 kernels later)
    if (blockIdx.x >= PRE_BLOCKS) {
        int i = (blockIdx.x - PRE_BLOCKS) * 256 + t;
        ((float4*)d_vol)[i] = make_float4(0.f, 0.f, 0.f, 0.f);
        return;
    }

    __shared__ unsigned int scount[512];
    scount[t] = 0u; scount[t + 256] = 0u;
    __syncthreads();

    int p = blockIdx.x * 256 + t;
    int w = -1;
    if (p < P_N) {
        float qw = quat[0], qx = quat[1], qy = quat[2], qz = quat[3];
        float qn = rsqrtf(qw * qw + qx * qx + qy * qy + qz * qz);
        qw *= qn; qx *= qn; qy *= qn; qz *= qn;
        float R00 = 1.f - 2.f * (qy * qy + qz * qz);
        float R01 = 2.f * (qx * qy - qw * qz);
        float R02 = 2.f * (qx * qz + qw * qy);
        float R10 = 2.f * (qx * qy + qw * qz);
        float R11 = 1.f - 2.f * (qx * qx + qz * qz);
        float R12 = 2.f * (qy * qz - qw * qx);
        float R20 = 2.f * (qx * qz - qw * qy);
        float R21 = 2.f * (qy * qz + qw * qx);
        float R22 = 1.f - 2.f * (qx * qx + qy * qy);

        int a = p / G_N;
        float px = pos[a * 3 + 0], py = pos[a * 3 + 1], pz = pos[a * 3 + 2];
        float cx = px * R00 + py * R10 + pz * R20 + offset[0];
        float cy = px * R01 + py * R11 + pz * R21 + offset[1];
        float cz = px * R02 + py * R12 + pz * R22 + offset[2];

        float v    = var[p];
        float am   = amp[p];
        float r    = rsqrtf(6.283185307179586f * v);
        float pref = am * r * r * r;            // amp * (2*pi*var)^(-3/2)
        float ninv = -0.5f / v;

        // even-aligned, centered window [ix0 .. ix0+11]; margins > 4 voxels
        int ix0 = ((int)floorf(cx) + 59) & ~1;
        int iy0 = ((int)floorf(cy) + 59) & ~1;
        int iz0 = ((int)floorf(cz) + 59) & ~1;

        float q2 = __expf(2.f * ninv);
        float g[16];
        {
            float d0 = (float)(ix0 - 64) - cx;
            float e  = __expf(ninv * d0 * d0);
            float rr = __expf(ninv * (2.f * d0 + 1.f));
            #pragma unroll
            for (int i = 0; i < 16; i++) { g[i] = (i < WIN) ? e : 0.f; e *= rr; rr *= q2; }
            float4* dst = (float4*)&d_gx[p * 16];
            dst[0] = make_float4(g[0], g[1], g[2], g[3]);
            dst[1] = make_float4(g[4], g[5], g[6], g[7]);
            dst[2] = make_float4(g[8], g[9], g[10], g[11]);
            dst[3] = make_float4(0.f, 0.f, 0.f, 0.f);
        }
        {
            float d0 = (float)(iy0 - 64) - cy;
            float e  = __expf(ninv * d0 * d0);
            float rr = __expf(ninv * (2.f * d0 + 1.f));
            #pragma unroll
            for (int i = 0; i < 16; i++) { g[i] = (i < WIN) ? e : 0.f; e *= rr; rr *= q2; }
            float4* dst = (float4*)&d_gy[p * 16];
            dst[0] = make_float4(g[0], g[1], g[2], g[3]);
            dst[1] = make_float4(g[4], g[5], g[6], g[7]);
            dst[2] = make_float4(g[8], g[9], g[10], g[11]);
            dst[3] = make_float4(0.f, 0.f, 0.f, 0.f);
        }
        {
            float d0 = (float)(iz0 - 64) - cz;
            float e  = pref * __expf(ninv * d0 * d0);
            float rr = __expf(ninv * (2.f * d0 + 1.f));
            #pragma unroll
            for (int i = 0; i < 16; i++) { g[i] = (i < WIN) ? e : 0.f; e *= rr; rr *= q2; }
            float4* dst = (float4*)&d_gz[p * 16];
            dst[0] = make_float4(g[0], g[1], g[2], g[3]);
            dst[1] = make_float4(g[4], g[5], g[6], g[7]);
            dst[2] = make_float4(g[8], g[9], g[10], g[11]);
            dst[3] = make_float4(0.f, 0.f, 0.f, 0.f);
        }

        int xlo = max(ix0, 0), xhi = min(ix0 + WIN - 1, 127);
        int ylo = max(iy0, 0), yhi = min(iy0 + WIN - 1, 127);
        int zlo = max(iz0, 0), zhi = min(iz0 + WIN - 1, 127);
        if (xlo <= xhi && ylo <= yhi && zlo <= zhi) {
            int txlo = xlo >> 4, txhi = xhi >> 4;
            int tylo = ylo >> 4, tyhi = yhi >> 4;
            int tzlo = zlo >> 4, tzhi = zhi >> 4;
            w = txlo | (txhi << 3) | (tylo << 6) | (tyhi << 9) | (tzlo << 12) | (tzhi << 15);
            for (int tz = tzlo; tz <= tzhi; tz++)
                for (int ty = tylo; ty <= tyhi; ty++)
                    for (int tx = txlo; tx <= txhi; tx++)
                        atomicAdd(&scount[(tz << 6) | (ty << 3) | tx], 1u);
        }
        d_meta[p] = make_int4(ix0, iy0, iz0, w);
    }
    __syncthreads();
    for (int i = t; i < 512; i += 256) {
        unsigned int c = scount[i];
        if (c) atomicAdd(&d_counts[i], c);   // d_counts pre-zeroed by previous run's k_final
    }
}

// ---------------- K3: scans + chunk descriptor emission + sums zero ----------------
__global__ void k_scan() {
    __shared__ unsigned int s[512];
    int t = threadIdx.x;
    unsigned int own = d_counts[t];
    s[t] = own;
    __syncthreads();
    for (int off = 1; off < 512; off <<= 1) {
        unsigned int v = (t >= off) ? s[t - off] : 0u;
        __syncthreads();
        s[t] += v;
        __syncthreads();
    }
    unsigned int segstart = s[t] - own;
    d_segstart[t] = segstart;
    d_cursor[t]   = segstart;
    if (t == 511) d_total = s[511];
    if (t < 3)    d_sums[t] = 0.0;
    __syncthreads();

    // second scan: chunk counts
    unsigned int nch = (own + CHUNK - 1) / CHUNK;
    s[t] = nch;
    __syncthreads();
    for (int off = 1; off < 512; off <<= 1) {
        unsigned int v = (t >= off) ? s[t - off] : 0u;
        __syncthreads();
        s[t] += v;
        __syncthreads();
    }
    unsigned int cb = s[t] - nch;
    if (t == 511) d_nchunks = s[511];

    for (unsigned int j = 0; j * CHUNK < own; j++) {
        unsigned int len = min((unsigned int)CHUNK, own - j * CHUNK);
        d_chunkdesc[cb + j] = make_uint2(segstart + j * CHUNK,
                                         (unsigned int)t | (len << 16));
    }
}

// ---------------- K4: fill entry list, block-aggregated cursors ----------------
__global__ void k_fill() {
    __shared__ unsigned int scount[512];
    __shared__ unsigned int sbase[512];
    int t = threadIdx.x;
    scount[t] = 0u; scount[t + 256] = 0u;
    __syncthreads();

    int p = blockIdx.x * 256 + t;
    int w = (p < P_N) ? d_meta[p].w : -1;
    int txlo = 0, txhi = -1, tylo = 0, tyhi = -1, tzlo = 0, tzhi = -1;
    if (w >= 0) {
        txlo =  w        & 7; txhi = (w >> 3)  & 7;
        tylo = (w >> 6)  & 7; tyhi = (w >> 9)  & 7;
        tzlo = (w >> 12) & 7; tzhi = (w >> 15) & 7;
        for (int tz = tzlo; tz <= tzhi; tz++)
            for (int ty = tylo; ty <= tyhi; ty++)
                for (int tx = txlo; tx <= txhi; tx++)
                    atomicAdd(&scount[(tz << 6) | (ty << 3) | tx], 1u);
    }
    __syncthreads();
    for (int i = t; i < 512; i += 256) {
        unsigned int c = scount[i];
        sbase[i] = c ? atomicAdd(&d_cursor[i], c) : 0u;
    }
    __syncthreads();
    if (w >= 0) {
        for (int tz = tzlo; tz <= tzhi; tz++)
            for (int ty = tylo; ty <= tyhi; ty++)
                for (int tx = txlo; tx <= txhi; tx++) {
                    int tile = (tz << 6) | (ty << 3) | tx;
                    unsigned int posn = atomicAdd(&sbase[tile], 1u);
                    d_entries[posn] = ((unsigned int)tile << 17) | (unsigned int)p;
                }
    }
}

// ---------------- K5: splat — one tile/CTA, ballot-compacted k-loop ----------------
__global__ void __launch_bounds__(128) k_splat() {
    __shared__ __align__(16) float sgx[2][NB][16];
    __shared__ __align__(16) float sgy[2][NB][16];
    __shared__ __align__(16) float sgz[2][NB][16];
    __shared__ unsigned int szmask[2][NB];

    if (blockIdx.x >= d_nchunks) return;
    uint2 desc = d_chunkdesc[blockIdx.x];
    unsigned int s   = desc.x;
    int tile         = (int)(desc.y & 0x1FFu);
    unsigned int len = desc.y >> 16;
    unsigned int e_end = s + len;

    int X0 =  (tile       & 7) << 4;
    int Y0 = ((tile >> 3) & 7) << 4;
    int Z0 = ((tile >> 6) & 7) << 4;

    int t    = threadIdx.x;
    int y    = t & 15;        // owned y row
    int zp   = t >> 4;        // owned z rows: 2*zp, 2*zp+1
    int wid  = t >> 5;        // warp id 0..3, covers z in [4w, 4w+4)
    int lane = t & 31;

    ull acc[2][8];            // [zz][x-pair]
    #pragma unroll
    for (int r = 0; r < 2; r++)
        #pragma unroll
        for (int i = 0; i < 8; i++) acc[r][i] = 0ull;

    auto stage = [&](int buf, unsigned int base, int n) {
        #pragma unroll
        for (int s2 = t; s2 < NB * 16; s2 += 128) {
            int b = s2 >> 4, l = s2 & 15;
            if (b < n) {
                unsigned int ent = d_entries[base + (unsigned int)b];
                int pid = (int)(ent & 0x1FFFFu);
                int4 mt = d_meta[pid];
                int ox = X0 - mt.x, oy = Y0 - mt.y, oz = Z0 - mt.z;
                int ix = l + ox, iy = l + oy, iz = l + oz;
                sgx[buf][b][l] = ((unsigned)ix < (unsigned)WIN) ? d_gx[pid * 16 + ix] : 0.f;
                sgy[buf][b][l] = ((unsigned)iy < (unsigned)WIN) ? d_gy[pid * 16 + iy] : 0.f;
                sgz[buf][b][l] = ((unsigned)iz < (unsigned)WIN) ? d_gz[pid * 16 + iz] : 0.f;
                if (l == 0) {
                    int loz = max(0, -oz), hiz = min(15, (WIN - 1) - oz);
                    unsigned int c = 0u;
                    #pragma unroll
                    for (int w2 = 0; w2 < 4; w2++)
                        if (loz <= 4 * w2 + 3 && hiz >= 4 * w2) c |= 1u << w2;
                    szmask[buf][b] = c;
                }
            } else if (l == 0) {
                szmask[buf][b] = 0u;
            }
        }
    };

    int nbatch = (int)((len + NB - 1) / NB);
    stage(0, s, (int)min((unsigned int)NB, len));

    for (int i = 0; i < nbatch; i++) {
        __syncthreads();
        int cur = i & 1;
        if (i + 1 < nbatch) {
            unsigned int bnext = s + (unsigned int)(i + 1) * NB;
            stage(cur ^ 1, bnext, (int)min((unsigned int)NB, e_end - bnext));
        }

        unsigned int em = szmask[cur][lane];
        unsigned int m  = __ballot_sync(0xFFFFFFFFu, (em >> wid) & 1u);

        while (m) {
            int k = __ffs(m) - 1;
            m &= m - 1;

            float  gyv = sgy[cur][k][y];
            float2 gzp = *(const float2*)&sgz[cur][k][2 * zp];
            float a0 = gyv * gzp.x;
            float a1 = gyv * gzp.y;
            ull c0 = pack2(a0, a0), c1 = pack2(a1, a1);

            ulonglong2 qa = *(const ulonglong2*)&sgx[cur][k][0];
            ulonglong2 qb = *(const ulonglong2*)&sgx[cur][k][4];
            ulonglong2 qc = *(const ulonglong2*)&sgx[cur][k][8];
            ulonglong2 qd = *(const ulonglong2*)&sgx[cur][k][12];
            acc[0][0] = fma2(c0, qa.x, acc[0][0]); acc[0][1] = fma2(c0, qa.y, acc[0][1]);
            acc[0][2] = fma2(c0, qb.x, acc[0][2]); acc[0][3] = fma2(c0, qb.y, acc[0][3]);
            acc[0][4] = fma2(c0, qc.x, acc[0][4]); acc[0][5] = fma2(c0, qc.y, acc[0][5]);
            acc[0][6] = fma2(c0, qd.x, acc[0][6]); acc[0][7] = fma2(c0, qd.y, acc[0][7]);
            acc[1][0] = fma2(c1, qa.x, acc[1][0]); acc[1][1] = fma2(c1, qa.y, acc[1][1]);
            acc[1][2] = fma2(c1, qb.x, acc[1][2]); acc[1][3] = fma2(c1, qb.y, acc[1][3]);
            acc[1][4] = fma2(c1, qc.x, acc[1][4]); acc[1][5] = fma2(c1, qc.y, acc[1][5]);
            acc[1][6] = fma2(c1, qd.x, acc[1][6]); acc[1][7] = fma2(c1, qd.y, acc[1][7]);
        }
    }

    #pragma unroll
    for (int zz = 0; zz < 2; zz++) {
        int rb = ((Z0 + 2 * zp + zz) * 128 + (Y0 + y)) * 128 + X0;
        #pragma unroll
        for (int i2 = 0; i2 < 8; i2++)
            if (acc[zz][i2]) red2(&d_vol[rb + 2 * i2], acc[zz][i2]);
    }
}

// ---------------- K6: fused triple reduction (float inner, double tree) ----------------
__global__ void k_reduce(const float* __restrict__ grid) {
    __shared__ double sh0[256], sh1[256], sh2[256];
    int t = threadIdx.x;
    float s1 = 0.f, s2 = 0.f, s3 = 0.f;
    for (int i = blockIdx.x * 256 + t; i < NVOX; i += gridDim.x * 256) {
        float v = d_vol[i];
        float g = grid[i];
        s1 += v * g;
        s2 += v * v;
        s3 += g * g;
    }
    sh0[t] = (double)s1; sh1[t] = (double)s2; sh2[t] = (double)s3;
    __syncthreads();
    for (int off = 128; off > 0; off >>= 1) {
        if (t < off) {
            sh0[t] += sh0[t + off];
            sh1[t] += sh1[t + off];
            sh2[t] += sh2[t + off];
        }
        __syncthreads();
    }
    if (t == 0) {
        atomicAdd(&d_sums[0], sh0[0]);
        atomicAdd(&d_sums[1], sh1[0]);
        atomicAdd(&d_sums[2], sh2[0]);
    }
}

// ---------------- K7: finish + reset d_counts invariant for the next run ----------------
__global__ void k_final(float* __restrict__ out) {
    int t = threadIdx.x;
    if (t == 0)
        out[0] = (float)(1.0 - d_sums[0] / sqrt(d_sums[1] * d_sums[2]));
    d_counts[t] = 0u;   // 512 threads: restore pre-run invariant
}

extern "C" void kernel_launch(void* const* d_in, const int* in_sizes, int n_in,
                              void* d_out, int out_size) {
    const float* quat   = (const float*)d_in[0];
    const float* offset = (const float*)d_in[1];
    const float* pos    = (const float*)d_in[2];
    const float* amp    = (const float*)d_in[3];
    const float* var    = (const float*)d_in[4];
    const float* grid   = (const float*)d_in[5];
    float* out = (float*)d_out;

    k_precompute<<<PRE_BLOCKS + ZERO_BLOCKS, 256>>>(quat, offset, pos, amp, var);
    k_scan<<<1, 512>>>();
    k_fill<<<(P_N + 255) / 256, 256>>>();
    k_splat<<<MAXC, 128>>>();
    k_reduce<<<512, 256>>>(grid);
    k_final<<<1, 512>>>(out);
}

// round 11
// speedup vs baseline: 4.2660x; 1.1657x over previous
#include <cuda_runtime.h>
#include <math.h>

#define A_N   20480
#define G_N   5
#define P_N   (A_N * G_N)           // 102400 pairs
#define NVOX  (128 * 128 * 128)
#define WIN   12                    // gaussian window width (slots 0..11), min margin >4 voxels
#define MAXE  (P_N * 8)
#define CHUNK 512
#define NB    32                    // batch size == warp width (ballot compaction)
#define MAXC  (512 + MAXE / CHUNK)  // max chunk descriptors
#define PRE_BLOCKS ((P_N + 255) / 256)          // 400
#define ZERO_BLOCKS (NVOX / 4 / 256)            // 2048

typedef unsigned long long ull;

// ---------------- device scratch (d_counts invariant: zeroed at end of every run) ----------------
__device__ float        d_gx[P_N * 16];
__device__ float        d_gy[P_N * 16];
__device__ float        d_gz[P_N * 16];     // prefactor folded in
__device__ int4         d_meta[P_N];        // ix0, iy0, iz0, packed tile spans (w=-1: none)
__device__ float        d_vol[NVOX];
__device__ unsigned int d_counts[512];
__device__ unsigned int d_segstart[512];
__device__ unsigned int d_cursor[512];
__device__ uint2        d_chunkdesc[MAXC];  // {entry start, tile | (len<<16)}
__device__ unsigned int d_nchunks;
__device__ unsigned int d_entries[MAXE];    // (tile << 17) | pair
__device__ unsigned int d_total;
__device__ double       d_sums[3];          // S1, S2, S3

// ---------------- f32x2 helpers ----------------
__device__ __forceinline__ ull pack2(float lo, float hi) {
    ull r; asm("mov.b64 %0, {%1, %2};" : "=l"(r) : "f"(lo), "f"(hi)); return r;
}
__device__ __forceinline__ void unpack2(ull v, float& lo, float& hi) {
    asm("mov.b64 {%0, %1}, %2;" : "=f"(lo), "=f"(hi) : "l"(v));
}
__device__ __forceinline__ ull fma2(ull a, ull b, ull c) {
    ull d; asm("fma.rn.f32x2 %0, %1, %2, %3;" : "=l"(d) : "l"(a), "l"(b), "l"(c)); return d;
}
__device__ __forceinline__ void red2(float* p, ull v) {
    float lo, hi; unpack2(v, lo, hi);
    asm volatile("red.global.add.v2.f32 [%0], {%1, %2};" :: "l"(p), "f"(lo), "f"(hi) : "memory");
}

// ---------------- K2: rotate + 1D gaussians + tile counting, fused d_vol zeroing ----------------
__global__ void k_precompute(const float* __restrict__ quat,
                             const float* __restrict__ offset,
                             const float* __restrict__ pos,
                             const float* __restrict__ amp,
                             const float* __restrict__ var) {
    int t = threadIdx.x;

    // tail blocks: zero the volume (splat is 2 kernels later)
    if (blockIdx.x >= PRE_BLOCKS) {
        int i = (blockIdx.x - PRE_BLOCKS) * 256 + t;
        ((float4*)d_vol)[i] = make_float4(0.f, 0.f, 0.f, 0.f);
        return;
    }

    __shared__ unsigned int scount[512];
    scount[t] = 0u; scount[t + 256] = 0u;
    __syncthreads();

    int p = blockIdx.x * 256 + t;
    int w = -1;
    if (p < P_N) {
        float qw = quat[0], qx = quat[1], qy = quat[2], qz = quat[3];
        float qn = rsqrtf(qw * qw + qx * qx + qy * qy + qz * qz);
        qw *= qn; qx *= qn; qy *= qn; qz *= qn;
        float R00 = 1.f - 2.f * (qy * qy + qz * qz);
        float R01 = 2.f * (qx * qy - qw * qz);
        float R02 = 2.f * (qx * qz + qw * qy);
        float R10 = 2.f * (qx * qy + qw * qz);
        float R11 = 1.f - 2.f * (qx * qx + qz * qz);
        float R12 = 2.f * (qy * qz - qw * qx);
        float R20 = 2.f * (qx * qz - qw * qy);
        float R21 = 2.f * (qy * qz + qw * qx);
        float R22 = 1.f - 2.f * (qx * qx + qy * qy);

        int a = p / G_N;
        float px = pos[a * 3 + 0], py = pos[a * 3 + 1], pz = pos[a * 3 + 2];
        float cx = px * R00 + py * R10 + pz * R20 + offset[0];
        float cy = px * R01 + py * R11 + pz * R21 + offset[1];
        float cz = px * R02 + py * R12 + pz * R22 + offset[2];

        float v    = var[p];
        float am   = amp[p];
        float r    = rsqrtf(6.283185307179586f * v);
        float pref = am * r * r * r;            // amp * (2*pi*var)^(-3/2)
        float ninv = -0.5f / v;

        // even-aligned, centered window [ix0 .. ix0+11]; margins > 4 voxels
        int ix0 = ((int)floorf(cx) + 59) & ~1;
        int iy0 = ((int)floorf(cy) + 59) & ~1;
        int iz0 = ((int)floorf(cz) + 59) & ~1;

        float q2 = __expf(2.f * ninv);
        float g[16];
        {
            float d0 = (float)(ix0 - 64) - cx;
            float e  = __expf(ninv * d0 * d0);
            float rr = __expf(ninv * (2.f * d0 + 1.f));
            #pragma unroll
            for (int i = 0; i < 16; i++) { g[i] = (i < WIN) ? e : 0.f; e *= rr; rr *= q2; }
            float4* dst = (float4*)&d_gx[p * 16];
            dst[0] = make_float4(g[0], g[1], g[2], g[3]);
            dst[1] = make_float4(g[4], g[5], g[6], g[7]);
            dst[2] = make_float4(g[8], g[9], g[10], g[11]);
            dst[3] = make_float4(0.f, 0.f, 0.f, 0.f);
        }
        {
            float d0 = (float)(iy0 - 64) - cy;
            float e  = __expf(ninv * d0 * d0);
            float rr = __expf(ninv * (2.f * d0 + 1.f));
            #pragma unroll
            for (int i = 0; i < 16; i++) { g[i] = (i < WIN) ? e : 0.f; e *= rr; rr *= q2; }
            float4* dst = (float4*)&d_gy[p * 16];
            dst[0] = make_float4(g[0], g[1], g[2], g[3]);
            dst[1] = make_float4(g[4], g[5], g[6], g[7]);
            dst[2] = make_float4(g[8], g[9], g[10], g[11]);
            dst[3] = make_float4(0.f, 0.f, 0.f, 0.f);
        }
        {
            float d0 = (float)(iz0 - 64) - cz;
            float e  = pref * __expf(ninv * d0 * d0);
            float rr = __expf(ninv * (2.f * d0 + 1.f));
            #pragma unroll
            for (int i = 0; i < 16; i++) { g[i] = (i < WIN) ? e : 0.f; e *= rr; rr *= q2; }
            float4* dst = (float4*)&d_gz[p * 16];
            dst[0] = make_float4(g[0], g[1], g[2], g[3]);
            dst[1] = make_float4(g[4], g[5], g[6], g[7]);
            dst[2] = make_float4(g[8], g[9], g[10], g[11]);
            dst[3] = make_float4(0.f, 0.f, 0.f, 0.f);
        }

        int xlo = max(ix0, 0), xhi = min(ix0 + WIN - 1, 127);
        int ylo = max(iy0, 0), yhi = min(iy0 + WIN - 1, 127);
        int zlo = max(iz0, 0), zhi = min(iz0 + WIN - 1, 127);
        if (xlo <= xhi && ylo <= yhi && zlo <= zhi) {
            int txlo = xlo >> 4, txhi = xhi >> 4;
            int tylo = ylo >> 4, tyhi = yhi >> 4;
            int tzlo = zlo >> 4, tzhi = zhi >> 4;
            w = txlo | (txhi << 3) | (tylo << 6) | (tyhi << 9) | (tzlo << 12) | (tzhi << 15);
            for (int tz = tzlo; tz <= tzhi; tz++)
                for (int ty = tylo; ty <= tyhi; ty++)
                    for (int tx = txlo; tx <= txhi; tx++)
                        atomicAdd(&scount[(tz << 6) | (ty << 3) | tx], 1u);
        }
        d_meta[p] = make_int4(ix0, iy0, iz0, w);
    }
    __syncthreads();
    for (int i = t; i < 512; i += 256) {
        unsigned int c = scount[i];
        if (c) atomicAdd(&d_counts[i], c);   // d_counts pre-zeroed by previous run's k_final
    }
}

// ---------------- K3: scans + chunk descriptor emission + sums zero ----------------
__global__ void k_scan() {
    __shared__ unsigned int s[512];
    int t = threadIdx.x;
    unsigned int own = d_counts[t];
    s[t] = own;
    __syncthreads();
    for (int off = 1; off < 512; off <<= 1) {
        unsigned int v = (t >= off) ? s[t - off] : 0u;
        __syncthreads();
        s[t] += v;
        __syncthreads();
    }
    unsigned int segstart = s[t] - own;
    d_segstart[t] = segstart;
    d_cursor[t]   = segstart;
    if (t == 511) d_total = s[511];
    if (t < 3)    d_sums[t] = 0.0;
    __syncthreads();

    unsigned int nch = (own + CHUNK - 1) / CHUNK;
    s[t] = nch;
    __syncthreads();
    for (int off = 1; off < 512; off <<= 1) {
        unsigned int v = (t >= off) ? s[t - off] : 0u;
        __syncthreads();
        s[t] += v;
        __syncthreads();
    }
    unsigned int cb = s[t] - nch;
    if (t == 511) d_nchunks = s[511];

    for (unsigned int j = 0; j * CHUNK < own; j++) {
        unsigned int len = min((unsigned int)CHUNK, own - j * CHUNK);
        d_chunkdesc[cb + j] = make_uint2(segstart + j * CHUNK,
                                         (unsigned int)t | (len << 16));
    }
}

// ---------------- K4: fill entry list, block-aggregated cursors ----------------
__global__ void k_fill() {
    __shared__ unsigned int scount[512];
    __shared__ unsigned int sbase[512];
    int t = threadIdx.x;
    scount[t] = 0u; scount[t + 256] = 0u;
    __syncthreads();

    int p = blockIdx.x * 256 + t;
    int w = (p < P_N) ? d_meta[p].w : -1;
    int txlo = 0, txhi = -1, tylo = 0, tyhi = -1, tzlo = 0, tzhi = -1;
    if (w >= 0) {
        txlo =  w        & 7; txhi = (w >> 3)  & 7;
        tylo = (w >> 6)  & 7; tyhi = (w >> 9)  & 7;
        tzlo = (w >> 12) & 7; tzhi = (w >> 15) & 7;
        for (int tz = tzlo; tz <= tzhi; tz++)
            for (int ty = tylo; ty <= tyhi; ty++)
                for (int tx = txlo; tx <= txhi; tx++)
                    atomicAdd(&scount[(tz << 6) | (ty << 3) | tx], 1u);
    }
    __syncthreads();
    for (int i = t; i < 512; i += 256) {
        unsigned int c = scount[i];
        sbase[i] = c ? atomicAdd(&d_cursor[i], c) : 0u;
    }
    __syncthreads();
    if (w >= 0) {
        for (int tz = tzlo; tz <= tzhi; tz++)
            for (int ty = tylo; ty <= tyhi; ty++)
                for (int tx = txlo; tx <= txhi; tx++) {
                    int tile = (tz << 6) | (ty << 3) | tx;
                    unsigned int posn = atomicAdd(&sbase[tile], 1u);
                    d_entries[posn] = ((unsigned int)tile << 17) | (unsigned int)p;
                }
    }
}

// ---------------- K5: splat — one tile/CTA, dual-entry ballot-compacted k-loop ----------------
__global__ void __launch_bounds__(128) k_splat() {
    __shared__ __align__(16) float sgx[2][NB][16];
    __shared__ __align__(16) float sgy[2][NB][16];
    __shared__ __align__(16) float sgz[2][NB][16];
    __shared__ unsigned int szmask[2][NB];

    if (blockIdx.x >= d_nchunks) return;
    uint2 desc = d_chunkdesc[blockIdx.x];
    unsigned int s   = desc.x;
    int tile         = (int)(desc.y & 0x1FFu);
    unsigned int len = desc.y >> 16;
    unsigned int e_end = s + len;

    int X0 =  (tile       & 7) << 4;
    int Y0 = ((tile >> 3) & 7) << 4;
    int Z0 = ((tile >> 6) & 7) << 4;

    int t    = threadIdx.x;
    int y    = t & 15;        // owned y row
    int zp   = t >> 4;        // owned z rows: 2*zp, 2*zp+1
    int wid  = t >> 5;        // warp id 0..3, covers z in [4w, 4w+4)
    int lane = t & 31;

    ull acc[2][8];            // [zz][x-pair]
    #pragma unroll
    for (int r = 0; r < 2; r++)
        #pragma unroll
        for (int i = 0; i < 8; i++) acc[r][i] = 0ull;

    // stage: float2 granularity (slots pair up: ox and 2*l2 both even)
    auto stage = [&](int buf, unsigned int base, int n) {
        #pragma unroll
        for (int s2 = t; s2 < NB * 8; s2 += 128) {
            int b = s2 >> 3, l2 = s2 & 7;
            if (b < n) {
                unsigned int ent = d_entries[base + (unsigned int)b];
                int pid = (int)(ent & 0x1FFFFu);
                int4 mt = d_meta[pid];
                int ox = X0 - mt.x, oy = Y0 - mt.y, oz = Z0 - mt.z;
                int ix = 2 * l2 + ox, iy = 2 * l2 + oy, iz = 2 * l2 + oz;
                float2 vx = make_float2(0.f, 0.f), vy = vx, vz = vx;
                if ((unsigned)ix < (unsigned)WIN) vx = *(const float2*)&d_gx[pid * 16 + ix];
                if ((unsigned)iy < (unsigned)WIN) vy = *(const float2*)&d_gy[pid * 16 + iy];
                if ((unsigned)iz < (unsigned)WIN) vz = *(const float2*)&d_gz[pid * 16 + iz];
                *(float2*)&sgx[buf][b][2 * l2] = vx;
                *(float2*)&sgy[buf][b][2 * l2] = vy;
                *(float2*)&sgz[buf][b][2 * l2] = vz;
                if (l2 == 0) {
                    int loz = max(0, -oz), hiz = min(15, (WIN - 1) - oz);
                    unsigned int c = 0u;
                    #pragma unroll
                    for (int w2 = 0; w2 < 4; w2++)
                        if (loz <= 4 * w2 + 3 && hiz >= 4 * w2) c |= 1u << w2;
                    szmask[buf][b] = c;
                }
            } else if (l2 == 0) {
                szmask[buf][b] = 0u;
            }
        }
    };

    int nbatch = (int)((len + NB - 1) / NB);
    stage(0, s, (int)min((unsigned int)NB, len));

    for (int i = 0; i < nbatch; i++) {
        __syncthreads();
        int cur = i & 1;
        if (i + 1 < nbatch) {
            unsigned int bnext = s + (unsigned int)(i + 1) * NB;
            stage(cur ^ 1, bnext, (int)min((unsigned int)NB, e_end - bnext));
        }

        unsigned int em = szmask[cur][lane];
        unsigned int m  = __ballot_sync(0xFFFFFFFFu, (em >> wid) & 1u);

        while (m) {
            int k1 = __ffs(m) - 1;
            m &= m - 1;
            float sec = m ? 1.f : 0.f;               // second entry valid?
            int k2 = m ? (__ffs(m) - 1) : k1;        // duplicate k1, zeroed by sec
            m &= m - 1;                              // safe at m==0

            float  gy1 = sgy[cur][k1][y];
            float2 gza = *(const float2*)&sgz[cur][k1][2 * zp];
            float  gy2 = sgy[cur][k2][y] * sec;
            float2 gzb = *(const float2*)&sgz[cur][k2][2 * zp];
            float a0 = gy1 * gza.x, a1 = gy1 * gza.y;
            float b0 = gy2 * gzb.x, b1 = gy2 * gzb.y;
            ull ca0 = pack2(a0, a0), ca1 = pack2(a1, a1);
            ull cb0 = pack2(b0, b0), cb1 = pack2(b1, b1);

            ulonglong2 pa = *(const ulonglong2*)&sgx[cur][k1][0];
            ulonglong2 pb = *(const ulonglong2*)&sgx[cur][k1][4];
            ulonglong2 pc = *(const ulonglong2*)&sgx[cur][k1][8];
            ulonglong2 pd = *(const ulonglong2*)&sgx[cur][k1][12];
            ulonglong2 qa = *(const ulonglong2*)&sgx[cur][k2][0];
            ulonglong2 qb = *(const ulonglong2*)&sgx[cur][k2][4];
            ulonglong2 qc = *(const ulonglong2*)&sgx[cur][k2][8];
            ulonglong2 qd = *(const ulonglong2*)&sgx[cur][k2][12];

            acc[0][0] = fma2(ca0, pa.x, acc[0][0]); acc[0][1] = fma2(ca0, pa.y, acc[0][1]);
            acc[0][2] = fma2(ca0, pb.x, acc[0][2]); acc[0][3] = fma2(ca0, pb.y, acc[0][3]);
            acc[0][4] = fma2(ca0, pc.x, acc[0][4]); acc[0][5] = fma2(ca0, pc.y, acc[0][5]);
            acc[0][6] = fma2(ca0, pd.x, acc[0][6]); acc[0][7] = fma2(ca0, pd.y, acc[0][7]);
            acc[1][0] = fma2(ca1, pa.x, acc[1][0]); acc[1][1] = fma2(ca1, pa.y, acc[1][1]);
            acc[1][2] = fma2(ca1, pb.x, acc[1][2]); acc[1][3] = fma2(ca1, pb.y, acc[1][3]);
            acc[1][4] = fma2(ca1, pc.x, acc[1][4]); acc[1][5] = fma2(ca1, pc.y, acc[1][5]);
            acc[1][6] = fma2(ca1, pd.x, acc[1][6]); acc[1][7] = fma2(ca1, pd.y, acc[1][7]);

            acc[0][0] = fma2(cb0, qa.x, acc[0][0]); acc[0][1] = fma2(cb0, qa.y, acc[0][1]);
            acc[0][2] = fma2(cb0, qb.x, acc[0][2]); acc[0][3] = fma2(cb0, qb.y, acc[0][3]);
            acc[0][4] = fma2(cb0, qc.x, acc[0][4]); acc[0][5] = fma2(cb0, qc.y, acc[0][5]);
            acc[0][6] = fma2(cb0, qd.x, acc[0][6]); acc[0][7] = fma2(cb0, qd.y, acc[0][7]);
            acc[1][0] = fma2(cb1, qa.x, acc[1][0]); acc[1][1] = fma2(cb1, qa.y, acc[1][1]);
            acc[1][2] = fma2(cb1, qb.x, acc[1][2]); acc[1][3] = fma2(cb1, qb.y, acc[1][3]);
            acc[1][4] = fma2(cb1, qc.x, acc[1][4]); acc[1][5] = fma2(cb1, qc.y, acc[1][5]);
            acc[1][6] = fma2(cb1, qd.x, acc[1][6]); acc[1][7] = fma2(cb1, qd.y, acc[1][7]);
        }
    }

    #pragma unroll
    for (int zz = 0; zz < 2; zz++) {
        int rb = ((Z0 + 2 * zp + zz) * 128 + (Y0 + y)) * 128 + X0;
        #pragma unroll
        for (int i2 = 0; i2 < 8; i2++)
            if (acc[zz][i2]) red2(&d_vol[rb + 2 * i2], acc[zz][i2]);
    }
}

// ---------------- K6: fused triple reduction (float inner, double tree) ----------------
__global__ void k_reduce(const float* __restrict__ grid) {
    __shared__ double sh0[256], sh1[256], sh2[256];
    int t = threadIdx.x;
    float s1 = 0.f, s2 = 0.f, s3 = 0.f;
    for (int i = blockIdx.x * 256 + t; i < NVOX; i += gridDim.x * 256) {
        float v = d_vol[i];
        float g = grid[i];
        s1 += v * g;
        s2 += v * v;
        s3 += g * g;
    }
    sh0[t] = (double)s1; sh1[t] = (double)s2; sh2[t] = (double)s3;
    __syncthreads();
    for (int off = 128; off > 0; off >>= 1) {
        if (t < off) {
            sh0[t] += sh0[t + off];
            sh1[t] += sh1[t + off];
            sh2[t] += sh2[t + off];
        }
        __syncthreads();
    }
    if (t == 0) {
        atomicAdd(&d_sums[0], sh0[0]);
        atomicAdd(&d_sums[1], sh1[0]);
        atomicAdd(&d_sums[2], sh2[0]);
    }
}

// ---------------- K7: finish + reset d_counts invariant for the next run ----------------
__global__ void k_final(float* __restrict__ out) {
    int t = threadIdx.x;
    if (t == 0)
        out[0] = (float)(1.0 - d_sums[0] / sqrt(d_sums[1] * d_sums[2]));
    d_counts[t] = 0u;   // 512 threads: restore pre-run invariant
}

extern "C" void kernel_launch(void* const* d_in, const int* in_sizes, int n_in,
                              void* d_out, int out_size) {
    const float* quat   = (const float*)d_in[0];
    const float* offset = (const float*)d_in[1];
    const float* pos    = (const float*)d_in[2];
    const float* amp    = (const float*)d_in[3];
    const float* var    = (const float*)d_in[4];
    const float* grid   = (const float*)d_in[5];
    float* out = (float*)d_out;

    k_precompute<<<PRE_BLOCKS + ZERO_BLOCKS, 256>>>(quat, offset, pos, amp, var);
    k_scan<<<1, 512>>>();
    k_fill<<<(P_N + 255) / 256, 256>>>();
    k_splat<<<MAXC, 128>>>();
    k_reduce<<<512, 256>>>(grid);
    k_final<<<1, 512>>>(out);
}

// round 12
// speedup vs baseline: 4.7487x; 1.1132x over previous
#include <cuda_runtime.h>
#include <math.h>

#define A_N   20480
#define G_N   5
#define P_N   (A_N * G_N)           // 102400 pairs
#define NVOX  (128 * 128 * 128)
#define WIN   12                    // gaussian window width (slots 0..11), min margin >4 voxels
#define MAXE  (P_N * 8)
#define CHUNK 256
#define NB    32                    // batch size == warp width (ballot compaction)
#define MAXC  (512 + MAXE / CHUNK)  // max chunk descriptors (3712)
#define PRE_BLOCKS ((P_N + 255) / 256)          // 400
#define ZERO_BLOCKS (NVOX / 4 / 256)            // 2048
#define SPLAT_GRID (9 * 148)                    // persistent: 9 CTAs/SM at 56 regs

typedef unsigned long long ull;

// ---------------- device scratch (d_counts invariant: zeroed at end of every run) ----------------
__device__ float        d_gx[P_N * 16];
__device__ float        d_gy[P_N * 16];
__device__ float        d_gz[P_N * 16];     // prefactor folded in
__device__ int4         d_meta[P_N];        // ix0, iy0, iz0, packed tile spans (w=-1: none)
__device__ float        d_vol[NVOX];
__device__ unsigned int d_counts[512];
__device__ unsigned int d_segstart[512];
__device__ unsigned int d_cursor[512];
__device__ uint2        d_chunkdesc[MAXC];  // {entry start, tile | (len<<16)}
__device__ unsigned int d_nchunks;
__device__ unsigned int d_entries[MAXE];    // (tile << 17) | pair
__device__ unsigned int d_total;
__device__ double       d_sums[3];          // S1, S2, S3

// ---------------- f32x2 helpers ----------------
__device__ __forceinline__ ull pack2(float lo, float hi) {
    ull r; asm("mov.b64 %0, {%1, %2};" : "=l"(r) : "f"(lo), "f"(hi)); return r;
}
__device__ __forceinline__ void unpack2(ull v, float& lo, float& hi) {
    asm("mov.b64 {%0, %1}, %2;" : "=f"(lo), "=f"(hi) : "l"(v));
}
__device__ __forceinline__ ull fma2(ull a, ull b, ull c) {
    ull d; asm("fma.rn.f32x2 %0, %1, %2, %3;" : "=l"(d) : "l"(a), "l"(b), "l"(c)); return d;
}
__device__ __forceinline__ void red2(float* p, ull v) {
    float lo, hi; unpack2(v, lo, hi);
    asm volatile("red.global.add.v2.f32 [%0], {%1, %2};" :: "l"(p), "f"(lo), "f"(hi) : "memory");
}

// ---------------- K2: rotate + 1D gaussians + tile counting, fused d_vol zeroing ----------------
__global__ void k_precompute(const float* __restrict__ quat,
                             const float* __restrict__ offset,
                             const float* __restrict__ pos,
                             const float* __restrict__ amp,
                             const float* __restrict__ var) {
    int t = threadIdx.x;

    if (blockIdx.x >= PRE_BLOCKS) {
        int i = (blockIdx.x - PRE_BLOCKS) * 256 + t;
        ((float4*)d_vol)[i] = make_float4(0.f, 0.f, 0.f, 0.f);
        return;
    }

    __shared__ unsigned int scount[512];
    scount[t] = 0u; scount[t + 256] = 0u;
    __syncthreads();

    int p = blockIdx.x * 256 + t;
    int w = -1;
    if (p < P_N) {
        float qw = quat[0], qx = quat[1], qy = quat[2], qz = quat[3];
        float qn = rsqrtf(qw * qw + qx * qx + qy * qy + qz * qz);
        qw *= qn; qx *= qn; qy *= qn; qz *= qn;
        float R00 = 1.f - 2.f * (qy * qy + qz * qz);
        float R01 = 2.f * (qx * qy - qw * qz);
        float R02 = 2.f * (qx * qz + qw * qy);
        float R10 = 2.f * (qx * qy + qw * qz);
        float R11 = 1.f - 2.f * (qx * qx + qz * qz);
        float R12 = 2.f * (qy * qz - qw * qx);
        float R20 = 2.f * (qx * qz - qw * qy);
        float R21 = 2.f * (qy * qz + qw * qx);
        float R22 = 1.f - 2.f * (qx * qx + qy * qy);

        int a = p / G_N;
        float px = pos[a * 3 + 0], py = pos[a * 3 + 1], pz = pos[a * 3 + 2];
        float cx = px * R00 + py * R10 + pz * R20 + offset[0];
        float cy = px * R01 + py * R11 + pz * R21 + offset[1];
        float cz = px * R02 + py * R12 + pz * R22 + offset[2];

        float v    = var[p];
        float am   = amp[p];
        float r    = rsqrtf(6.283185307179586f * v);
        float pref = am * r * r * r;            // amp * (2*pi*var)^(-3/2)
        float ninv = -0.5f / v;

        int ix0 = ((int)floorf(cx) + 59) & ~1;
        int iy0 = ((int)floorf(cy) + 59) & ~1;
        int iz0 = ((int)floorf(cz) + 59) & ~1;

        float q2 = __expf(2.f * ninv);
        float g[16];
        {
            float d0 = (float)(ix0 - 64) - cx;
            float e  = __expf(ninv * d0 * d0);
            float rr = __expf(ninv * (2.f * d0 + 1.f));
            #pragma unroll
            for (int i = 0; i < 16; i++) { g[i] = (i < WIN) ? e : 0.f; e *= rr; rr *= q2; }
            float4* dst = (float4*)&d_gx[p * 16];
            dst[0] = make_float4(g[0], g[1], g[2], g[3]);
            dst[1] = make_float4(g[4], g[5], g[6], g[7]);
            dst[2] = make_float4(g[8], g[9], g[10], g[11]);
            dst[3] = make_float4(0.f, 0.f, 0.f, 0.f);
        }
        {
            float d0 = (float)(iy0 - 64) - cy;
            float e  = __expf(ninv * d0 * d0);
            float rr = __expf(ninv * (2.f * d0 + 1.f));
            #pragma unroll
            for (int i = 0; i < 16; i++) { g[i] = (i < WIN) ? e : 0.f; e *= rr; rr *= q2; }
            float4* dst = (float4*)&d_gy[p * 16];
            dst[0] = make_float4(g[0], g[1], g[2], g[3]);
            dst[1] = make_float4(g[4], g[5], g[6], g[7]);
            dst[2] = make_float4(g[8], g[9], g[10], g[11]);
            dst[3] = make_float4(0.f, 0.f, 0.f, 0.f);
        }
        {
            float d0 = (float)(iz0 - 64) - cz;
            float e  = pref * __expf(ninv * d0 * d0);
            float rr = __expf(ninv * (2.f * d0 + 1.f));
            #pragma unroll
            for (int i = 0; i < 16; i++) { g[i] = (i < WIN) ? e : 0.f; e *= rr; rr *= q2; }
            float4* dst = (float4*)&d_gz[p * 16];
            dst[0] = make_float4(g[0], g[1], g[2], g[3]);
            dst[1] = make_float4(g[4], g[5], g[6], g[7]);
            dst[2] = make_float4(g[8], g[9], g[10], g[11]);
            dst[3] = make_float4(0.f, 0.f, 0.f, 0.f);
        }

        int xlo = max(ix0, 0), xhi = min(ix0 + WIN - 1, 127);
        int ylo = max(iy0, 0), yhi = min(iy0 + WIN - 1, 127);
        int zlo = max(iz0, 0), zhi = min(iz0 + WIN - 1, 127);
        if (xlo <= xhi && ylo <= yhi && zlo <= zhi) {
            int txlo = xlo >> 4, txhi = xhi >> 4;
            int tylo = ylo >> 4, tyhi = yhi >> 4;
            int tzlo = zlo >> 4, tzhi = zhi >> 4;
            w = txlo | (txhi << 3) | (tylo << 6) | (tyhi << 9) | (tzlo << 12) | (tzhi << 15);
            for (int tz = tzlo; tz <= tzhi; tz++)
                for (int ty = tylo; ty <= tyhi; ty++)
                    for (int tx = txlo; tx <= txhi; tx++)
                        atomicAdd(&scount[(tz << 6) | (ty << 3) | tx], 1u);
        }
        d_meta[p] = make_int4(ix0, iy0, iz0, w);
    }
    __syncthreads();
    for (int i = t; i < 512; i += 256) {
        unsigned int c = scount[i];
        if (c) atomicAdd(&d_counts[i], c);   // d_counts pre-zeroed by previous run's k_final
    }
}

// ---------------- K3: scans + chunk descriptor emission + sums zero ----------------
__global__ void k_scan() {
    __shared__ unsigned int s[512];
    int t = threadIdx.x;
    unsigned int own = d_counts[t];
    s[t] = own;
    __syncthreads();
    for (int off = 1; off < 512; off <<= 1) {
        unsigned int v = (t >= off) ? s[t - off] : 0u;
        __syncthreads();
        s[t] += v;
        __syncthreads();
    }
    unsigned int segstart = s[t] - own;
    d_segstart[t] = segstart;
    d_cursor[t]   = segstart;
    if (t == 511) d_total = s[511];
    if (t < 3)    d_sums[t] = 0.0;
    __syncthreads();

    unsigned int nch = (own + CHUNK - 1) / CHUNK;
    s[t] = nch;
    __syncthreads();
    for (int off = 1; off < 512; off <<= 1) {
        unsigned int v = (t >= off) ? s[t - off] : 0u;
        __syncthreads();
        s[t] += v;
        __syncthreads();
    }
    unsigned int cb = s[t] - nch;
    if (t == 511) d_nchunks = s[511];

    for (unsigned int j = 0; j * CHUNK < own; j++) {
        unsigned int len = min((unsigned int)CHUNK, own - j * CHUNK);
        d_chunkdesc[cb + j] = make_uint2(segstart + j * CHUNK,
                                         (unsigned int)t | (len << 16));
    }
}

// ---------------- K4: fill entry list, block-aggregated cursors ----------------
__global__ void k_fill() {
    __shared__ unsigned int scount[512];
    __shared__ unsigned int sbase[512];
    int t = threadIdx.x;
    scount[t] = 0u; scount[t + 256] = 0u;
    __syncthreads();

    int p = blockIdx.x * 256 + t;
    int w = (p < P_N) ? d_meta[p].w : -1;
    int txlo = 0, txhi = -1, tylo = 0, tyhi = -1, tzlo = 0, tzhi = -1;
    if (w >= 0) {
        txlo =  w        & 7; txhi = (w >> 3)  & 7;
        tylo = (w >> 6)  & 7; tyhi = (w >> 9)  & 7;
        tzlo = (w >> 12) & 7; tzhi = (w >> 15) & 7;
        for (int tz = tzlo; tz <= tzhi; tz++)
            for (int ty = tylo; ty <= tyhi; ty++)
                for (int tx = txlo; tx <= txhi; tx++)
                    atomicAdd(&scount[(tz << 6) | (ty << 3) | tx], 1u);
    }
    __syncthreads();
    for (int i = t; i < 512; i += 256) {
        unsigned int c = scount[i];
        sbase[i] = c ? atomicAdd(&d_cursor[i], c) : 0u;
    }
    __syncthreads();
    if (w >= 0) {
        for (int tz = tzlo; tz <= tzhi; tz++)
            for (int ty = tylo; ty <= tyhi; ty++)
                for (int tx = txlo; tx <= txhi; tx++) {
                    int tile = (tz << 6) | (ty << 3) | tx;
                    unsigned int posn = atomicAdd(&sbase[tile], 1u);
                    d_entries[posn] = ((unsigned int)tile << 17) | (unsigned int)p;
                }
    }
}

// ---------------- K5: splat — persistent grid-stride over chunks, dual-entry k-loop ----------------
__global__ void __launch_bounds__(128) k_splat() {
    __shared__ __align__(16) float sgx[2][NB][16];
    __shared__ __align__(16) float sgy[2][NB][16];
    __shared__ __align__(16) float sgz[2][NB][16];
    __shared__ unsigned int szmask[2][NB];

    int t    = threadIdx.x;
    int y    = t & 15;        // owned y row
    int zp   = t >> 4;        // owned z rows: 2*zp, 2*zp+1
    int wid  = t >> 5;        // warp id 0..3, covers z in [4w, 4w+4)
    int lane = t & 31;

    unsigned int nchunks = d_nchunks;

    for (unsigned int cidx = blockIdx.x; cidx < nchunks; cidx += gridDim.x) {
        uint2 desc = d_chunkdesc[cidx];
        unsigned int s   = desc.x;
        int tile         = (int)(desc.y & 0x1FFu);
        unsigned int len = desc.y >> 16;
        unsigned int e_end = s + len;

        int X0 =  (tile       & 7) << 4;
        int Y0 = ((tile >> 3) & 7) << 4;
        int Z0 = ((tile >> 6) & 7) << 4;

        ull acc[2][8];        // [zz][x-pair]
        #pragma unroll
        for (int r = 0; r < 2; r++)
            #pragma unroll
            for (int i = 0; i < 8; i++) acc[r][i] = 0ull;

        // stage: float2 granularity (slots pair up: offsets and 2*l2 both even)
        auto stage = [&](int buf, unsigned int base, int n) {
            #pragma unroll
            for (int s2 = t; s2 < NB * 8; s2 += 128) {
                int b = s2 >> 3, l2 = s2 & 7;
                if (b < n) {
                    unsigned int ent = d_entries[base + (unsigned int)b];
                    int pid = (int)(ent & 0x1FFFFu);
                    int4 mt = d_meta[pid];
                    int ox = X0 - mt.x, oy = Y0 - mt.y, oz = Z0 - mt.z;
                    int ix = 2 * l2 + ox, iy = 2 * l2 + oy, iz = 2 * l2 + oz;
                    float2 vx = make_float2(0.f, 0.f), vy = vx, vz = vx;
                    if ((unsigned)ix < (unsigned)WIN) vx = *(const float2*)&d_gx[pid * 16 + ix];
                    if ((unsigned)iy < (unsigned)WIN) vy = *(const float2*)&d_gy[pid * 16 + iy];
                    if ((unsigned)iz < (unsigned)WIN) vz = *(const float2*)&d_gz[pid * 16 + iz];
                    *(float2*)&sgx[buf][b][2 * l2] = vx;
                    *(float2*)&sgy[buf][b][2 * l2] = vy;
                    *(float2*)&sgz[buf][b][2 * l2] = vz;
                    if (l2 == 0) {
                        int loz = max(0, -oz), hiz = min(15, (WIN - 1) - oz);
                        unsigned int c = 0u;
                        #pragma unroll
                        for (int w2 = 0; w2 < 4; w2++)
                            if (loz <= 4 * w2 + 3 && hiz >= 4 * w2) c |= 1u << w2;
                        szmask[buf][b] = c;
                    }
                } else if (l2 == 0) {
                    szmask[buf][b] = 0u;
                }
            }
        };

        int nbatch = (int)((len + NB - 1) / NB);
        __syncthreads();   // previous chunk's buffers fully consumed before restaging
        stage(0, s, (int)min((unsigned int)NB, len));

        for (int i = 0; i < nbatch; i++) {
            __syncthreads();
            int cur = i & 1;
            if (i + 1 < nbatch) {
                unsigned int bnext = s + (unsigned int)(i + 1) * NB;
                stage(cur ^ 1, bnext, (int)min((unsigned int)NB, e_end - bnext));
            }

            unsigned int em = szmask[cur][lane];
            unsigned int m  = __ballot_sync(0xFFFFFFFFu, (em >> wid) & 1u);

            while (m) {
                int k1 = __ffs(m) - 1;
                m &= m - 1;
                float sec = m ? 1.f : 0.f;           // second entry valid?
                int k2 = m ? (__ffs(m) - 1) : k1;    // duplicate k1, zeroed by sec
                m &= m - 1;                          // safe at m==0

                float  gy1 = sgy[cur][k1][y];
                float2 gza = *(const float2*)&sgz[cur][k1][2 * zp];
                float  gy2 = sgy[cur][k2][y] * sec;
                float2 gzb = *(const float2*)&sgz[cur][k2][2 * zp];
                float a0 = gy1 * gza.x, a1 = gy1 * gza.y;
                float b0 = gy2 * gzb.x, b1 = gy2 * gzb.y;
                ull ca0 = pack2(a0, a0), ca1 = pack2(a1, a1);
                ull cb0 = pack2(b0, b0), cb1 = pack2(b1, b1);

                ulonglong2 pa = *(const ulonglong2*)&sgx[cur][k1][0];
                ulonglong2 pb = *(const ulonglong2*)&sgx[cur][k1][4];
                ulonglong2 pc = *(const ulonglong2*)&sgx[cur][k1][8];
                ulonglong2 pd = *(const ulonglong2*)&sgx[cur][k1][12];
                ulonglong2 qa = *(const ulonglong2*)&sgx[cur][k2][0];
                ulonglong2 qb = *(const ulonglong2*)&sgx[cur][k2][4];
                ulonglong2 qc = *(const ulonglong2*)&sgx[cur][k2][8];
                ulonglong2 qd = *(const ulonglong2*)&sgx[cur][k2][12];

                acc[0][0] = fma2(ca0, pa.x, acc[0][0]); acc[0][1] = fma2(ca0, pa.y, acc[0][1]);
                acc[0][2] = fma2(ca0, pb.x, acc[0][2]); acc[0][3] = fma2(ca0, pb.y, acc[0][3]);
                acc[0][4] = fma2(ca0, pc.x, acc[0][4]); acc[0][5] = fma2(ca0, pc.y, acc[0][5]);
                acc[0][6] = fma2(ca0, pd.x, acc[0][6]); acc[0][7] = fma2(ca0, pd.y, acc[0][7]);
                acc[1][0] = fma2(ca1, pa.x, acc[1][0]); acc[1][1] = fma2(ca1, pa.y, acc[1][1]);
                acc[1][2] = fma2(ca1, pb.x, acc[1][2]); acc[1][3] = fma2(ca1, pb.y, acc[1][3]);
                acc[1][4] = fma2(ca1, pc.x, acc[1][4]); acc[1][5] = fma2(ca1, pc.y, acc[1][5]);
                acc[1][6] = fma2(ca1, pd.x, acc[1][6]); acc[1][7] = fma2(ca1, pd.y, acc[1][7]);

                acc[0][0] = fma2(cb0, qa.x, acc[0][0]); acc[0][1] = fma2(cb0, qa.y, acc[0][1]);
                acc[0][2] = fma2(cb0, qb.x, acc[0][2]); acc[0][3] = fma2(cb0, qb.y, acc[0][3]);
                acc[0][4] = fma2(cb0, qc.x, acc[0][4]); acc[0][5] = fma2(cb0, qc.y, acc[0][5]);
                acc[0][6] = fma2(cb0, qd.x, acc[0][6]); acc[0][7] = fma2(cb0, qd.y, acc[0][7]);
                acc[1][0] = fma2(cb1, qa.x, acc[1][0]); acc[1][1] = fma2(cb1, qa.y, acc[1][1]);
                acc[1][2] = fma2(cb1, qb.x, acc[1][2]); acc[1][3] = fma2(cb1, qb.y, acc[1][3]);
                acc[1][4] = fma2(cb1, qc.x, acc[1][4]); acc[1][5] = fma2(cb1, qc.y, acc[1][5]);
                acc[1][6] = fma2(cb1, qd.x, acc[1][6]); acc[1][7] = fma2(cb1, qd.y, acc[1][7]);
            }
        }

        #pragma unroll
        for (int zz = 0; zz < 2; zz++) {
            int rb = ((Z0 + 2 * zp + zz) * 128 + (Y0 + y)) * 128 + X0;
            #pragma unroll
            for (int i2 = 0; i2 < 8; i2++)
                if (acc[zz][i2]) red2(&d_vol[rb + 2 * i2], acc[zz][i2]);
        }
    }
}

// ---------------- K6: fused triple reduction (float inner, double tree) ----------------
__global__ void k_reduce(const float* __restrict__ grid) {
    __shared__ double sh0[256], sh1[256], sh2[256];
    int t = threadIdx.x;
    float s1 = 0.f, s2 = 0.f, s3 = 0.f;
    for (int i = blockIdx.x * 256 + t; i < NVOX; i += gridDim.x * 256) {
        float v = d_vol[i];
        float g = grid[i];
        s1 += v * g;
        s2 += v * v;
        s3 += g * g;
    }
    sh0[t] = (double)s1; sh1[t] = (double)s2; sh2[t] = (double)s3;
    __syncthreads();
    for (int off = 128; off > 0; off >>= 1) {
        if (t < off) {
            sh0[t] += sh0[t + off];
            sh1[t] += sh1[t + off];
            sh2[t] += sh2[t + off];
        }
        __syncthreads();
    }
    if (t == 0) {
        atomicAdd(&d_sums[0], sh0[0]);
        atomicAdd(&d_sums[1], sh1[0]);
        atomicAdd(&d_sums[2], sh2[0]);
    }
}

// ---------------- K7: finish + reset d_counts invariant for the next run ----------------
__global__ void k_final(float* __restrict__ out) {
    int t = threadIdx.x;
    if (t == 0)
        out[0] = (float)(1.0 - d_sums[0] / sqrt(d_sums[1] * d_sums[2]));
    d_counts[t] = 0u;   // 512 threads: restore pre-run invariant
}

extern "C" void kernel_launch(void* const* d_in, const int* in_sizes, int n_in,
                              void* d_out, int out_size) {
    const float* quat   = (const float*)d_in[0];
    const float* offset = (const float*)d_in[1];
    const float* pos    = (const float*)d_in[2];
    const float* amp    = (const float*)d_in[3];
    const float* var    = (const float*)d_in[4];
    const float* grid   = (const float*)d_in[5];
    float* out = (float*)d_out;

    k_precompute<<<PRE_BLOCKS + ZERO_BLOCKS, 256>>>(quat, offset, pos, amp, var);
    k_scan<<<1, 512>>>();
    k_fill<<<(P_N + 255) / 256, 256>>>();
    k_splat<<<SPLAT_GRID, 128>>>();
    k_reduce<<<512, 256>>>(grid);
    k_final<<<1, 512>>>(out);
}

// round 13
// speedup vs baseline: 5.8903x; 1.2404x over previous
#include <cuda_runtime.h>
#include <math.h>

#define A_N   20480
#define G_N   5
#define P_N   (A_N * G_N)           // 102400 pairs
#define NVOX  (128 * 128 * 128)
#define WIN   10                    // gaussian window width (slots 0..9), centered: margins in [4,5]
#define MAXE  (P_N * 8)
#define CHUNK 128
#define NB    32                    // batch size == warp width (ballot compaction)
#define MAXC  (512 + MAXE / CHUNK)  // max chunk descriptors (6912)
#define PRE_BLOCKS ((P_N + 255) / 256)          // 400
#define ZERO_BLOCKS (NVOX / 4 / 256)            // 2048

typedef unsigned long long ull;

// ---------------- device scratch (d_counts invariant: zeroed at end of every run) ----------------
__device__ float        d_gx[P_N * 16];
__device__ float        d_gy[P_N * 16];
__device__ float        d_gz[P_N * 16];     // prefactor folded in
__device__ int4         d_meta[P_N];        // ix0, iy0, iz0, packed tile spans (w=-1: none)
__device__ float        d_vol[NVOX];
__device__ unsigned int d_counts[512];
__device__ unsigned int d_segstart[512];
__device__ unsigned int d_cursor[512];
__device__ uint2        d_chunkdesc[MAXC];  // {entry start, tile | (len<<16)}
__device__ unsigned int d_nchunks;
__device__ unsigned int d_entries[MAXE];    // (tile << 17) | pair
__device__ unsigned int d_total;
__device__ double       d_sums[3];          // S1, S2, S3

// ---------------- f32x2 helpers ----------------
__device__ __forceinline__ ull pack2(float lo, float hi) {
    ull r; asm("mov.b64 %0, {%1, %2};" : "=l"(r) : "f"(lo), "f"(hi)); return r;
}
__device__ __forceinline__ void unpack2(ull v, float& lo, float& hi) {
    asm("mov.b64 {%0, %1}, %2;" : "=f"(lo), "=f"(hi) : "l"(v));
}
__device__ __forceinline__ ull fma2(ull a, ull b, ull c) {
    ull d; asm("fma.rn.f32x2 %0, %1, %2, %3;" : "=l"(d) : "l"(a), "l"(b), "l"(c)); return d;
}
__device__ __forceinline__ void red2(float* p, ull v) {
    float lo, hi; unpack2(v, lo, hi);
    asm volatile("red.global.add.v2.f32 [%0], {%1, %2};" :: "l"(p), "f"(lo), "f"(hi) : "memory");
}

// ---------------- K2: rotate + 1D gaussians + tile counting, fused d_vol zeroing ----------------
__global__ void k_precompute(const float* __restrict__ quat,
                             const float* __restrict__ offset,
                             const float* __restrict__ pos,
                             const float* __restrict__ amp,
                             const float* __restrict__ var) {
    int t = threadIdx.x;

    if (blockIdx.x >= PRE_BLOCKS) {
        int i = (blockIdx.x - PRE_BLOCKS) * 256 + t;
        ((float4*)d_vol)[i] = make_float4(0.f, 0.f, 0.f, 0.f);
        return;
    }

    __shared__ unsigned int scount[512];
    scount[t] = 0u; scount[t + 256] = 0u;
    __syncthreads();

    int p = blockIdx.x * 256 + t;
    int w = -1;
    if (p < P_N) {
        float qw = quat[0], qx = quat[1], qy = quat[2], qz = quat[3];
        float qn = rsqrtf(qw * qw + qx * qx + qy * qy + qz * qz);
        qw *= qn; qx *= qn; qy *= qn; qz *= qn;
        float R00 = 1.f - 2.f * (qy * qy + qz * qz);
        float R01 = 2.f * (qx * qy - qw * qz);
        float R02 = 2.f * (qx * qz + qw * qy);
        float R10 = 2.f * (qx * qy + qw * qz);
        float R11 = 1.f - 2.f * (qx * qx + qz * qz);
        float R12 = 2.f * (qy * qz - qw * qx);
        float R20 = 2.f * (qx * qz - qw * qy);
        float R21 = 2.f * (qy * qz + qw * qx);
        float R22 = 1.f - 2.f * (qx * qx + qy * qy);

        int a = p / G_N;
        float px = pos[a * 3 + 0], py = pos[a * 3 + 1], pz = pos[a * 3 + 2];
        float cx = px * R00 + py * R10 + pz * R20 + offset[0];
        float cy = px * R01 + py * R11 + pz * R21 + offset[1];
        float cz = px * R02 + py * R12 + pz * R22 + offset[2];

        float v    = var[p];
        float am   = amp[p];
        float r    = rsqrtf(6.283185307179586f * v);
        float pref = am * r * r * r;            // amp * (2*pi*var)^(-3/2)
        float ninv = -0.5f / v;

        // even-aligned, centered window [ix0 .. ix0+9]; margins in [4,5] both sides
        int ix0 = ((int)floorf(cx) + 60) & ~1;
        int iy0 = ((int)floorf(cy) + 60) & ~1;
        int iz0 = ((int)floorf(cz) + 60) & ~1;

        float q2 = __expf(2.f * ninv);
        float g[16];
        {
            float d0 = (float)(ix0 - 64) - cx;
            float e  = __expf(ninv * d0 * d0);
            float rr = __expf(ninv * (2.f * d0 + 1.f));
            #pragma unroll
            for (int i = 0; i < 16; i++) { g[i] = (i < WIN) ? e : 0.f; e *= rr; rr *= q2; }
            float4* dst = (float4*)&d_gx[p * 16];
            dst[0] = make_float4(g[0], g[1], g[2], g[3]);
            dst[1] = make_float4(g[4], g[5], g[6], g[7]);
            dst[2] = make_float4(g[8], g[9], 0.f, 0.f);
            dst[3] = make_float4(0.f, 0.f, 0.f, 0.f);
        }
        {
            float d0 = (float)(iy0 - 64) - cy;
            float e  = __expf(ninv * d0 * d0);
            float rr = __expf(ninv * (2.f * d0 + 1.f));
            #pragma unroll
            for (int i = 0; i < 16; i++) { g[i] = (i < WIN) ? e : 0.f; e *= rr; rr *= q2; }
            float4* dst = (float4*)&d_gy[p * 16];
            dst[0] = make_float4(g[0], g[1], g[2], g[3]);
            dst[1] = make_float4(g[4], g[5], g[6], g[7]);
            dst[2] = make_float4(g[8], g[9], 0.f, 0.f);
            dst[3] = make_float4(0.f, 0.f, 0.f, 0.f);
        }
        {
            float d0 = (float)(iz0 - 64) - cz;
            float e  = pref * __expf(ninv * d0 * d0);
            float rr = __expf(ninv * (2.f * d0 + 1.f));
            #pragma unroll
            for (int i = 0; i < 16; i++) { g[i] = (i < WIN) ? e : 0.f; e *= rr; rr *= q2; }
            float4* dst = (float4*)&d_gz[p * 16];
            dst[0] = make_float4(g[0], g[1], g[2], g[3]);
            dst[1] = make_float4(g[4], g[5], g[6], g[7]);
            dst[2] = make_float4(g[8], g[9], 0.f, 0.f);
            dst[3] = make_float4(0.f, 0.f, 0.f, 0.f);
        }

        int xlo = max(ix0, 0), xhi = min(ix0 + WIN - 1, 127);
        int ylo = max(iy0, 0), yhi = min(iy0 + WIN - 1, 127);
        int zlo = max(iz0, 0), zhi = min(iz0 + WIN - 1, 127);
        if (xlo <= xhi && ylo <= yhi && zlo <= zhi) {
            int txlo = xlo >> 4, txhi = xhi >> 4;
            int tylo = ylo >> 4, tyhi = yhi >> 4;
            int tzlo = zlo >> 4, tzhi = zhi >> 4;
            w = txlo | (txhi << 3) | (tylo << 6) | (tyhi << 9) | (tzlo << 12) | (tzhi << 15);
            for (int tz = tzlo; tz <= tzhi; tz++)
                for (int ty = tylo; ty <= tyhi; ty++)
                    for (int tx = txlo; tx <= txhi; tx++)
                        atomicAdd(&scount[(tz << 6) | (ty << 3) | tx], 1u);
        }
        d_meta[p] = make_int4(ix0, iy0, iz0, w);
    }
    __syncthreads();
    for (int i = t; i < 512; i += 256) {
        unsigned int c = scount[i];
        if (c) atomicAdd(&d_counts[i], c);   // d_counts pre-zeroed by previous run's k_final
    }
}

// ---------------- K3: scans + chunk descriptor emission + sums zero ----------------
__global__ void k_scan() {
    __shared__ unsigned int s[512];
    int t = threadIdx.x;
    unsigned int own = d_counts[t];
    s[t] = own;
    __syncthreads();
    for (int off = 1; off < 512; off <<= 1) {
        unsigned int v = (t >= off) ? s[t - off] : 0u;
        __syncthreads();
        s[t] += v;
        __syncthreads();
    }
    unsigned int segstart = s[t] - own;
    d_segstart[t] = segstart;
    d_cursor[t]   = segstart;
    if (t == 511) d_total = s[511];
    if (t < 3)    d_sums[t] = 0.0;
    __syncthreads();

    unsigned int nch = (own + CHUNK - 1) / CHUNK;
    s[t] = nch;
    __syncthreads();
    for (int off = 1; off < 512; off <<= 1) {
        unsigned int v = (t >= off) ? s[t - off] : 0u;
        __syncthreads();
        s[t] += v;
        __syncthreads();
    }
    unsigned int cb = s[t] - nch;
    if (t == 511) d_nchunks = s[511];

    for (unsigned int j = 0; j * CHUNK < own; j++) {
        unsigned int len = min((unsigned int)CHUNK, own - j * CHUNK);
        d_chunkdesc[cb + j] = make_uint2(segstart + j * CHUNK,
                                         (unsigned int)t | (len << 16));
    }
}

// ---------------- K4: fill entry list, block-aggregated cursors ----------------
__global__ void k_fill() {
    __shared__ unsigned int scount[512];
    __shared__ unsigned int sbase[512];
    int t = threadIdx.x;
    scount[t] = 0u; scount[t + 256] = 0u;
    __syncthreads();

    int p = blockIdx.x * 256 + t;
    int w = (p < P_N) ? d_meta[p].w : -1;
    int txlo = 0, txhi = -1, tylo = 0, tyhi = -1, tzlo = 0, tzhi = -1;
    if (w >= 0) {
        txlo =  w        & 7; txhi = (w >> 3)  & 7;
        tylo = (w >> 6)  & 7; tyhi = (w >> 9)  & 7;
        tzlo = (w >> 12) & 7; tzhi = (w >> 15) & 7;
        for (int tz = tzlo; tz <= tzhi; tz++)
            for (int ty = tylo; ty <= tyhi; ty++)
                for (int tx = txlo; tx <= txhi; tx++)
                    atomicAdd(&scount[(tz << 6) | (ty << 3) | tx], 1u);
    }
    __syncthreads();
    for (int i = t; i < 512; i += 256) {
        unsigned int c = scount[i];
        sbase[i] = c ? atomicAdd(&d_cursor[i], c) : 0u;
    }
    __syncthreads();
    if (w >= 0) {
        for (int tz = tzlo; tz <= tzhi; tz++)
            for (int ty = tylo; ty <= tyhi; ty++)
                for (int tx = txlo; tx <= txhi; tx++) {
                    int tile = (tz << 6) | (ty << 3) | tx;
                    unsigned int posn = atomicAdd(&sbase[tile], 1u);
                    d_entries[posn] = ((unsigned int)tile << 17) | (unsigned int)p;
                }
    }
}

// ---------------- K5: splat — one chunk per CTA (HW scheduler load-balances), dual-entry k-loop ----------------
__global__ void __launch_bounds__(128) k_splat() {
    __shared__ __align__(16) float sgx[2][NB][16];
    __shared__ __align__(16) float sgy[2][NB][16];
    __shared__ __align__(16) float sgz[2][NB][16];
    __shared__ unsigned int szmask[2][NB];

    if (blockIdx.x >= d_nchunks) return;
    uint2 desc = d_chunkdesc[blockIdx.x];
    unsigned int s   = desc.x;
    int tile         = (int)(desc.y & 0x1FFu);
    unsigned int len = desc.y >> 16;
    unsigned int e_end = s + len;

    int X0 =  (tile       & 7) << 4;
    int Y0 = ((tile >> 3) & 7) << 4;
    int Z0 = ((tile >> 6) & 7) << 4;

    int t    = threadIdx.x;
    int y    = t & 15;        // owned y row
    int zp   = t >> 4;        // owned z rows: 2*zp, 2*zp+1
    int wid  = t >> 5;        // warp id 0..3, covers z in [4w, 4w+4)
    int lane = t & 31;

    ull acc[2][8];            // [zz][x-pair]
    #pragma unroll
    for (int r = 0; r < 2; r++)
        #pragma unroll
        for (int i = 0; i < 8; i++) acc[r][i] = 0ull;

    // stage: float2 granularity (slots pair up: offsets and 2*l2 both even)
    auto stage = [&](int buf, unsigned int base, int n) {
        #pragma unroll
        for (int s2 = t; s2 < NB * 8; s2 += 128) {
            int b = s2 >> 3, l2 = s2 & 7;
            if (b < n) {
                unsigned int ent = d_entries[base + (unsigned int)b];
                int pid = (int)(ent & 0x1FFFFu);
                int4 mt = d_meta[pid];
                int ox = X0 - mt.x, oy = Y0 - mt.y, oz = Z0 - mt.z;
                int ix = 2 * l2 + ox, iy = 2 * l2 + oy, iz = 2 * l2 + oz;
                float2 vx = make_float2(0.f, 0.f), vy = vx, vz = vx;
                if ((unsigned)ix < (unsigned)WIN) vx = *(const float2*)&d_gx[pid * 16 + ix];
                if ((unsigned)iy < (unsigned)WIN) vy = *(const float2*)&d_gy[pid * 16 + iy];
                if ((unsigned)iz < (unsigned)WIN) vz = *(const float2*)&d_gz[pid * 16 + iz];
                *(float2*)&sgx[buf][b][2 * l2] = vx;
                *(float2*)&sgy[buf][b][2 * l2] = vy;
                *(float2*)&sgz[buf][b][2 * l2] = vz;
                if (l2 == 0) {
                    int loz = max(0, -oz), hiz = min(15, (WIN - 1) - oz);
                    unsigned int c = 0u;
                    #pragma unroll
                    for (int w2 = 0; w2 < 4; w2++)
                        if (loz <= 4 * w2 + 3 && hiz >= 4 * w2) c |= 1u << w2;
                    szmask[buf][b] = c;
                }
            } else if (l2 == 0) {
                szmask[buf][b] = 0u;
            }
        }
    };

    int nbatch = (int)((len + NB - 1) / NB);
    stage(0, s, (int)min((unsigned int)NB, len));

    for (int i = 0; i < nbatch; i++) {
        __syncthreads();
        int cur = i & 1;
        if (i + 1 < nbatch) {
            unsigned int bnext = s + (unsigned int)(i + 1) * NB;
            stage(cur ^ 1, bnext, (int)min((unsigned int)NB, e_end - bnext));
        }

        unsigned int em = szmask[cur][lane];
        unsigned int m  = __ballot_sync(0xFFFFFFFFu, (em >> wid) & 1u);

        while (m) {
            int k1 = __ffs(m) - 1;
            m &= m - 1;
            float sec = m ? 1.f : 0.f;           // second entry valid?
            int k2 = m ? (__ffs(m) - 1) : k1;    // duplicate k1, zeroed by sec
            m &= m - 1;                          // safe at m==0

            float  gy1 = sgy[cur][k1][y];
            float2 gza = *(const float2*)&sgz[cur][k1][2 * zp];
            float  gy2 = sgy[cur][k2][y] * sec;
            float2 gzb = *(const float2*)&sgz[cur][k2][2 * zp];
            float a0 = gy1 * gza.x, a1 = gy1 * gza.y;
            float b0 = gy2 * gzb.x, b1 = gy2 * gzb.y;
            ull ca0 = pack2(a0, a0), ca1 = pack2(a1, a1);
            ull cb0 = pack2(b0, b0), cb1 = pack2(b1, b1);

            ulonglong2 pa = *(const ulonglong2*)&sgx[cur][k1][0];
            ulonglong2 pb = *(const ulonglong2*)&sgx[cur][k1][4];
            ulonglong2 pc = *(const ulonglong2*)&sgx[cur][k1][8];
            ulonglong2 pd = *(const ulonglong2*)&sgx[cur][k1][12];
            ulonglong2 qa = *(const ulonglong2*)&sgx[cur][k2][0];
            ulonglong2 qb = *(const ulonglong2*)&sgx[cur][k2][4];
            ulonglong2 qc = *(const ulonglong2*)&sgx[cur][k2][8];
            ulonglong2 qd = *(const ulonglong2*)&sgx[cur][k2][12];

            acc[0][0] = fma2(ca0, pa.x, acc[0][0]); acc[0][1] = fma2(ca0, pa.y, acc[0][1]);
            acc[0][2] = fma2(ca0, pb.x, acc[0][2]); acc[0][3] = fma2(ca0, pb.y, acc[0][3]);
            acc[0][4] = fma2(ca0, pc.x, acc[0][4]); acc[0][5] = fma2(ca0, pc.y, acc[0][5]);
            acc[0][6] = fma2(ca0, pd.x, acc[0][6]); acc[0][7] = fma2(ca0, pd.y, acc[0][7]);
            acc[1][0] = fma2(ca1, pa.x, acc[1][0]); acc[1][1] = fma2(ca1, pa.y, acc[1][1]);
            acc[1][2] = fma2(ca1, pb.x, acc[1][2]); acc[1][3] = fma2(ca1, pb.y, acc[1][3]);
            acc[1][4] = fma2(ca1, pc.x, acc[1][4]); acc[1][5] = fma2(ca1, pc.y, acc[1][5]);
            acc[1][6] = fma2(ca1, pd.x, acc[1][6]); acc[1][7] = fma2(ca1, pd.y, acc[1][7]);

            acc[0][0] = fma2(cb0, qa.x, acc[0][0]); acc[0][1] = fma2(cb0, qa.y, acc[0][1]);
            acc[0][2] = fma2(cb0, qb.x, acc[0][2]); acc[0][3] = fma2(cb0, qb.y, acc[0][3]);
            acc[0][4] = fma2(cb0, qc.x, acc[0][4]); acc[0][5] = fma2(cb0, qc.y, acc[0][5]);
            acc[0][6] = fma2(cb0, qd.x, acc[0][6]); acc[0][7] = fma2(cb0, qd.y, acc[0][7]);
            acc[1][0] = fma2(cb1, qa.x, acc[1][0]); acc[1][1] = fma2(cb1, qa.y, acc[1][1]);
            acc[1][2] = fma2(cb1, qb.x, acc[1][2]); acc[1][3] = fma2(cb1, qb.y, acc[1][3]);
            acc[1][4] = fma2(cb1, qc.x, acc[1][4]); acc[1][5] = fma2(cb1, qc.y, acc[1][5]);
            acc[1][6] = fma2(cb1, qd.x, acc[1][6]); acc[1][7] = fma2(cb1, qd.y, acc[1][7]);
        }
    }

    #pragma unroll
    for (int zz = 0; zz < 2; zz++) {
        int rb = ((Z0 + 2 * zp + zz) * 128 + (Y0 + y)) * 128 + X0;
        #pragma unroll
        for (int i2 = 0; i2 < 8; i2++)
            if (acc[zz][i2]) red2(&d_vol[rb + 2 * i2], acc[zz][i2]);
    }
}

// ---------------- K6: fused triple reduction (float inner, double tree) ----------------
__global__ void k_reduce(const float* __restrict__ grid) {
    __shared__ double sh0[256], sh1[256], sh2[256];
    int t = threadIdx.x;
    float s1 = 0.f, s2 = 0.f, s3 = 0.f;
    for (int i = blockIdx.x * 256 + t; i < NVOX; i += gridDim.x * 256) {
        float v = d_vol[i];
        float g = grid[i];
        s1 += v * g;
        s2 += v * v;
        s3 += g * g;
    }
    sh0[t] = (double)s1; sh1[t] = (double)s2; sh2[t] = (double)s3;
    __syncthreads();
    for (int off = 128; off > 0; off >>= 1) {
        if (t < off) {
            sh0[t] += sh0[t + off];
            sh1[t] += sh1[t + off];
            sh2[t] += sh2[t + off];
        }
        __syncthreads();
    }
    if (t == 0) {
        atomicAdd(&d_sums[0], sh0[0]);
        atomicAdd(&d_sums[1], sh1[0]);
        atomicAdd(&d_sums[2], sh2[0]);
    }
}

// ---------------- K7: finish + reset d_counts invariant for the next run ----------------
__global__ void k_final(float* __restrict__ out) {
    int t = threadIdx.x;
    if (t == 0)
        out[0] = (float)(1.0 - d_sums[0] / sqrt(d_sums[1] * d_sums[2]));
    d_counts[t] = 0u;   // 512 threads: restore pre-run invariant
}

extern "C" void kernel_launch(void* const* d_in, const int* in_sizes, int n_in,
                              void* d_out, int out_size) {
    const float* quat   = (const float*)d_in[0];
    const float* offset = (const float*)d_in[1];
    const float* pos    = (const float*)d_in[2];
    const float* amp    = (const float*)d_in[3];
    const float* var    = (const float*)d_in[4];
    const float* grid   = (const float*)d_in[5];
    float* out = (float*)d_out;

    k_precompute<<<PRE_BLOCKS + ZERO_BLOCKS, 256>>>(quat, offset, pos, amp, var);
    k_scan<<<1, 512>>>();
    k_fill<<<(P_N + 255) / 256, 256>>>();
    k_splat<<<MAXC, 128>>>();
    k_reduce<<<512, 256>>>(grid);
    k_final<<<1, 512>>>(out);
}